// round 9
// baseline (speedup 1.0000x reference)
#include <cuda_runtime.h>
#include <cuda_bf16.h>
#include <cstdint>

// Problem constants (fixed by setup_inputs)
#define NN 50000
#define EE 400000
#define HD 128
#define FIN 16
#define EAD 8
#define MAX_LAYERS 6
#define NODE_OUT_ELEMS (NN * 2)
#define G64 ((NN + 63) / 64)   // 782
#define LGRID 391              // 2 tiles per block, 2*391 = 782

typedef unsigned long long ull;

// ---------------- scratch (device globals; no allocation allowed) ----------------
__device__ float g_h[NN * HD];
__device__ float g_h2[NN * HD];
__device__ float g_P[NN * HD];
__device__ float g_Q[NN * HD];
__device__ float g_U[HD * HD];
__device__ float g_V[HD * HD];
__device__ float g_c1[HD];

__device__ int g_src[EE];
__device__ int g_dst[EE];
__device__ int g_csrc[EE];
__device__ int g_deg[NN];
__device__ int g_rowptr[NN + 1];
__device__ int g_cursor[NN];
__device__ int g_zlist[NN];
__device__ int g_zcount;
__device__ int g_is64;
__device__ int g_bsum[128];

// ---------------- f32x2 helpers ----------------
__device__ __forceinline__ ull pk2(float lo, float hi) {
    ull r;
    asm("mov.b64 %0, {%1, %2};" : "=l"(r) : "f"(lo), "f"(hi));
    return r;
}
__device__ __forceinline__ void upk2(ull v, float& lo, float& hi) {
    asm("mov.b64 {%0, %1}, %2;" : "=f"(lo), "=f"(hi) : "l"(v));
}
__device__ __forceinline__ void ffma2(ull& d, ull a, ull b) {
    asm("fma.rn.f32x2 %0, %1, %2, %0;" : "+l"(d) : "l"(a), "l"(b));
}

// ---------------- streams/events for capture-forked concurrency ----------------
static cudaStream_t s_b = 0;
static cudaEvent_t s_ev0 = 0, s_ev1 = 0, s_evB = 0, s_evB2 = 0;
static bool s_fork = false;
static struct StreamInit {
    StreamInit() {
        bool ok = true;
        ok = ok && (cudaStreamCreateWithFlags(&s_b, cudaStreamNonBlocking) == cudaSuccess);
        ok = ok && (cudaEventCreateWithFlags(&s_ev0, cudaEventDisableTiming) == cudaSuccess);
        ok = ok && (cudaEventCreateWithFlags(&s_ev1, cudaEventDisableTiming) == cudaSuccess);
        ok = ok && (cudaEventCreateWithFlags(&s_evB, cudaEventDisableTiming) == cudaSuccess);
        ok = ok && (cudaEventCreateWithFlags(&s_evB2, cudaEventDisableTiming) == cudaSuccess);
        s_fork = ok;
    }
} s_streaminit;

// ---------------- detect dtype + zero deg ----------------
__global__ void detect_kernel(const long long* ei) {
    int idx = blockIdx.x * blockDim.x + threadIdx.x;
    int stride = gridDim.x * blockDim.x;
    for (int i = idx; i < NN; i += stride) g_deg[i] = 0;
    if (idx == 0) g_zcount = 0;
    if (blockIdx.x == 0) {
        __shared__ int bad;
        if (threadIdx.x == 0) bad = 0;
        __syncthreads();
        for (int i = threadIdx.x; i < 1024; i += blockDim.x) {
            long long v = ei[i];
            if (v < 0 || v >= NN) bad = 1;
        }
        __syncthreads();
        if (threadIdx.x == 0) g_is64 = bad ? 0 : 1;
    }
}

// ---------------- prep: convert + histogram ----------------
__global__ void prep_kernel(const void* ei) {
    int idx = blockIdx.x * blockDim.x + threadIdx.x;
    int stride = gridDim.x * blockDim.x;
    int is64 = g_is64;
    const long long* p64 = (const long long*)ei;
    const int* p32 = (const int*)ei;
    for (int i = idx; i < EE; i += stride) {
        int s, d;
        if (is64) {
            s = (int)p64[i];
            d = (int)p64[EE + i];
        } else {
            s = p32[i];
            d = p32[EE + i];
        }
        g_src[i] = s;
        g_dst[i] = d;
        atomicAdd(&g_deg[d], 1);
    }
}

// ---------------- multi-block exclusive scan ----------------
#define SCAN_B 512
#define SCAN_NB ((NN + SCAN_B - 1) / SCAN_B)   // 98

__global__ void scan1_kernel() {
    __shared__ int wsum[16];
    int b = blockIdx.x, tid = threadIdx.x;
    int i = b * SCAN_B + tid;
    int v = (i < NN) ? g_deg[i] : 0;
    int lane = tid & 31, w = tid >> 5;
    int x = v;
#pragma unroll
    for (int off = 1; off < 32; off <<= 1) {
        int t = __shfl_up_sync(0xffffffffu, x, off);
        if (lane >= off) x += t;
    }
    if (lane == 31) wsum[w] = x;
    __syncthreads();
    if (w == 0) {
        int s = (lane < 16) ? wsum[lane] : 0;
#pragma unroll
        for (int off = 1; off < 16; off <<= 1) {
            int t = __shfl_up_sync(0xffffffffu, s, off);
            if (lane >= off) s += t;
        }
        if (lane < 16) wsum[lane] = s;
    }
    __syncthreads();
    int base = (w > 0) ? wsum[w - 1] : 0;
    int incl = base + x;
    if (i < NN) g_rowptr[i] = incl - v;
    if (tid == SCAN_B - 1) g_bsum[b] = incl;
}

__global__ void scan3_kernel() {
    __shared__ int boffs;
    int b = blockIdx.x, tid = threadIdx.x;
    if (tid < 32) {
        int s = 0;
        for (int i = tid; i < b; i += 32) s += g_bsum[i];
#pragma unroll
        for (int off = 16; off >= 1; off >>= 1) s += __shfl_xor_sync(0xffffffffu, s, off);
        if (tid == 0) boffs = s;
    }
    __syncthreads();
    int i = b * SCAN_B + tid;
    if (i < NN) {
        int rp = g_rowptr[i] + boffs;
        g_rowptr[i] = rp;
        g_cursor[i] = rp;
        if (g_deg[i] == 0) {
            int p = atomicAdd(&g_zcount, 1);
            g_zlist[p] = i;
        }
    }
    if (b == 0 && tid == 0) g_rowptr[NN] = EE;
}

__global__ void scatter_kernel() {
    int idx = blockIdx.x * blockDim.x + threadIdx.x;
    int stride = gridDim.x * blockDim.x;
    for (int i = idx; i < EE; i += stride) {
        int d = g_dst[i];
        int pos = atomicAdd(&g_cursor[d], 1);
        g_csrc[pos] = g_src[i];
    }
}

// ---------------- encoder + uv fused ----------------
__global__ void encuv_kernel(const float* __restrict__ x, const float* __restrict__ Wenc,
                             const float* __restrict__ benc,
                             const float* __restrict__ Wmsg, const float* __restrict__ bmsg,
                             const float* __restrict__ Wupd, const float* __restrict__ bupd) {
    if (blockIdx.x >= 1184) {
        int k = blockIdx.x - 1184;   // 0..127
        int j = threadIdx.x;         // 0..127
        float u = Wupd[k * HD + j];
        float v = 0.f;
        for (int t = 0; t < HD; t++) {
            float wub = Wupd[(HD + t) * HD + j];
            u += Wmsg[(HD + k) * HD + t] * wub;
            v += Wmsg[k * HD + t] * wub;
        }
        g_U[k * HD + j] = u;
        g_V[k * HD + j] = v;
        if (k == 0) {
            float c = bupd[j];
            for (int t = 0; t < HD; t++) c += bmsg[t] * Wupd[(HD + t) * HD + j];
            g_c1[j] = c;
        }
        return;
    }
    __shared__ float ws[FIN * HD];
    __shared__ float bs[HD];
    __shared__ float xs[FIN];
    int tid = threadIdx.x;  // 128
    for (int i = tid; i < FIN * HD; i += 128) ws[i] = Wenc[i];
    bs[tid] = benc[tid];
    __syncthreads();
    for (int v = blockIdx.x; v < NN; v += 1184) {
        if (tid < FIN) xs[tid] = x[v * FIN + tid];
        __syncthreads();
        float acc = bs[tid];
#pragma unroll
        for (int k = 0; k < FIN; k++) acc += xs[k] * ws[k * HD + tid];
        g_h[v * HD + tid] = acc;
        __syncthreads();
    }
}

// ---------------- fused layer: agg + h' = relu(h@U + A@V + c1) + zero-deg fixup ----------
// W via warp-uniform __ldg (no smem staging, no inner barriers).
#define LAYER_SMEM_FLOATS (8448 + 8448)
__global__ void __launch_bounds__(256, 3)
layer_kernel(const float* __restrict__ hcur, float* __restrict__ hnext,
             const int* __restrict__ lnum, int layer,
             const float* __restrict__ Wupd, const float* __restrict__ bupd) {
    if (layer >= *lnum) return;
    int tid = threadIdx.x;
    if (blockIdx.x >= LGRID) {
        __shared__ float hs[HD];
        int zc = g_zcount;
        for (int zi = blockIdx.x - LGRID; zi < zc; zi += 16) {
            int v = g_zlist[zi];
            if (tid < 128) hs[tid] = hcur[v * HD + tid];
            __syncthreads();
            if (tid < 128) {
                float acc = bupd[tid];
#pragma unroll 8
                for (int k = 0; k < HD; k++) acc += hs[k] * Wupd[k * HD + tid];
                hnext[v * HD + tid] = fmaxf(acc, 0.f);
            }
            __syncthreads();
        }
        return;
    }
    extern __shared__ float lsm[];
    float* Hst = lsm;            // [k 128][r 64] stride 66
    float* Ast = Hst + 8448;     // [k 128][r 64] stride 66
    int warp = tid >> 5, lane = tid & 31;

    for (int tile = blockIdx.x; tile < G64; tile += LGRID) {
        int row0 = tile * 64;
        __syncthreads();

#pragma unroll 4
        for (int q = 0; q < 32; q++) {
            int e = tid + 256 * q;
            int r = e >> 7, k = e & 127;
            int gr = row0 + r;
            Hst[k * 66 + r] = (gr < NN) ? hcur[gr * HD + k] : 0.f;
        }

        for (int n = warp; n < 64; n += 8) {
            int v = row0 + n;
            float4 a0 = make_float4(0.f, 0.f, 0.f, 0.f);
            float4 a1 = make_float4(0.f, 0.f, 0.f, 0.f);
            float4 a2 = make_float4(0.f, 0.f, 0.f, 0.f);
            float4 a3 = make_float4(0.f, 0.f, 0.f, 0.f);
            int dg = 0;
            if (v < NN) {
                int s0r = g_rowptr[v], s1r = g_rowptr[v + 1];
                dg = s1r - s0r;
                int idx = s0r;
                for (; idx + 3 < s1r; idx += 4) {
                    int i0 = g_csrc[idx], i1 = g_csrc[idx + 1];
                    int i2 = g_csrc[idx + 2], i3 = g_csrc[idx + 3];
                    float4 h0 = __ldg((const float4*)(hcur + i0 * HD + lane * 4));
                    float4 h1 = __ldg((const float4*)(hcur + i1 * HD + lane * 4));
                    float4 h2 = __ldg((const float4*)(hcur + i2 * HD + lane * 4));
                    float4 h3 = __ldg((const float4*)(hcur + i3 * HD + lane * 4));
                    a0.x += h0.x; a0.y += h0.y; a0.z += h0.z; a0.w += h0.w;
                    a1.x += h1.x; a1.y += h1.y; a1.z += h1.z; a1.w += h1.w;
                    a2.x += h2.x; a2.y += h2.y; a2.z += h2.z; a2.w += h2.w;
                    a3.x += h3.x; a3.y += h3.y; a3.z += h3.z; a3.w += h3.w;
                }
                for (; idx < s1r; idx++) {
                    int i0 = g_csrc[idx];
                    float4 h0 = __ldg((const float4*)(hcur + i0 * HD + lane * 4));
                    a0.x += h0.x; a0.y += h0.y; a0.z += h0.z; a0.w += h0.w;
                }
            }
            float inv = 1.f / (float)(dg > 0 ? dg : 1);
            int j0 = lane * 4;
            Ast[(j0 + 0) * 66 + n] = (a0.x + a1.x + a2.x + a3.x) * inv;
            Ast[(j0 + 1) * 66 + n] = (a0.y + a1.y + a2.y + a3.y) * inv;
            Ast[(j0 + 2) * 66 + n] = (a0.z + a1.z + a2.z + a3.z) * inv;
            Ast[(j0 + 3) * 66 + n] = (a0.w + a1.w + a2.w + a3.w) * inv;
        }
        __syncthreads();

        int jb = warp * 16;
        ull acc[2][8];
        {
            const ulonglong2* cp = (const ulonglong2*)(g_c1 + jb);
            ulonglong2 q0 = cp[0], q1 = cp[1], q2 = cp[2], q3 = cp[3];
            acc[0][0] = q0.x; acc[0][1] = q0.y; acc[0][2] = q1.x; acc[0][3] = q1.y;
            acc[0][4] = q2.x; acc[0][5] = q2.y; acc[0][6] = q3.x; acc[0][7] = q3.y;
#pragma unroll
            for (int i = 0; i < 8; i++) acc[1][i] = acc[0][i];
        }
        for (int pass = 0; pass < 2; pass++) {
            const float* Wg = pass ? g_V : g_U;
            const float* Xt = pass ? Ast : Hst;
#pragma unroll 8
            for (int k = 0; k < HD; k++) {
                const ulonglong2* wr = (const ulonglong2*)(Wg + k * HD + jb);
                ulonglong2 wA = __ldg(wr);
                ulonglong2 wB = __ldg(wr + 1);
                ulonglong2 wC = __ldg(wr + 2);
                ulonglong2 wD = __ldg(wr + 3);
                float2 xv = *(const float2*)(Xt + k * 66 + lane * 2);
                ull x0 = pk2(xv.x, xv.x), x1 = pk2(xv.y, xv.y);
                ffma2(acc[0][0], x0, wA.x); ffma2(acc[0][1], x0, wA.y);
                ffma2(acc[0][2], x0, wB.x); ffma2(acc[0][3], x0, wB.y);
                ffma2(acc[0][4], x0, wC.x); ffma2(acc[0][5], x0, wC.y);
                ffma2(acc[0][6], x0, wD.x); ffma2(acc[0][7], x0, wD.y);
                ffma2(acc[1][0], x1, wA.x); ffma2(acc[1][1], x1, wA.y);
                ffma2(acc[1][2], x1, wB.x); ffma2(acc[1][3], x1, wB.y);
                ffma2(acc[1][4], x1, wC.x); ffma2(acc[1][5], x1, wC.y);
                ffma2(acc[1][6], x1, wD.x); ffma2(acc[1][7], x1, wD.y);
            }
        }
#pragma unroll
        for (int rr = 0; rr < 2; rr++) {
            int r = row0 + lane * 2 + rr;
            if (r < NN && g_deg[r] != 0) {
                float f[16];
#pragma unroll
                for (int i = 0; i < 8; i++) upk2(acc[rr][i], f[2 * i], f[2 * i + 1]);
                float4* dst = (float4*)(hnext + r * HD + jb);
#pragma unroll
                for (int qq = 0; qq < 4; qq++) {
                    float4 o;
                    o.x = fmaxf(f[4 * qq + 0], 0.f); o.y = fmaxf(f[4 * qq + 1], 0.f);
                    o.z = fmaxf(f[4 * qq + 2], 0.f); o.w = fmaxf(f[4 * qq + 3], 0.f);
                    dst[qq] = o;
                }
            }
        }
    }
}

// ---------------- P/Q: P = h@We1[0:128], Q = h@We1[128:256] (W via __ldg) ----------------
#define PQ_SMEM_FLOATS 8448
__global__ void pq_kernel(const float* __restrict__ We1, const int* __restrict__ lnum) {
    const float* X = ((*lnum) & 1) ? g_h2 : g_h;
    extern __shared__ float psm[];
    float* Hst = psm;            // [k 128][r 64] stride 66
    int tid = threadIdx.x;
    int warp = tid >> 5, lane = tid & 31;
    int row0 = blockIdx.x * 64;
#pragma unroll 4
    for (int q = 0; q < 32; q++) {
        int e = tid + 256 * q;
        int r = e >> 7, k = e & 127;
        int gr = row0 + r;
        Hst[k * 66 + r] = (gr < NN) ? X[gr * HD + k] : 0.f;
    }
    __syncthreads();

    int jb = warp * 16;
    for (int m = 0; m < 2; m++) {
        const float* Wg = We1 + m * 128 * HD;
        float* C = m ? g_Q : g_P;
        ull acc[2][8];
        ull z = pk2(0.f, 0.f);
#pragma unroll
        for (int i = 0; i < 8; i++) { acc[0][i] = z; acc[1][i] = z; }
#pragma unroll 8
        for (int k = 0; k < HD; k++) {
            const ulonglong2* wr = (const ulonglong2*)(Wg + k * HD + jb);
            ulonglong2 wA = __ldg(wr);
            ulonglong2 wB = __ldg(wr + 1);
            ulonglong2 wC = __ldg(wr + 2);
            ulonglong2 wD = __ldg(wr + 3);
            float2 xv = *(const float2*)(Hst + k * 66 + lane * 2);
            ull x0 = pk2(xv.x, xv.x), x1 = pk2(xv.y, xv.y);
            ffma2(acc[0][0], x0, wA.x); ffma2(acc[0][1], x0, wA.y);
            ffma2(acc[0][2], x0, wB.x); ffma2(acc[0][3], x0, wB.y);
            ffma2(acc[0][4], x0, wC.x); ffma2(acc[0][5], x0, wC.y);
            ffma2(acc[0][6], x0, wD.x); ffma2(acc[0][7], x0, wD.y);
            ffma2(acc[1][0], x1, wA.x); ffma2(acc[1][1], x1, wA.y);
            ffma2(acc[1][2], x1, wB.x); ffma2(acc[1][3], x1, wB.y);
            ffma2(acc[1][4], x1, wC.x); ffma2(acc[1][5], x1, wC.y);
            ffma2(acc[1][6], x1, wD.x); ffma2(acc[1][7], x1, wD.y);
        }
#pragma unroll
        for (int rr = 0; rr < 2; rr++) {
            int r = row0 + lane * 2 + rr;
            if (r < NN) {
                float f[16];
#pragma unroll
                for (int i = 0; i < 8; i++) upk2(acc[rr][i], f[2 * i], f[2 * i + 1]);
                float4* dst = (float4*)(C + r * HD + jb);
#pragma unroll
                for (int qq = 0; qq < 4; qq++) {
                    float4 o;
                    o.x = f[4 * qq + 0]; o.y = f[4 * qq + 1];
                    o.z = f[4 * qq + 2]; o.w = f[4 * qq + 3];
                    dst[qq] = o;
                }
            }
        }
    }
}

// ---------------- node head (on forked stream) ----------------
#define NH_SMEM_FLOATS (8448 + 4352 + 128)
__global__ void nh_kernel(const float* __restrict__ Wn1, const float* __restrict__ bn1,
                          const float* __restrict__ Wn2, const float* __restrict__ bn2,
                          float* __restrict__ out, const int* __restrict__ lnum) {
    const float* X = ((*lnum) & 1) ? g_h2 : g_h;
    extern __shared__ float nsm[];
    float* Hst = nsm;             // [k 128][r 64] stride 66
    float* tsb = Hst + 8448;      // [r 64][j 64] stride 68
    float* W2s = tsb + 4352;      // 64*2
    int tid = threadIdx.x;
    int warp = tid >> 5, lane = tid & 31;
    int row0 = blockIdx.x * 64;
    if (tid < 128) W2s[tid] = Wn2[tid];
#pragma unroll 4
    for (int q = 0; q < 32; q++) {
        int e = tid + 256 * q;
        int r = e >> 7, k = e & 127;
        int gr = row0 + r;
        Hst[k * 66 + r] = (gr < NN) ? X[gr * HD + k] : 0.f;
    }
    __syncthreads();

    int jb8 = warp * 8;
    ull acc2[2][4];
    {
        ulonglong2 b01 = *(const ulonglong2*)(bn1 + jb8);
        ulonglong2 b23 = *(const ulonglong2*)(bn1 + jb8 + 4);
        acc2[0][0] = b01.x; acc2[0][1] = b01.y; acc2[0][2] = b23.x; acc2[0][3] = b23.y;
#pragma unroll
        for (int i = 0; i < 4; i++) acc2[1][i] = acc2[0][i];
    }
#pragma unroll 8
    for (int k = 0; k < HD; k++) {
        const ulonglong2* wr = (const ulonglong2*)(Wn1 + k * 64 + jb8);
        ulonglong2 wA = __ldg(wr);
        ulonglong2 wB = __ldg(wr + 1);
        float2 xv = *(const float2*)(Hst + k * 66 + lane * 2);
        ull x0 = pk2(xv.x, xv.x), x1 = pk2(xv.y, xv.y);
        ffma2(acc2[0][0], x0, wA.x); ffma2(acc2[0][1], x0, wA.y);
        ffma2(acc2[0][2], x0, wB.x); ffma2(acc2[0][3], x0, wB.y);
        ffma2(acc2[1][0], x1, wA.x); ffma2(acc2[1][1], x1, wA.y);
        ffma2(acc2[1][2], x1, wB.x); ffma2(acc2[1][3], x1, wB.y);
    }
#pragma unroll
    for (int rr = 0; rr < 2; rr++) {
        int r = lane * 2 + rr;
        float f[8];
#pragma unroll
        for (int i = 0; i < 4; i++) upk2(acc2[rr][i], f[2 * i], f[2 * i + 1]);
        float4 o1, o2;
        o1.x = fmaxf(f[0], 0.f); o1.y = fmaxf(f[1], 0.f); o1.z = fmaxf(f[2], 0.f); o1.w = fmaxf(f[3], 0.f);
        o2.x = fmaxf(f[4], 0.f); o2.y = fmaxf(f[5], 0.f); o2.z = fmaxf(f[6], 0.f); o2.w = fmaxf(f[7], 0.f);
        *(float4*)(tsb + r * 68 + jb8) = o1;
        *(float4*)(tsb + r * 68 + jb8 + 4) = o2;
    }
    __syncthreads();
    if (tid < 128) {
        int r = tid >> 1, o = tid & 1;
        float s = 0.f;
#pragma unroll 8
        for (int j = 0; j < 64; j++) s += tsb[r * 68 + j] * W2s[j * 2 + o];
        int gr = row0 + r;
        if (gr < NN) out[gr * 2 + o] = s + bn2[o];
    }
}

// ---------------- fused edge head (proven R6 FFMA2 version) ----------------
#define EDGE_SMEM_FLOATS (16896 + 8704 + 384 + 8)
#define P2STEP(CMP, JJ)                                                              \
    {                                                                                \
        const ulonglong2* wp = (const ulonglong2*)(wbase + (JJ) * 64);               \
        ulonglong2 wA = __ldg(wp);                                                   \
        ulonglong2 wB = __ldg(wp + 1);                                               \
        ull x0 = pk2(t0.CMP, t0.CMP), x1 = pk2(t1.CMP, t1.CMP);                      \
        ull x2 = pk2(t2.CMP, t2.CMP), x3 = pk2(t3.CMP, t3.CMP);                      \
        ffma2(acc[0][0], x0, wA.x); ffma2(acc[0][1], x0, wA.y);                      \
        ffma2(acc[0][2], x0, wB.x); ffma2(acc[0][3], x0, wB.y);                      \
        ffma2(acc[1][0], x1, wA.x); ffma2(acc[1][1], x1, wA.y);                      \
        ffma2(acc[1][2], x1, wB.x); ffma2(acc[1][3], x1, wB.y);                      \
        ffma2(acc[2][0], x2, wA.x); ffma2(acc[2][1], x2, wA.y);                      \
        ffma2(acc[2][2], x2, wB.x); ffma2(acc[2][3], x2, wB.y);                      \
        ffma2(acc[3][0], x3, wA.x); ffma2(acc[3][1], x3, wA.y);                      \
        ffma2(acc[3][2], x3, wB.x); ffma2(acc[3][3], x3, wB.y);                      \
    }
__global__ void __launch_bounds__(256, 2)
edge_kernel(const float* __restrict__ ea, const float* __restrict__ We1,
            const float* __restrict__ be1, const float* __restrict__ We2,
            const float* __restrict__ be2, const float* __restrict__ We3,
            const float* __restrict__ be3, float* __restrict__ out) {
    extern __shared__ float esm[];
    float* ts  = esm;             // [128 el][132 j]
    float* us  = ts + 16896;      // [128 el][68 j]
    float* w3t = us + 8704;       // [6][64] transposed
    float* b3s = w3t + 384;       // 8
    __shared__ int esrc[128], edst[128];
    int tid = threadIdx.x, warp = tid >> 5, lane = tid & 31;
    int j0 = lane * 4;

    for (int i = tid; i < 384; i += 256) w3t[i] = We3[(i & 63) * 6 + (i >> 6)];
    if (tid < 8) b3s[tid] = (tid < 6) ? be3[tid] : 0.f;

    float4 bq = __ldg((const float4*)(be1 + j0));
    float4 wck[8];
#pragma unroll
    for (int k = 0; k < 8; k++)
        wck[k] = __ldg((const float4*)(We1 + 256 * HD + k * 128 + j0));
    int jb = warp * 8;
    ulonglong2 b2a = __ldg((const ulonglong2*)(be2 + jb));
    ulonglong2 b2b = __ldg((const ulonglong2*)(be2 + jb + 4));
    __syncthreads();

    for (int e0 = blockIdx.x * 128; e0 < EE; e0 += gridDim.x * 128) {
        if (tid < 128) {
            int e = e0 + tid;
            esrc[tid] = g_src[e];
            edst[tid] = g_dst[e];
        }
        __syncthreads();
        // ---- phase 1 ----
        for (int it = 0; it < 8; it++) {
            int elA = warp + 8 * (2 * it);
            int elB = elA + 8;
            int sA = esrc[elA], dA = edst[elA];
            int sB = esrc[elB], dB = edst[elB];
            float4 pA = __ldg((const float4*)(g_P + sA * HD + j0));
            float4 qA = __ldg((const float4*)(g_Q + dA * HD + j0));
            float4 pB = __ldg((const float4*)(g_P + sB * HD + j0));
            float4 qB = __ldg((const float4*)(g_Q + dB * HD + j0));
            float4 eA0 = __ldg((const float4*)(ea + (e0 + elA) * EAD));
            float4 eA1 = __ldg((const float4*)(ea + (e0 + elA) * EAD + 4));
            float4 eB0 = __ldg((const float4*)(ea + (e0 + elB) * EAD));
            float4 eB1 = __ldg((const float4*)(ea + (e0 + elB) * EAD + 4));
            float4 t = bq;
            t.x += eA0.x * wck[0].x + eA0.y * wck[1].x + eA0.z * wck[2].x + eA0.w * wck[3].x
                 + eA1.x * wck[4].x + eA1.y * wck[5].x + eA1.z * wck[6].x + eA1.w * wck[7].x;
            t.y += eA0.x * wck[0].y + eA0.y * wck[1].y + eA0.z * wck[2].y + eA0.w * wck[3].y
                 + eA1.x * wck[4].y + eA1.y * wck[5].y + eA1.z * wck[6].y + eA1.w * wck[7].y;
            t.z += eA0.x * wck[0].z + eA0.y * wck[1].z + eA0.z * wck[2].z + eA0.w * wck[3].z
                 + eA1.x * wck[4].z + eA1.y * wck[5].z + eA1.z * wck[6].z + eA1.w * wck[7].z;
            t.w += eA0.x * wck[0].w + eA0.y * wck[1].w + eA0.z * wck[2].w + eA0.w * wck[3].w
                 + eA1.x * wck[4].w + eA1.y * wck[5].w + eA1.z * wck[6].w + eA1.w * wck[7].w;
            t.x = fmaxf(t.x + pA.x + qA.x, 0.f);
            t.y = fmaxf(t.y + pA.y + qA.y, 0.f);
            t.z = fmaxf(t.z + pA.z + qA.z, 0.f);
            t.w = fmaxf(t.w + pA.w + qA.w, 0.f);
            *(float4*)(ts + elA * 132 + j0) = t;
            float4 u = bq;
            u.x += eB0.x * wck[0].x + eB0.y * wck[1].x + eB0.z * wck[2].x + eB0.w * wck[3].x
                 + eB1.x * wck[4].x + eB1.y * wck[5].x + eB1.z * wck[6].x + eB1.w * wck[7].x;
            u.y += eB0.x * wck[0].y + eB0.y * wck[1].y + eB0.z * wck[2].y + eB0.w * wck[3].y
                 + eB1.x * wck[4].y + eB1.y * wck[5].y + eB1.z * wck[6].y + eB1.w * wck[7].y;
            u.z += eB0.x * wck[0].z + eB0.y * wck[1].z + eB0.z * wck[2].z + eB0.w * wck[3].z
                 + eB1.x * wck[4].z + eB1.y * wck[5].z + eB1.z * wck[6].z + eB1.w * wck[7].z;
            u.w += eB0.x * wck[0].w + eB0.y * wck[1].w + eB0.z * wck[2].w + eB0.w * wck[3].w
                 + eB1.x * wck[4].w + eB1.y * wck[5].w + eB1.z * wck[6].w + eB1.w * wck[7].w;
            u.x = fmaxf(u.x + pB.x + qB.x, 0.f);
            u.y = fmaxf(u.y + pB.y + qB.y, 0.f);
            u.z = fmaxf(u.z + pB.z + qB.z, 0.f);
            u.w = fmaxf(u.w + pB.w + qB.w, 0.f);
            *(float4*)(ts + elB * 132 + j0) = u;
        }
        __syncthreads();
        // ---- phase 2 ----
        ull acc[4][4];
#pragma unroll
        for (int e = 0; e < 4; e++) {
            acc[e][0] = b2a.x; acc[e][1] = b2a.y; acc[e][2] = b2b.x; acc[e][3] = b2b.y;
        }
#pragma unroll 2
        for (int jv = 0; jv < 128; jv += 4) {
            float4 t0 = *(const float4*)(ts + (lane) * 132 + jv);
            float4 t1 = *(const float4*)(ts + (lane + 32) * 132 + jv);
            float4 t2 = *(const float4*)(ts + (lane + 64) * 132 + jv);
            float4 t3 = *(const float4*)(ts + (lane + 96) * 132 + jv);
            const float* wbase = We2 + jv * 64 + jb;
            P2STEP(x, 0)
            P2STEP(y, 1)
            P2STEP(z, 2)
            P2STEP(w, 3)
        }
#pragma unroll
        for (int e = 0; e < 4; e++) {
            int el = lane + 32 * e;
            float f[8];
#pragma unroll
            for (int i = 0; i < 4; i++) upk2(acc[e][i], f[2 * i], f[2 * i + 1]);
            float4 o1, o2;
            o1.x = fmaxf(f[0], 0.f); o1.y = fmaxf(f[1], 0.f); o1.z = fmaxf(f[2], 0.f); o1.w = fmaxf(f[3], 0.f);
            o2.x = fmaxf(f[4], 0.f); o2.y = fmaxf(f[5], 0.f); o2.z = fmaxf(f[6], 0.f); o2.w = fmaxf(f[7], 0.f);
            *(float4*)(us + el * 68 + jb) = o1;
            *(float4*)(us + el * 68 + jb + 4) = o2;
        }
        __syncthreads();
        // ---- phase 3 ----
        {
            int el = tid >> 1;
            int o3 = (tid & 1) * 3;
            float a0 = b3s[o3], a1 = b3s[o3 + 1], a2 = b3s[o3 + 2];
#pragma unroll
            for (int q = 0; q < 16; q++) {
                float4 u = *(const float4*)(us + el * 68 + 4 * q);
                float4 w0 = *(const float4*)(w3t + (o3 + 0) * 64 + 4 * q);
                float4 w1 = *(const float4*)(w3t + (o3 + 1) * 64 + 4 * q);
                float4 w2 = *(const float4*)(w3t + (o3 + 2) * 64 + 4 * q);
                a0 += u.x * w0.x + u.y * w0.y + u.z * w0.z + u.w * w0.w;
                a1 += u.x * w1.x + u.y * w1.y + u.z * w1.z + u.w * w1.w;
                a2 += u.x * w2.x + u.y * w2.y + u.z * w2.z + u.w * w2.w;
            }
            int e = e0 + el;
            out[e * 6 + o3 + 0] = a0;
            out[e * 6 + o3 + 1] = a1;
            out[e * 6 + o3 + 2] = a2;
        }
        __syncthreads();
    }
}

// ---------------- launch ----------------
extern "C" void kernel_launch(void* const* d_in, const int* in_sizes, int n_in,
                              void* d_out, int out_size) {
    const float* x    = (const float*)d_in[0];
    const void*  ei   = d_in[1];
    const float* ea   = (const float*)d_in[2];
    const int*   lnum = (const int*)d_in[3];
    const float* Wenc = (const float*)d_in[4];
    const float* benc = (const float*)d_in[5];
    const float* Wmsg = (const float*)d_in[6];
    const float* bmsg = (const float*)d_in[7];
    const float* Wupd = (const float*)d_in[8];
    const float* bupd = (const float*)d_in[9];
    const float* Wn1  = (const float*)d_in[10];
    const float* bn1  = (const float*)d_in[11];
    const float* Wn2  = (const float*)d_in[12];
    const float* bn2  = (const float*)d_in[13];
    const float* We1  = (const float*)d_in[14];
    const float* be1  = (const float*)d_in[15];
    const float* We2  = (const float*)d_in[16];
    const float* be2  = (const float*)d_in[17];
    const float* We3  = (const float*)d_in[18];
    const float* be3  = (const float*)d_in[19];
    float* out = (float*)d_out;

    float *hp, *h2p;
    cudaGetSymbolAddress((void**)&hp,  g_h);
    cudaGetSymbolAddress((void**)&h2p, g_h2);

    const int layerSmem = LAYER_SMEM_FLOATS * 4;
    const int pqSmem    = PQ_SMEM_FLOATS * 4;
    const int nhSmem    = NH_SMEM_FLOATS * 4;
    const int edgeSmem  = EDGE_SMEM_FLOATS * 4;
    cudaFuncSetAttribute(layer_kernel, cudaFuncAttributeMaxDynamicSharedMemorySize, layerSmem);
    cudaFuncSetAttribute(pq_kernel, cudaFuncAttributeMaxDynamicSharedMemorySize, pqSmem);
    cudaFuncSetAttribute(nh_kernel, cudaFuncAttributeMaxDynamicSharedMemorySize, nhSmem);
    cudaFuncSetAttribute(edge_kernel, cudaFuncAttributeMaxDynamicSharedMemorySize, edgeSmem);

    cudaStream_t s0 = 0;
    bool fork = s_fork;

    detect_kernel<<<256, 256, 0, s0>>>((const long long*)ei);
    if (fork) {
        cudaEventRecord(s_ev0, s0);
        cudaStreamWaitEvent(s_b, s_ev0, 0);
        encuv_kernel<<<1312, 128, 0, s_b>>>(x, Wenc, benc, Wmsg, bmsg, Wupd, bupd);
        cudaEventRecord(s_evB, s_b);
    }
    prep_kernel<<<1024, 256, 0, s0>>>(ei);
    scan1_kernel<<<SCAN_NB, SCAN_B, 0, s0>>>();
    scan3_kernel<<<SCAN_NB, SCAN_B, 0, s0>>>();
    scatter_kernel<<<1024, 256, 0, s0>>>();
    if (fork) {
        cudaStreamWaitEvent(s0, s_evB, 0);
    } else {
        encuv_kernel<<<1312, 128, 0, s0>>>(x, Wenc, benc, Wmsg, bmsg, Wupd, bupd);
    }

    for (int L = 0; L < MAX_LAYERS; L++) {
        const float* cur = (L & 1) ? h2p : hp;
        float* nxt = (L & 1) ? hp : h2p;
        layer_kernel<<<LGRID + 16, 256, layerSmem, s0>>>(cur, nxt, lnum, L, Wupd, bupd);
    }

    if (fork) {
        cudaEventRecord(s_ev1, s0);
        cudaStreamWaitEvent(s_b, s_ev1, 0);
        nh_kernel<<<G64, 256, nhSmem, s_b>>>(Wn1, bn1, Wn2, bn2, out, lnum);
        cudaEventRecord(s_evB2, s_b);
    } else {
        nh_kernel<<<G64, 256, nhSmem, s0>>>(Wn1, bn1, Wn2, bn2, out, lnum);
    }
    pq_kernel<<<G64, 256, pqSmem, s0>>>(We1, lnum);
    edge_kernel<<<296, 256, edgeSmem, s0>>>(ea, We1, be1, We2, be2, We3, be3, out + NODE_OUT_ELEMS);
    if (fork) {
        cudaStreamWaitEvent(s0, s_evB2, 0);
    }
}

// round 10
// speedup vs baseline: 1.4214x; 1.4214x over previous
#include <cuda_runtime.h>
#include <cuda_bf16.h>
#include <cstdint>

// Problem constants (fixed by setup_inputs)
#define NN 50000
#define EE 400000
#define HD 128
#define FIN 16
#define EAD 8
#define MAX_LAYERS 6
#define NODE_OUT_ELEMS (NN * 2)
#define G64 ((NN + 63) / 64)   // 782
#define LGRID 391              // 2 tiles per block, 2*391 = 782

typedef unsigned long long ull;

// ---------------- scratch (device globals; no allocation allowed) ----------------
__device__ float g_h[NN * HD];
__device__ float g_h2[NN * HD];
__device__ float g_P[NN * HD];
__device__ float g_Q[NN * HD];
__device__ float g_U[HD * HD];
__device__ float g_V[HD * HD];
__device__ float g_c1[HD];

__device__ int g_src[EE];
__device__ int g_dst[EE];
__device__ int g_csrc[EE];
__device__ int g_deg[NN];
__device__ int g_rowptr[NN + 1];
__device__ int g_cursor[NN];
__device__ int g_zlist[NN];
__device__ int g_zcount;
__device__ int g_is64;
__device__ int g_bsum[128];

// ---------------- f32x2 helpers ----------------
__device__ __forceinline__ ull pk2(float lo, float hi) {
    ull r;
    asm("mov.b64 %0, {%1, %2};" : "=l"(r) : "f"(lo), "f"(hi));
    return r;
}
__device__ __forceinline__ void upk2(ull v, float& lo, float& hi) {
    asm("mov.b64 {%0, %1}, %2;" : "=f"(lo), "=f"(hi) : "l"(v));
}
__device__ __forceinline__ void ffma2(ull& d, ull a, ull b) {
    asm("fma.rn.f32x2 %0, %1, %2, %0;" : "+l"(d) : "l"(a), "l"(b));
}
__device__ __forceinline__ uint32_t smem_u32(const void* p) {
    uint32_t a;
    asm("{ .reg .u64 t; cvta.to.shared.u64 t, %1; cvt.u32.u64 %0, t; }" : "=r"(a) : "l"(p));
    return a;
}

// ---------------- mma.sync helpers (sm_80 baseline PTX — compiles on sm_103) ----------
#define LDM4(R0, R1, R2, R3, ADDR)                                                   \
    asm volatile("ldmatrix.sync.aligned.m8n8.x4.shared.b16 {%0,%1,%2,%3}, [%4];"     \
                 : "=r"(R0), "=r"(R1), "=r"(R2), "=r"(R3) : "r"(ADDR))

#define MMA16816(C, A0, A1, A2, A3, B0, B1)                                          \
    asm volatile("mma.sync.aligned.m16n8k16.row.col.f32.bf16.bf16.f32 "              \
                 "{%0,%1,%2,%3}, {%4,%5,%6,%7}, {%8,%9}, {%0,%1,%2,%3};"             \
                 : "+f"((C)[0]), "+f"((C)[1]), "+f"((C)[2]), "+f"((C)[3])            \
                 : "r"(A0), "r"(A1), "r"(A2), "r"(A3), "r"(B0), "r"(B1))

// ---------------- streams/events for capture-forked concurrency ----------------
static cudaStream_t s_b = 0;
static cudaEvent_t s_ev0 = 0, s_ev1 = 0, s_evB = 0, s_evB2 = 0;
static bool s_fork = false;
static struct StreamInit {
    StreamInit() {
        bool ok = true;
        ok = ok && (cudaStreamCreateWithFlags(&s_b, cudaStreamNonBlocking) == cudaSuccess);
        ok = ok && (cudaEventCreateWithFlags(&s_ev0, cudaEventDisableTiming) == cudaSuccess);
        ok = ok && (cudaEventCreateWithFlags(&s_ev1, cudaEventDisableTiming) == cudaSuccess);
        ok = ok && (cudaEventCreateWithFlags(&s_evB, cudaEventDisableTiming) == cudaSuccess);
        ok = ok && (cudaEventCreateWithFlags(&s_evB2, cudaEventDisableTiming) == cudaSuccess);
        s_fork = ok;
    }
} s_streaminit;

// ---------------- detect dtype + zero deg ----------------
__global__ void detect_kernel(const long long* ei) {
    int idx = blockIdx.x * blockDim.x + threadIdx.x;
    int stride = gridDim.x * blockDim.x;
    for (int i = idx; i < NN; i += stride) g_deg[i] = 0;
    if (idx == 0) g_zcount = 0;
    if (blockIdx.x == 0) {
        __shared__ int bad;
        if (threadIdx.x == 0) bad = 0;
        __syncthreads();
        for (int i = threadIdx.x; i < 1024; i += blockDim.x) {
            long long v = ei[i];
            if (v < 0 || v >= NN) bad = 1;
        }
        __syncthreads();
        if (threadIdx.x == 0) g_is64 = bad ? 0 : 1;
    }
}

// ---------------- prep: convert + histogram ----------------
__global__ void prep_kernel(const void* ei) {
    int idx = blockIdx.x * blockDim.x + threadIdx.x;
    int stride = gridDim.x * blockDim.x;
    int is64 = g_is64;
    const long long* p64 = (const long long*)ei;
    const int* p32 = (const int*)ei;
    for (int i = idx; i < EE; i += stride) {
        int s, d;
        if (is64) {
            s = (int)p64[i];
            d = (int)p64[EE + i];
        } else {
            s = p32[i];
            d = p32[EE + i];
        }
        g_src[i] = s;
        g_dst[i] = d;
        atomicAdd(&g_deg[d], 1);
    }
}

// ---------------- multi-block exclusive scan ----------------
#define SCAN_B 512
#define SCAN_NB ((NN + SCAN_B - 1) / SCAN_B)   // 98

__global__ void scan1_kernel() {
    __shared__ int wsum[16];
    int b = blockIdx.x, tid = threadIdx.x;
    int i = b * SCAN_B + tid;
    int v = (i < NN) ? g_deg[i] : 0;
    int lane = tid & 31, w = tid >> 5;
    int x = v;
#pragma unroll
    for (int off = 1; off < 32; off <<= 1) {
        int t = __shfl_up_sync(0xffffffffu, x, off);
        if (lane >= off) x += t;
    }
    if (lane == 31) wsum[w] = x;
    __syncthreads();
    if (w == 0) {
        int s = (lane < 16) ? wsum[lane] : 0;
#pragma unroll
        for (int off = 1; off < 16; off <<= 1) {
            int t = __shfl_up_sync(0xffffffffu, s, off);
            if (lane >= off) s += t;
        }
        if (lane < 16) wsum[lane] = s;
    }
    __syncthreads();
    int base = (w > 0) ? wsum[w - 1] : 0;
    int incl = base + x;
    if (i < NN) g_rowptr[i] = incl - v;
    if (tid == SCAN_B - 1) g_bsum[b] = incl;
}

__global__ void scan3_kernel() {
    __shared__ int boffs;
    int b = blockIdx.x, tid = threadIdx.x;
    if (tid < 32) {
        int s = 0;
        for (int i = tid; i < b; i += 32) s += g_bsum[i];
#pragma unroll
        for (int off = 16; off >= 1; off >>= 1) s += __shfl_xor_sync(0xffffffffu, s, off);
        if (tid == 0) boffs = s;
    }
    __syncthreads();
    int i = b * SCAN_B + tid;
    if (i < NN) {
        int rp = g_rowptr[i] + boffs;
        g_rowptr[i] = rp;
        g_cursor[i] = rp;
        if (g_deg[i] == 0) {
            int p = atomicAdd(&g_zcount, 1);
            g_zlist[p] = i;
        }
    }
    if (b == 0 && tid == 0) g_rowptr[NN] = EE;
}

__global__ void scatter_kernel() {
    int idx = blockIdx.x * blockDim.x + threadIdx.x;
    int stride = gridDim.x * blockDim.x;
    for (int i = idx; i < EE; i += stride) {
        int d = g_dst[i];
        int pos = atomicAdd(&g_cursor[d], 1);
        g_csrc[pos] = g_src[i];
    }
}

// ---------------- encoder + uv fused ----------------
__global__ void encuv_kernel(const float* __restrict__ x, const float* __restrict__ Wenc,
                             const float* __restrict__ benc,
                             const float* __restrict__ Wmsg, const float* __restrict__ bmsg,
                             const float* __restrict__ Wupd, const float* __restrict__ bupd) {
    if (blockIdx.x >= 1184) {
        int k = blockIdx.x - 1184;   // 0..127
        int j = threadIdx.x;         // 0..127
        float u = Wupd[k * HD + j];
        float v = 0.f;
        for (int t = 0; t < HD; t++) {
            float wub = Wupd[(HD + t) * HD + j];
            u += Wmsg[(HD + k) * HD + t] * wub;
            v += Wmsg[k * HD + t] * wub;
        }
        g_U[k * HD + j] = u;
        g_V[k * HD + j] = v;
        if (k == 0) {
            float c = bupd[j];
            for (int t = 0; t < HD; t++) c += bmsg[t] * Wupd[(HD + t) * HD + j];
            g_c1[j] = c;
        }
        return;
    }
    __shared__ float ws[FIN * HD];
    __shared__ float bs[HD];
    __shared__ float xs[FIN];
    int tid = threadIdx.x;  // 128
    for (int i = tid; i < FIN * HD; i += 128) ws[i] = Wenc[i];
    bs[tid] = benc[tid];
    __syncthreads();
    for (int v = blockIdx.x; v < NN; v += 1184) {
        if (tid < FIN) xs[tid] = x[v * FIN + tid];
        __syncthreads();
        float acc = bs[tid];
#pragma unroll
        for (int k = 0; k < FIN; k++) acc += xs[k] * ws[k * HD + tid];
        g_h[v * HD + tid] = acc;
        __syncthreads();
    }
}

// ---------------- fused layer: agg + h' = relu(h@U + A@V + c1) + zero-deg fixup ----------
// (proven R6 version: smem-staged W chunks)
#define LAYER_SMEM_FLOATS (8448 + 8448 + 1024)
__global__ void __launch_bounds__(256, 3)
layer_kernel(const float* __restrict__ hcur, float* __restrict__ hnext,
             const int* __restrict__ lnum, int layer,
             const float* __restrict__ Wupd, const float* __restrict__ bupd) {
    if (layer >= *lnum) return;
    int tid = threadIdx.x;
    if (blockIdx.x >= LGRID) {
        __shared__ float hs[HD];
        int zc = g_zcount;
        for (int zi = blockIdx.x - LGRID; zi < zc; zi += 16) {
            int v = g_zlist[zi];
            if (tid < 128) hs[tid] = hcur[v * HD + tid];
            __syncthreads();
            if (tid < 128) {
                float acc = bupd[tid];
#pragma unroll 8
                for (int k = 0; k < HD; k++) acc += hs[k] * Wupd[k * HD + tid];
                hnext[v * HD + tid] = fmaxf(acc, 0.f);
            }
            __syncthreads();
        }
        return;
    }
    extern __shared__ float lsm[];
    float* Hst = lsm;            // [k 128][r 64] stride 66
    float* Ast = Hst + 8448;     // [k 128][r 64] stride 66
    float* Ws  = Ast + 8448;     // [8][128] chunk
    int warp = tid >> 5, lane = tid & 31;

    for (int tile = blockIdx.x; tile < G64; tile += LGRID) {
        int row0 = tile * 64;
        __syncthreads();

#pragma unroll 4
        for (int q = 0; q < 32; q++) {
            int e = tid + 256 * q;
            int r = e >> 7, k = e & 127;
            int gr = row0 + r;
            Hst[k * 66 + r] = (gr < NN) ? hcur[gr * HD + k] : 0.f;
        }

        for (int n = warp; n < 64; n += 8) {
            int v = row0 + n;
            float4 a0 = make_float4(0.f, 0.f, 0.f, 0.f);
            float4 a1 = make_float4(0.f, 0.f, 0.f, 0.f);
            float4 a2 = make_float4(0.f, 0.f, 0.f, 0.f);
            float4 a3 = make_float4(0.f, 0.f, 0.f, 0.f);
            int dg = 0;
            if (v < NN) {
                int s0r = g_rowptr[v], s1r = g_rowptr[v + 1];
                dg = s1r - s0r;
                int idx = s0r;
                for (; idx + 3 < s1r; idx += 4) {
                    int i0 = g_csrc[idx], i1 = g_csrc[idx + 1];
                    int i2 = g_csrc[idx + 2], i3 = g_csrc[idx + 3];
                    float4 h0 = __ldg((const float4*)(hcur + i0 * HD + lane * 4));
                    float4 h1 = __ldg((const float4*)(hcur + i1 * HD + lane * 4));
                    float4 h2 = __ldg((const float4*)(hcur + i2 * HD + lane * 4));
                    float4 h3 = __ldg((const float4*)(hcur + i3 * HD + lane * 4));
                    a0.x += h0.x; a0.y += h0.y; a0.z += h0.z; a0.w += h0.w;
                    a1.x += h1.x; a1.y += h1.y; a1.z += h1.z; a1.w += h1.w;
                    a2.x += h2.x; a2.y += h2.y; a2.z += h2.z; a2.w += h2.w;
                    a3.x += h3.x; a3.y += h3.y; a3.z += h3.z; a3.w += h3.w;
                }
                for (; idx < s1r; idx++) {
                    int i0 = g_csrc[idx];
                    float4 h0 = __ldg((const float4*)(hcur + i0 * HD + lane * 4));
                    a0.x += h0.x; a0.y += h0.y; a0.z += h0.z; a0.w += h0.w;
                }
            }
            float inv = 1.f / (float)(dg > 0 ? dg : 1);
            int j0 = lane * 4;
            Ast[(j0 + 0) * 66 + n] = (a0.x + a1.x + a2.x + a3.x) * inv;
            Ast[(j0 + 1) * 66 + n] = (a0.y + a1.y + a2.y + a3.y) * inv;
            Ast[(j0 + 2) * 66 + n] = (a0.z + a1.z + a2.z + a3.z) * inv;
            Ast[(j0 + 3) * 66 + n] = (a0.w + a1.w + a2.w + a3.w) * inv;
        }
        __syncthreads();

        int jb = warp * 16;
        ull acc[2][8];
        {
            const ulonglong2* cp = (const ulonglong2*)(g_c1 + jb);
            ulonglong2 q0 = cp[0], q1 = cp[1], q2 = cp[2], q3 = cp[3];
            acc[0][0] = q0.x; acc[0][1] = q0.y; acc[0][2] = q1.x; acc[0][3] = q1.y;
            acc[0][4] = q2.x; acc[0][5] = q2.y; acc[0][6] = q3.x; acc[0][7] = q3.y;
#pragma unroll
            for (int i = 0; i < 8; i++) acc[1][i] = acc[0][i];
        }
        for (int pass = 0; pass < 2; pass++) {
            const float* Wg = pass ? g_V : g_U;
            const float* Xt = pass ? Ast : Hst;
            for (int c = 0; c < 16; c++) {
#pragma unroll
                for (int q = 0; q < 4; q++) Ws[tid + 256 * q] = Wg[c * 1024 + tid + 256 * q];
                __syncthreads();
#pragma unroll
                for (int kk = 0; kk < 8; kk++) {
                    const float* wr = Ws + kk * 128 + jb;
                    ulonglong2 wA = *(const ulonglong2*)(wr);
                    ulonglong2 wB = *(const ulonglong2*)(wr + 4);
                    ulonglong2 wC = *(const ulonglong2*)(wr + 8);
                    ulonglong2 wD = *(const ulonglong2*)(wr + 12);
                    float2 xv = *(const float2*)(Xt + (c * 8 + kk) * 66 + lane * 2);
                    ull x0 = pk2(xv.x, xv.x), x1 = pk2(xv.y, xv.y);
                    ffma2(acc[0][0], x0, wA.x); ffma2(acc[0][1], x0, wA.y);
                    ffma2(acc[0][2], x0, wB.x); ffma2(acc[0][3], x0, wB.y);
                    ffma2(acc[0][4], x0, wC.x); ffma2(acc[0][5], x0, wC.y);
                    ffma2(acc[0][6], x0, wD.x); ffma2(acc[0][7], x0, wD.y);
                    ffma2(acc[1][0], x1, wA.x); ffma2(acc[1][1], x1, wA.y);
                    ffma2(acc[1][2], x1, wB.x); ffma2(acc[1][3], x1, wB.y);
                    ffma2(acc[1][4], x1, wC.x); ffma2(acc[1][5], x1, wC.y);
                    ffma2(acc[1][6], x1, wD.x); ffma2(acc[1][7], x1, wD.y);
                }
                __syncthreads();
            }
        }
#pragma unroll
        for (int rr = 0; rr < 2; rr++) {
            int r = row0 + lane * 2 + rr;
            if (r < NN && g_deg[r] != 0) {
                float f[16];
#pragma unroll
                for (int i = 0; i < 8; i++) upk2(acc[rr][i], f[2 * i], f[2 * i + 1]);
                float4* dst = (float4*)(hnext + r * HD + jb);
#pragma unroll
                for (int qq = 0; qq < 4; qq++) {
                    float4 o;
                    o.x = fmaxf(f[4 * qq + 0], 0.f); o.y = fmaxf(f[4 * qq + 1], 0.f);
                    o.z = fmaxf(f[4 * qq + 2], 0.f); o.w = fmaxf(f[4 * qq + 3], 0.f);
                    dst[qq] = o;
                }
            }
        }
    }
}

// ---------------- P/Q: P = h@We1[0:128], Q = h@We1[128:256] (proven R6 version) --------
#define PQ_SMEM_FLOATS (8448 + 2048)
__global__ void pq_kernel(const float* __restrict__ We1, const int* __restrict__ lnum) {
    const float* X = ((*lnum) & 1) ? g_h2 : g_h;
    extern __shared__ float psm[];
    float* Hst  = psm;            // [k 128][r 64] stride 66
    float* Wbuf = Hst + 8448;     // 2048 chunk
    int tid = threadIdx.x;
    int warp = tid >> 5, lane = tid & 31;
    int row0 = blockIdx.x * 64;
#pragma unroll 4
    for (int q = 0; q < 32; q++) {
        int e = tid + 256 * q;
        int r = e >> 7, k = e & 127;
        int gr = row0 + r;
        Hst[k * 66 + r] = (gr < NN) ? X[gr * HD + k] : 0.f;
    }
    __syncthreads();

    int jb = warp * 16;
    for (int m = 0; m < 2; m++) {
        const float* Wg = We1 + m * 128 * HD;
        float* C = m ? g_Q : g_P;
        ull acc[2][8];
        ull z = pk2(0.f, 0.f);
#pragma unroll
        for (int i = 0; i < 8; i++) { acc[0][i] = z; acc[1][i] = z; }
        for (int c = 0; c < 8; c++) {
#pragma unroll
            for (int q = 0; q < 8; q++) Wbuf[tid + 256 * q] = Wg[c * 2048 + tid + 256 * q];
            __syncthreads();
#pragma unroll
            for (int kk = 0; kk < 16; kk++) {
                const float* wr = Wbuf + kk * 128 + jb;
                ulonglong2 wA = *(const ulonglong2*)(wr);
                ulonglong2 wB = *(const ulonglong2*)(wr + 4);
                ulonglong2 wC = *(const ulonglong2*)(wr + 8);
                ulonglong2 wD = *(const ulonglong2*)(wr + 12);
                float2 xv = *(const float2*)(Hst + (c * 16 + kk) * 66 + lane * 2);
                ull x0 = pk2(xv.x, xv.x), x1 = pk2(xv.y, xv.y);
                ffma2(acc[0][0], x0, wA.x); ffma2(acc[0][1], x0, wA.y);
                ffma2(acc[0][2], x0, wB.x); ffma2(acc[0][3], x0, wB.y);
                ffma2(acc[0][4], x0, wC.x); ffma2(acc[0][5], x0, wC.y);
                ffma2(acc[0][6], x0, wD.x); ffma2(acc[0][7], x0, wD.y);
                ffma2(acc[1][0], x1, wA.x); ffma2(acc[1][1], x1, wA.y);
                ffma2(acc[1][2], x1, wB.x); ffma2(acc[1][3], x1, wB.y);
                ffma2(acc[1][4], x1, wC.x); ffma2(acc[1][5], x1, wC.y);
                ffma2(acc[1][6], x1, wD.x); ffma2(acc[1][7], x1, wD.y);
            }
            __syncthreads();
        }
#pragma unroll
        for (int rr = 0; rr < 2; rr++) {
            int r = row0 + lane * 2 + rr;
            if (r < NN) {
                float f[16];
#pragma unroll
                for (int i = 0; i < 8; i++) upk2(acc[rr][i], f[2 * i], f[2 * i + 1]);
                float4* dst = (float4*)(C + r * HD + jb);
#pragma unroll
                for (int qq = 0; qq < 4; qq++) {
                    float4 o;
                    o.x = f[4 * qq + 0]; o.y = f[4 * qq + 1];
                    o.z = f[4 * qq + 2]; o.w = f[4 * qq + 3];
                    dst[qq] = o;
                }
            }
        }
    }
}

// ---------------- node head (proven R6 version, on forked stream) ----------------
#define NH_SMEM_FLOATS (8448 + 2048 + 4352 + 128)
__global__ void nh_kernel(const float* __restrict__ Wn1, const float* __restrict__ bn1,
                          const float* __restrict__ Wn2, const float* __restrict__ bn2,
                          float* __restrict__ out, const int* __restrict__ lnum) {
    const float* X = ((*lnum) & 1) ? g_h2 : g_h;
    extern __shared__ float nsm[];
    float* Hst  = nsm;            // [k 128][r 64] stride 66
    float* Wbuf = Hst + 8448;     // 2048 chunk
    float* tsb  = Wbuf + 2048;    // [r 64][j 64] stride 68
    float* W2s  = tsb + 4352;     // 64*2
    int tid = threadIdx.x;
    int warp = tid >> 5, lane = tid & 31;
    int row0 = blockIdx.x * 64;
    if (tid < 128) W2s[tid] = Wn2[tid];
#pragma unroll 4
    for (int q = 0; q < 32; q++) {
        int e = tid + 256 * q;
        int r = e >> 7, k = e & 127;
        int gr = row0 + r;
        Hst[k * 66 + r] = (gr < NN) ? X[gr * HD + k] : 0.f;
    }
    __syncthreads();

    int jb8 = warp * 8;
    ull acc2[2][4];
    {
        ulonglong2 b01 = *(const ulonglong2*)(bn1 + jb8);
        ulonglong2 b23 = *(const ulonglong2*)(bn1 + jb8 + 4);
        acc2[0][0] = b01.x; acc2[0][1] = b01.y; acc2[0][2] = b23.x; acc2[0][3] = b23.y;
#pragma unroll
        for (int i = 0; i < 4; i++) acc2[1][i] = acc2[0][i];
    }
    for (int c = 0; c < 4; c++) {
#pragma unroll
        for (int q = 0; q < 8; q++) Wbuf[tid + 256 * q] = Wn1[c * 2048 + tid + 256 * q];
        __syncthreads();
#pragma unroll 8
        for (int kk = 0; kk < 32; kk++) {
            const float* wr = Wbuf + kk * 64 + jb8;
            ulonglong2 wA = *(const ulonglong2*)(wr);
            ulonglong2 wB = *(const ulonglong2*)(wr + 4);
            float2 xv = *(const float2*)(Hst + (c * 32 + kk) * 66 + lane * 2);
            ull x0 = pk2(xv.x, xv.x), x1 = pk2(xv.y, xv.y);
            ffma2(acc2[0][0], x0, wA.x); ffma2(acc2[0][1], x0, wA.y);
            ffma2(acc2[0][2], x0, wB.x); ffma2(acc2[0][3], x0, wB.y);
            ffma2(acc2[1][0], x1, wA.x); ffma2(acc2[1][1], x1, wA.y);
            ffma2(acc2[1][2], x1, wB.x); ffma2(acc2[1][3], x1, wB.y);
        }
        __syncthreads();
    }
#pragma unroll
    for (int rr = 0; rr < 2; rr++) {
        int r = lane * 2 + rr;
        float f[8];
#pragma unroll
        for (int i = 0; i < 4; i++) upk2(acc2[rr][i], f[2 * i], f[2 * i + 1]);
        float4 o1, o2;
        o1.x = fmaxf(f[0], 0.f); o1.y = fmaxf(f[1], 0.f); o1.z = fmaxf(f[2], 0.f); o1.w = fmaxf(f[3], 0.f);
        o2.x = fmaxf(f[4], 0.f); o2.y = fmaxf(f[5], 0.f); o2.z = fmaxf(f[6], 0.f); o2.w = fmaxf(f[7], 0.f);
        *(float4*)(tsb + r * 68 + jb8) = o1;
        *(float4*)(tsb + r * 68 + jb8 + 4) = o2;
    }
    __syncthreads();
    if (tid < 128) {
        int r = tid >> 1, o = tid & 1;
        float s = 0.f;
#pragma unroll 8
        for (int j = 0; j < 64; j++) s += tsb[r * 68 + j] * W2s[j * 2 + o];
        int gr = row0 + r;
        if (gr < NN) out[gr * 2 + o] = s + bn2[o];
    }
}

// ---------------- fused edge head: mma.sync bf16-split for phase 2 ----------------
// t = relu(P[src]+Q[dst]+ea@We1c+be1)  (fp32, phase1) -> bf16 hi/lo in smem
// D = AhBh + AhBl + AlBh  via mma.sync.m16n8k16 (fp32 accum, registers)
// u = relu(D + be2); out = u@We3 + be3  (in registers, quad shuffle-reduce)
// smem: tsH 34816 | tsL 34816 | bfH 16384 | bfL 16384 | w3t 1536 | b2s 256 | b3s 32
#define EDGE_SMEM_BYTES (34816 + 34816 + 16384 + 16384 + 1536 + 256 + 32)
#define TSL_OFF 34816
#define BFH_OFF 69632
#define BFL_OFF 86016
#define W3T_OFF 102400
#define B2S_OFF 103936
#define B3S_OFF 104192
__global__ void __launch_bounds__(256, 2)
edge_kernel(const float* __restrict__ ea, const float* __restrict__ We1,
            const float* __restrict__ be1, const float* __restrict__ We2,
            const float* __restrict__ be2, const float* __restrict__ We3,
            const float* __restrict__ be3, float* __restrict__ out) {
    extern __shared__ char esm[];
    char* tsH = esm;
    char* tsL = esm + TSL_OFF;
    uint32_t* bfH = (uint32_t*)(esm + BFH_OFF);
    uint32_t* bfL = (uint32_t*)(esm + BFL_OFF);
    float* w3t = (float*)(esm + W3T_OFF);   // [6][64] transposed
    float* b2s = (float*)(esm + B2S_OFF);   // 64
    float* b3s = (float*)(esm + B3S_OFF);   // 8
    __shared__ int esrc[128], edst[128];
    int tid = threadIdx.x, warp = tid >> 5, lane = tid & 31;
    int grp = lane >> 2, tig = lane & 3;
    int j0 = lane * 4;
    uint32_t sb = smem_u32(esm);

    // one-time setup
    for (int i = tid; i < 384; i += 256) w3t[i] = We3[(i & 63) * 6 + (i >> 6)];
    if (tid < 64) b2s[tid] = be2[tid];
    if (tid < 8) b3s[tid] = (tid < 6) ? be3[tid] : 0.f;
    // B fragments: c = ks*16 + nt*2 + r; layout [c][lane]
    for (int c = warp; c < 128; c += 8) {
        int ks = c >> 4, nt = (c >> 1) & 7, r = c & 1;
        int k0 = ks * 16 + tig * 2 + r * 8;
        int n = nt * 8 + grp;
        float v0 = We2[k0 * 64 + n];
        float v1 = We2[(k0 + 1) * 64 + n];
        __nv_bfloat16 h0 = __float2bfloat16_rn(v0);
        __nv_bfloat16 h1 = __float2bfloat16_rn(v1);
        float l0 = v0 - __bfloat162float(h0);
        float l1 = v1 - __bfloat162float(h1);
        uint32_t rh = ((uint32_t)__bfloat16_as_ushort(h1) << 16) | (uint32_t)__bfloat16_as_ushort(h0);
        uint32_t rl;
        asm("cvt.rn.bf16x2.f32 %0, %1, %2;" : "=r"(rl) : "f"(l1), "f"(l0));
        bfH[c * 32 + lane] = rh;
        bfL[c * 32 + lane] = rl;
    }

    // phase-1 constants (hoisted, reused every tile)
    float4 bq = __ldg((const float4*)(be1 + j0));
    float4 wck[8];
#pragma unroll
    for (int k = 0; k < 8; k++)
        wck[k] = __ldg((const float4*)(We1 + 256 * HD + k * 128 + j0));
    __syncthreads();

    for (int e0 = blockIdx.x * 128; e0 < EE; e0 += gridDim.x * 128) {
        if (tid < 128) {
            int e = e0 + tid;
            esrc[tid] = g_src[e];
            edst[tid] = g_dst[e];
        }
        __syncthreads();
        // ---- phase 1: t fp32, split to bf16 hi/lo, store el-major (272 B stride) ----
        for (int it = 0; it < 16; it++) {
            int el = warp + 8 * it;
            int s = esrc[el], d = edst[el];
            float4 pp = __ldg((const float4*)(g_P + s * HD + j0));
            float4 qq = __ldg((const float4*)(g_Q + d * HD + j0));
            float4 e0v = __ldg((const float4*)(ea + (e0 + el) * EAD));
            float4 e1v = __ldg((const float4*)(ea + (e0 + el) * EAD + 4));
            float4 t = bq;
            t.x += e0v.x * wck[0].x + e0v.y * wck[1].x + e0v.z * wck[2].x + e0v.w * wck[3].x
                 + e1v.x * wck[4].x + e1v.y * wck[5].x + e1v.z * wck[6].x + e1v.w * wck[7].x;
            t.y += e0v.x * wck[0].y + e0v.y * wck[1].y + e0v.z * wck[2].y + e0v.w * wck[3].y
                 + e1v.x * wck[4].y + e1v.y * wck[5].y + e1v.z * wck[6].y + e1v.w * wck[7].y;
            t.z += e0v.x * wck[0].z + e0v.y * wck[1].z + e0v.z * wck[2].z + e0v.w * wck[3].z
                 + e1v.x * wck[4].z + e1v.y * wck[5].z + e1v.z * wck[6].z + e1v.w * wck[7].z;
            t.w += e0v.x * wck[0].w + e0v.y * wck[1].w + e0v.z * wck[2].w + e0v.w * wck[3].w
                 + e1v.x * wck[4].w + e1v.y * wck[5].w + e1v.z * wck[6].w + e1v.w * wck[7].w;
            t.x = fmaxf(t.x + pp.x + qq.x, 0.f);
            t.y = fmaxf(t.y + pp.y + qq.y, 0.f);
            t.z = fmaxf(t.z + pp.z + qq.z, 0.f);
            t.w = fmaxf(t.w + pp.w + qq.w, 0.f);
            __nv_bfloat16 hx = __float2bfloat16_rn(t.x), hy = __float2bfloat16_rn(t.y);
            __nv_bfloat16 hz = __float2bfloat16_rn(t.z), hw = __float2bfloat16_rn(t.w);
            float lx = t.x - __bfloat162float(hx), ly = t.y - __bfloat162float(hy);
            float lz = t.z - __bfloat162float(hz), lw = t.w - __bfloat162float(hw);
            uint32_t H01 = ((uint32_t)__bfloat16_as_ushort(hy) << 16) | (uint32_t)__bfloat16_as_ushort(hx);
            uint32_t H23 = ((uint32_t)__bfloat16_as_ushort(hw) << 16) | (uint32_t)__bfloat16_as_ushort(hz);
            uint32_t L01, L23;
            asm("cvt.rn.bf16x2.f32 %0, %1, %2;" : "=r"(L01) : "f"(ly), "f"(lx));
            asm("cvt.rn.bf16x2.f32 %0, %1, %2;" : "=r"(L23) : "f"(lw), "f"(lz));
            *(uint2*)(tsH + el * 272 + lane * 8) = make_uint2(H01, H23);
            *(uint2*)(tsL + el * 272 + lane * 8) = make_uint2(L01, L23);
        }
        __syncthreads();
        // ---- phase 2: warp owns 16 edges (rows), mma over k=128, n=64 ----
        float cfr[8][4];
#pragma unroll
        for (int nt = 0; nt < 8; nt++) {
            cfr[nt][0] = 0.f; cfr[nt][1] = 0.f; cfr[nt][2] = 0.f; cfr[nt][3] = 0.f;
        }
        int mrow0 = warp * 16;
        uint32_t aBase = sb + (uint32_t)((mrow0 + (lane & 15)) * 272 + ((lane >> 4) & 1) * 16);
#pragma unroll
        for (int ks = 0; ks < 8; ks++) {
            uint32_t aH0, aH1, aH2, aH3, aL0, aL1, aL2, aL3;
            uint32_t addrH = aBase + ks * 32;
            LDM4(aH0, aH1, aH2, aH3, addrH);
            LDM4(aL0, aL1, aL2, aL3, addrH + TSL_OFF);
#pragma unroll
            for (int nt = 0; nt < 8; nt++) {
                int ci = ks * 16 + nt * 2;
                uint32_t bh0 = bfH[ci * 32 + lane], bh1 = bfH[(ci + 1) * 32 + lane];
                uint32_t bl0 = bfL[ci * 32 + lane], bl1 = bfL[(ci + 1) * 32 + lane];
                MMA16816(cfr[nt], aH0, aH1, aH2, aH3, bh0, bh1);
                MMA16816(cfr[nt], aH0, aH1, aH2, aH3, bl0, bl1);
                MMA16816(cfr[nt], aL0, aL1, aL2, aL3, bh0, bh1);
            }
        }
        // ---- phase 3: u = relu(C + b2); o6 = u @ We3 (in registers, quad reduce) ----
        float o6a[6], o6b[6];
#pragma unroll
        for (int o = 0; o < 6; o++) { o6a[o] = 0.f; o6b[o] = 0.f; }
#pragma unroll
        for (int nt = 0; nt < 8; nt++) {
            int col0 = nt * 8 + tig * 2;
            float ua0 = fmaxf(cfr[nt][0] + b2s[col0], 0.f);
            float ua1 = fmaxf(cfr[nt][1] + b2s[col0 + 1], 0.f);
            float ub0 = fmaxf(cfr[nt][2] + b2s[col0], 0.f);
            float ub1 = fmaxf(cfr[nt][3] + b2s[col0 + 1], 0.f);
#pragma unroll
            for (int o = 0; o < 6; o++) {
                float w0 = w3t[o * 64 + col0], w1 = w3t[o * 64 + col0 + 1];
                o6a[o] += ua0 * w0 + ua1 * w1;
                o6b[o] += ub0 * w0 + ub1 * w1;
            }
        }
#pragma unroll
        for (int o = 0; o < 6; o++) {
            o6a[o] += __shfl_xor_sync(0xffffffffu, o6a[o], 1);
            o6a[o] += __shfl_xor_sync(0xffffffffu, o6a[o], 2);
            o6b[o] += __shfl_xor_sync(0xffffffffu, o6b[o], 1);
            o6b[o] += __shfl_xor_sync(0xffffffffu, o6b[o], 2);
        }
        if (tig == 0) {
            int eA = e0 + mrow0 + grp;
            int eB = eA + 8;
            *(float2*)(out + eA * 6)     = make_float2(o6a[0] + b3s[0], o6a[1] + b3s[1]);
            *(float2*)(out + eA * 6 + 2) = make_float2(o6a[2] + b3s[2], o6a[3] + b3s[3]);
            *(float2*)(out + eA * 6 + 4) = make_float2(o6a[4] + b3s[4], o6a[5] + b3s[5]);
            *(float2*)(out + eB * 6)     = make_float2(o6b[0] + b3s[0], o6b[1] + b3s[1]);
            *(float2*)(out + eB * 6 + 2) = make_float2(o6b[2] + b3s[2], o6b[3] + b3s[3]);
            *(float2*)(out + eB * 6 + 4) = make_float2(o6b[4] + b3s[4], o6b[5] + b3s[5]);
        }
        __syncthreads();
    }
}

// ---------------- launch ----------------
extern "C" void kernel_launch(void* const* d_in, const int* in_sizes, int n_in,
                              void* d_out, int out_size) {
    const float* x    = (const float*)d_in[0];
    const void*  ei   = d_in[1];
    const float* ea   = (const float*)d_in[2];
    const int*   lnum = (const int*)d_in[3];
    const float* Wenc = (const float*)d_in[4];
    const float* benc = (const float*)d_in[5];
    const float* Wmsg = (const float*)d_in[6];
    const float* bmsg = (const float*)d_in[7];
    const float* Wupd = (const float*)d_in[8];
    const float* bupd = (const float*)d_in[9];
    const float* Wn1  = (const float*)d_in[10];
    const float* bn1  = (const float*)d_in[11];
    const float* Wn2  = (const float*)d_in[12];
    const float* bn2  = (const float*)d_in[13];
    const float* We1  = (const float*)d_in[14];
    const float* be1  = (const float*)d_in[15];
    const float* We2  = (const float*)d_in[16];
    const float* be2  = (const float*)d_in[17];
    const float* We3  = (const float*)d_in[18];
    const float* be3  = (const float*)d_in[19];
    float* out = (float*)d_out;

    float *hp, *h2p;
    cudaGetSymbolAddress((void**)&hp,  g_h);
    cudaGetSymbolAddress((void**)&h2p, g_h2);

    const int layerSmem = LAYER_SMEM_FLOATS * 4;
    const int pqSmem    = PQ_SMEM_FLOATS * 4;
    const int nhSmem    = NH_SMEM_FLOATS * 4;
    const int edgeSmem  = EDGE_SMEM_BYTES;
    cudaFuncSetAttribute(layer_kernel, cudaFuncAttributeMaxDynamicSharedMemorySize, layerSmem);
    cudaFuncSetAttribute(pq_kernel, cudaFuncAttributeMaxDynamicSharedMemorySize, pqSmem);
    cudaFuncSetAttribute(nh_kernel, cudaFuncAttributeMaxDynamicSharedMemorySize, nhSmem);
    cudaFuncSetAttribute(edge_kernel, cudaFuncAttributeMaxDynamicSharedMemorySize, edgeSmem);

    cudaStream_t s0 = 0;
    bool fork = s_fork;

    detect_kernel<<<256, 256, 0, s0>>>((const long long*)ei);
    if (fork) {
        cudaEventRecord(s_ev0, s0);
        cudaStreamWaitEvent(s_b, s_ev0, 0);
        encuv_kernel<<<1312, 128, 0, s_b>>>(x, Wenc, benc, Wmsg, bmsg, Wupd, bupd);
        cudaEventRecord(s_evB, s_b);
    }
    prep_kernel<<<1024, 256, 0, s0>>>(ei);
    scan1_kernel<<<SCAN_NB, SCAN_B, 0, s0>>>();
    scan3_kernel<<<SCAN_NB, SCAN_B, 0, s0>>>();
    scatter_kernel<<<1024, 256, 0, s0>>>();
    if (fork) {
        cudaStreamWaitEvent(s0, s_evB, 0);
    } else {
        encuv_kernel<<<1312, 128, 0, s0>>>(x, Wenc, benc, Wmsg, bmsg, Wupd, bupd);
    }

    for (int L = 0; L < MAX_LAYERS; L++) {
        const float* cur = (L & 1) ? h2p : hp;
        float* nxt = (L & 1) ? hp : h2p;
        layer_kernel<<<LGRID + 16, 256, layerSmem, s0>>>(cur, nxt, lnum, L, Wupd, bupd);
    }

    if (fork) {
        cudaEventRecord(s_ev1, s0);
        cudaStreamWaitEvent(s_b, s_ev1, 0);
        nh_kernel<<<G64, 256, nhSmem, s_b>>>(Wn1, bn1, Wn2, bn2, out, lnum);
        cudaEventRecord(s_evB2, s_b);
    } else {
        nh_kernel<<<G64, 256, nhSmem, s0>>>(Wn1, bn1, Wn2, bn2, out, lnum);
    }
    pq_kernel<<<G64, 256, pqSmem, s0>>>(We1, lnum);
    edge_kernel<<<296, 256, edgeSmem, s0>>>(ea, We1, be1, We2, be2, We3, be3, out + NODE_OUT_ELEMS);
    if (fork) {
        cudaStreamWaitEvent(s0, s_evB2, 0);
    }
}

// round 11
// speedup vs baseline: 1.9338x; 1.3606x over previous
#include <cuda_runtime.h>
#include <cuda_bf16.h>
#include <cstdint>

// Problem constants (fixed by setup_inputs)
#define NN 50000
#define EE 400000
#define HD 128
#define FIN 16
#define EAD 8
#define MAX_LAYERS 6
#define NODE_OUT_ELEMS (NN * 2)
#define G64 ((NN + 63) / 64)   // 782
#define LGRID2 261             // 3 tiles per block (261*3 = 783 >= 782), single wave at occ 2

typedef unsigned long long ull;

// ---------------- scratch (device globals; no allocation allowed) ----------------
__device__ float g_h[NN * HD];
__device__ float g_h2[NN * HD];
__device__ float g_P[NN * HD];
__device__ float g_Q[NN * HD];
__device__ float g_U[HD * HD];
__device__ float g_V[HD * HD];
__device__ float g_c1[HD];

__device__ int g_src[EE];
__device__ int g_dst[EE];
__device__ int g_csrc[EE];
__device__ int g_deg[NN];
__device__ int g_rowptr[NN + 1];
__device__ int g_cursor[NN];
__device__ int g_zlist[NN];
__device__ int g_zcount;
__device__ int g_is64;
__device__ int g_bsum[128];

// W fragments (bf16 hi/lo, mma.sync B-frag layout [c 256][lane 32])
__device__ __align__(16) uint32_t g_Ufh[8192], g_Ufl[8192];
__device__ __align__(16) uint32_t g_Vfh[8192], g_Vfl[8192];
__device__ __align__(16) uint32_t g_Efh[2][8192], g_Efl[2][8192];

// ---------------- f32x2 helpers ----------------
__device__ __forceinline__ ull pk2(float lo, float hi) {
    ull r;
    asm("mov.b64 %0, {%1, %2};" : "=l"(r) : "f"(lo), "f"(hi));
    return r;
}
__device__ __forceinline__ void upk2(ull v, float& lo, float& hi) {
    asm("mov.b64 {%0, %1}, %2;" : "=f"(lo), "=f"(hi) : "l"(v));
}
__device__ __forceinline__ void ffma2(ull& d, ull a, ull b) {
    asm("fma.rn.f32x2 %0, %1, %2, %0;" : "+l"(d) : "l"(a), "l"(b));
}
__device__ __forceinline__ uint32_t smem_u32(const void* p) {
    uint32_t a;
    asm("{ .reg .u64 t; cvta.to.shared.u64 t, %1; cvt.u32.u64 %0, t; }" : "=r"(a) : "l"(p));
    return a;
}

// ---------------- mma.sync helpers (sm_80 baseline PTX — compiles on sm_103) ----------
#define LDM4(R0, R1, R2, R3, ADDR)                                                   \
    asm volatile("ldmatrix.sync.aligned.m8n8.x4.shared.b16 {%0,%1,%2,%3}, [%4];"     \
                 : "=r"(R0), "=r"(R1), "=r"(R2), "=r"(R3) : "r"(ADDR))

#define MMA16816(C, A0, A1, A2, A3, B0, B1)                                          \
    asm volatile("mma.sync.aligned.m16n8k16.row.col.f32.bf16.bf16.f32 "              \
                 "{%0,%1,%2,%3}, {%4,%5,%6,%7}, {%8,%9}, {%0,%1,%2,%3};"             \
                 : "+f"((C)[0]), "+f"((C)[1]), "+f"((C)[2]), "+f"((C)[3])            \
                 : "r"(A0), "r"(A1), "r"(A2), "r"(A3), "r"(B0), "r"(B1))

// split a float4 to bf16x2 hi/lo pairs
#define SPLIT4(T, H01, H23, L01, L23)                                                \
    {                                                                                \
        __nv_bfloat16 _hx = __float2bfloat16_rn((T).x), _hy = __float2bfloat16_rn((T).y); \
        __nv_bfloat16 _hz = __float2bfloat16_rn((T).z), _hw = __float2bfloat16_rn((T).w); \
        float _lx = (T).x - __bfloat162float(_hx), _ly = (T).y - __bfloat162float(_hy);   \
        float _lz = (T).z - __bfloat162float(_hz), _lw = (T).w - __bfloat162float(_hw);   \
        H01 = ((uint32_t)__bfloat16_as_ushort(_hy) << 16) | (uint32_t)__bfloat16_as_ushort(_hx); \
        H23 = ((uint32_t)__bfloat16_as_ushort(_hw) << 16) | (uint32_t)__bfloat16_as_ushort(_hz); \
        asm("cvt.rn.bf16x2.f32 %0, %1, %2;" : "=r"(L01) : "f"(_ly), "f"(_lx));       \
        asm("cvt.rn.bf16x2.f32 %0, %1, %2;" : "=r"(L23) : "f"(_lw), "f"(_lz));       \
    }

// ---------------- streams/events for capture-forked concurrency ----------------
static cudaStream_t s_b = 0;
static cudaEvent_t s_ev0 = 0, s_ev1 = 0, s_evB = 0, s_evB2 = 0;
static bool s_fork = false;
static struct StreamInit {
    StreamInit() {
        bool ok = true;
        ok = ok && (cudaStreamCreateWithFlags(&s_b, cudaStreamNonBlocking) == cudaSuccess);
        ok = ok && (cudaEventCreateWithFlags(&s_ev0, cudaEventDisableTiming) == cudaSuccess);
        ok = ok && (cudaEventCreateWithFlags(&s_ev1, cudaEventDisableTiming) == cudaSuccess);
        ok = ok && (cudaEventCreateWithFlags(&s_evB, cudaEventDisableTiming) == cudaSuccess);
        ok = ok && (cudaEventCreateWithFlags(&s_evB2, cudaEventDisableTiming) == cudaSuccess);
        s_fork = ok;
    }
} s_streaminit;

// ---------------- detect dtype + zero deg ----------------
__global__ void detect_kernel(const long long* ei) {
    int idx = blockIdx.x * blockDim.x + threadIdx.x;
    int stride = gridDim.x * blockDim.x;
    for (int i = idx; i < NN; i += stride) g_deg[i] = 0;
    if (idx == 0) g_zcount = 0;
    if (blockIdx.x == 0) {
        __shared__ int bad;
        if (threadIdx.x == 0) bad = 0;
        __syncthreads();
        for (int i = threadIdx.x; i < 1024; i += blockDim.x) {
            long long v = ei[i];
            if (v < 0 || v >= NN) bad = 1;
        }
        __syncthreads();
        if (threadIdx.x == 0) g_is64 = bad ? 0 : 1;
    }
}

// ---------------- prep: convert + histogram ----------------
__global__ void prep_kernel(const void* ei) {
    int idx = blockIdx.x * blockDim.x + threadIdx.x;
    int stride = gridDim.x * blockDim.x;
    int is64 = g_is64;
    const long long* p64 = (const long long*)ei;
    const int* p32 = (const int*)ei;
    for (int i = idx; i < EE; i += stride) {
        int s, d;
        if (is64) {
            s = (int)p64[i];
            d = (int)p64[EE + i];
        } else {
            s = p32[i];
            d = p32[EE + i];
        }
        g_src[i] = s;
        g_dst[i] = d;
        atomicAdd(&g_deg[d], 1);
    }
}

// ---------------- multi-block exclusive scan ----------------
#define SCAN_B 512
#define SCAN_NB ((NN + SCAN_B - 1) / SCAN_B)   // 98

__global__ void scan1_kernel() {
    __shared__ int wsum[16];
    int b = blockIdx.x, tid = threadIdx.x;
    int i = b * SCAN_B + tid;
    int v = (i < NN) ? g_deg[i] : 0;
    int lane = tid & 31, w = tid >> 5;
    int x = v;
#pragma unroll
    for (int off = 1; off < 32; off <<= 1) {
        int t = __shfl_up_sync(0xffffffffu, x, off);
        if (lane >= off) x += t;
    }
    if (lane == 31) wsum[w] = x;
    __syncthreads();
    if (w == 0) {
        int s = (lane < 16) ? wsum[lane] : 0;
#pragma unroll
        for (int off = 1; off < 16; off <<= 1) {
            int t = __shfl_up_sync(0xffffffffu, s, off);
            if (lane >= off) s += t;
        }
        if (lane < 16) wsum[lane] = s;
    }
    __syncthreads();
    int base = (w > 0) ? wsum[w - 1] : 0;
    int incl = base + x;
    if (i < NN) g_rowptr[i] = incl - v;
    if (tid == SCAN_B - 1) g_bsum[b] = incl;
}

__global__ void scan3_kernel() {
    __shared__ int boffs;
    int b = blockIdx.x, tid = threadIdx.x;
    if (tid < 32) {
        int s = 0;
        for (int i = tid; i < b; i += 32) s += g_bsum[i];
#pragma unroll
        for (int off = 16; off >= 1; off >>= 1) s += __shfl_xor_sync(0xffffffffu, s, off);
        if (tid == 0) boffs = s;
    }
    __syncthreads();
    int i = b * SCAN_B + tid;
    if (i < NN) {
        int rp = g_rowptr[i] + boffs;
        g_rowptr[i] = rp;
        g_cursor[i] = rp;
        if (g_deg[i] == 0) {
            int p = atomicAdd(&g_zcount, 1);
            g_zlist[p] = i;
        }
    }
    if (b == 0 && tid == 0) g_rowptr[NN] = EE;
}

__global__ void scatter_kernel() {
    int idx = blockIdx.x * blockDim.x + threadIdx.x;
    int stride = gridDim.x * blockDim.x;
    for (int i = idx; i < EE; i += stride) {
        int d = g_dst[i];
        int pos = atomicAdd(&g_cursor[d], 1);
        g_csrc[pos] = g_src[i];
    }
}

// ---------------- encoder + uv fused ----------------
__global__ void encuv_kernel(const float* __restrict__ x, const float* __restrict__ Wenc,
                             const float* __restrict__ benc,
                             const float* __restrict__ Wmsg, const float* __restrict__ bmsg,
                             const float* __restrict__ Wupd, const float* __restrict__ bupd) {
    if (blockIdx.x >= 1184) {
        int k = blockIdx.x - 1184;   // 0..127
        int j = threadIdx.x;         // 0..127
        float u = Wupd[k * HD + j];
        float v = 0.f;
        for (int t = 0; t < HD; t++) {
            float wub = Wupd[(HD + t) * HD + j];
            u += Wmsg[(HD + k) * HD + t] * wub;
            v += Wmsg[k * HD + t] * wub;
        }
        g_U[k * HD + j] = u;
        g_V[k * HD + j] = v;
        if (k == 0) {
            float c = bupd[j];
            for (int t = 0; t < HD; t++) c += bmsg[t] * Wupd[(HD + t) * HD + j];
            g_c1[j] = c;
        }
        return;
    }
    __shared__ float ws[FIN * HD];
    __shared__ float bs[HD];
    __shared__ float xs[FIN];
    int tid = threadIdx.x;  // 128
    for (int i = tid; i < FIN * HD; i += 128) ws[i] = Wenc[i];
    bs[tid] = benc[tid];
    __syncthreads();
    for (int v = blockIdx.x; v < NN; v += 1184) {
        if (tid < FIN) xs[tid] = x[v * FIN + tid];
        __syncthreads();
        float acc = bs[tid];
#pragma unroll
        for (int k = 0; k < FIN; k++) acc += xs[k] * ws[k * HD + tid];
        g_h[v * HD + tid] = acc;
        __syncthreads();
    }
}

// ---------------- W fragment precompute (U, V, We1 halves) ----------------
// frag layout identical to validated edge B-frag builder: c = ks*32 + nt*2 + r,
// value = bf16x2 of W[k][n], W[k+1][n], k = ks*16 + tig*2 + r*8, n = nt*8 + grp.
__global__ void wfrag_kernel(const float* __restrict__ We1) {
    int idx0 = blockIdx.x * blockDim.x + threadIdx.x;
    int stride = gridDim.x * blockDim.x;
    for (int t = idx0; t < 4 * 8192; t += stride) {
        int plane = t >> 13, e = t & 8191;
        int c = e >> 5, lane = e & 31;
        int ks = c >> 5, nt = (c >> 1) & 15, r = c & 1;
        int grp = lane >> 2, tig = lane & 3;
        int k = ks * 16 + tig * 2 + r * 8;
        int n = nt * 8 + grp;
        const float* W = (plane == 0) ? g_U : (plane == 1) ? g_V
                       : (plane == 2) ? We1 : (We1 + 128 * HD);
        float v0 = W[k * HD + n];
        float v1 = W[(k + 1) * HD + n];
        __nv_bfloat16 h0 = __float2bfloat16_rn(v0);
        __nv_bfloat16 h1 = __float2bfloat16_rn(v1);
        float l0 = v0 - __bfloat162float(h0);
        float l1 = v1 - __bfloat162float(h1);
        uint32_t rh = ((uint32_t)__bfloat16_as_ushort(h1) << 16) | (uint32_t)__bfloat16_as_ushort(h0);
        uint32_t rl;
        asm("cvt.rn.bf16x2.f32 %0, %1, %2;" : "=r"(rl) : "f"(l1), "f"(l0));
        if (plane == 0) { g_Ufh[e] = rh; g_Ufl[e] = rl; }
        else if (plane == 1) { g_Vfh[e] = rh; g_Vfl[e] = rl; }
        else { g_Efh[plane - 2][e] = rh; g_Efl[plane - 2][e] = rl; }
    }
}

// ---------------- fused layer (tensorized): agg + h' = relu(h@U + A@V + c1) --------
// smem: H_hi 17408 | H_lo 17408 | A_hi 17408 | A_lo 17408 | wf_hi 16384 | wf_lo 16384 | c1s 512
#define L2_H_HI 0
#define L2_H_LO 17408
#define L2_A_HI 34816
#define L2_A_LO 52224
#define L2_WF_HI 69632
#define L2_WF_LO 86016
#define L2_C1S  102400
#define LAYER2_SMEM 102912
__global__ void __launch_bounds__(256, 2)
layer_kernel(const float* __restrict__ hcur, float* __restrict__ hnext,
             const int* __restrict__ lnum, int layer,
             const float* __restrict__ Wupd, const float* __restrict__ bupd) {
    if (layer >= *lnum) return;
    int tid = threadIdx.x;
    if (blockIdx.x >= LGRID2) {
        __shared__ float hs[HD];
        int zc = g_zcount;
        for (int zi = blockIdx.x - LGRID2; zi < zc; zi += 16) {
            int v = g_zlist[zi];
            if (tid < 128) hs[tid] = hcur[v * HD + tid];
            __syncthreads();
            if (tid < 128) {
                float acc = bupd[tid];
#pragma unroll 8
                for (int k = 0; k < HD; k++) acc += hs[k] * Wupd[k * HD + tid];
                hnext[v * HD + tid] = fmaxf(acc, 0.f);
            }
            __syncthreads();
        }
        return;
    }
    extern __shared__ char lsm[];
    uint32_t sb = smem_u32(lsm);
    uint32_t* wfh = (uint32_t*)(lsm + L2_WF_HI);
    uint32_t* wfl = (uint32_t*)(lsm + L2_WF_LO);
    float* c1s = (float*)(lsm + L2_C1S);
    int warp = tid >> 5, lane = tid & 31;
    int grp = lane >> 2, tig = lane & 3;
    if (tid < 128) c1s[tid] = g_c1[tid];

    int wr4 = warp & 3, wc2 = warp >> 2;
    int mrow0 = wr4 * 16;
    uint32_t aAddrH = sb + L2_H_HI + (uint32_t)((mrow0 + (lane & 15)) * 272 + ((lane >> 4) & 1) * 16);
    uint32_t aAddrA = aAddrH + (uint32_t)(L2_A_HI - L2_H_HI);

    for (int tile = blockIdx.x; tile < G64; tile += LGRID2) {
        int row0 = tile * 64;
        __syncthreads();
        // ---- stage H as bf16 hi/lo (row-major, stride 272) ----
#pragma unroll
        for (int q = 0; q < 8; q++) {
            int f = tid + 256 * q;          // 2048 float4 units = 64 rows x 32
            int row = f >> 5, kq = f & 31;
            int gr = row0 + row;
            float4 hv = (gr < NN) ? *(const float4*)(hcur + gr * HD + kq * 4)
                                  : make_float4(0.f, 0.f, 0.f, 0.f);
            uint32_t H01, H23, L01, L23;
            SPLIT4(hv, H01, H23, L01, L23);
            *(uint2*)(lsm + L2_H_HI + row * 272 + kq * 8) = make_uint2(H01, H23);
            *(uint2*)(lsm + L2_H_LO + row * 272 + kq * 8) = make_uint2(L01, L23);
        }
        // ---- mean-aggregate, write bf16 hi/lo directly ----
        for (int n = warp; n < 64; n += 8) {
            int v = row0 + n;
            float4 a0 = make_float4(0.f, 0.f, 0.f, 0.f);
            float4 a1 = make_float4(0.f, 0.f, 0.f, 0.f);
            float4 a2 = make_float4(0.f, 0.f, 0.f, 0.f);
            float4 a3 = make_float4(0.f, 0.f, 0.f, 0.f);
            int dg = 0;
            if (v < NN) {
                int s0r = g_rowptr[v], s1r = g_rowptr[v + 1];
                dg = s1r - s0r;
                int idx = s0r;
                for (; idx + 3 < s1r; idx += 4) {
                    int i0 = g_csrc[idx], i1 = g_csrc[idx + 1];
                    int i2 = g_csrc[idx + 2], i3 = g_csrc[idx + 3];
                    float4 h0 = __ldg((const float4*)(hcur + i0 * HD + lane * 4));
                    float4 h1 = __ldg((const float4*)(hcur + i1 * HD + lane * 4));
                    float4 h2 = __ldg((const float4*)(hcur + i2 * HD + lane * 4));
                    float4 h3 = __ldg((const float4*)(hcur + i3 * HD + lane * 4));
                    a0.x += h0.x; a0.y += h0.y; a0.z += h0.z; a0.w += h0.w;
                    a1.x += h1.x; a1.y += h1.y; a1.z += h1.z; a1.w += h1.w;
                    a2.x += h2.x; a2.y += h2.y; a2.z += h2.z; a2.w += h2.w;
                    a3.x += h3.x; a3.y += h3.y; a3.z += h3.z; a3.w += h3.w;
                }
                for (; idx < s1r; idx++) {
                    int i0 = g_csrc[idx];
                    float4 h0 = __ldg((const float4*)(hcur + i0 * HD + lane * 4));
                    a0.x += h0.x; a0.y += h0.y; a0.z += h0.z; a0.w += h0.w;
                }
            }
            float inv = 1.f / (float)(dg > 0 ? dg : 1);
            float4 s;
            s.x = (a0.x + a1.x + a2.x + a3.x) * inv;
            s.y = (a0.y + a1.y + a2.y + a3.y) * inv;
            s.z = (a0.z + a1.z + a2.z + a3.z) * inv;
            s.w = (a0.w + a1.w + a2.w + a3.w) * inv;
            uint32_t H01, H23, L01, L23;
            SPLIT4(s, H01, H23, L01, L23);
            *(uint2*)(lsm + L2_A_HI + n * 272 + lane * 8) = make_uint2(H01, H23);
            *(uint2*)(lsm + L2_A_LO + n * 272 + lane * 8) = make_uint2(L01, L23);
        }
        __syncthreads();
        // ---- MMA: C = c1 + H@U + A@V  (split-bf16, 3 MMAs per product) ----
        float cfr[8][4];
#pragma unroll
        for (int ntl = 0; ntl < 8; ntl++) {
            int col0 = wc2 * 64 + ntl * 8 + tig * 2;
            float b0 = c1s[col0], b1v = c1s[col0 + 1];
            cfr[ntl][0] = b0; cfr[ntl][1] = b1v; cfr[ntl][2] = b0; cfr[ntl][3] = b1v;
        }
        for (int pass = 0; pass < 2; pass++) {
            const uint32_t* Gh = pass ? g_Vfh : g_Ufh;
            const uint32_t* Gl = pass ? g_Vfl : g_Ufl;
            uint32_t aBase = pass ? aAddrA : aAddrH;
            for (int half = 0; half < 2; half++) {
#pragma unroll
                for (int q = 0; q < 4; q++) {
                    ((uint4*)wfh)[tid + 256 * q] = ((const uint4*)(Gh + half * 4096))[tid + 256 * q];
                    ((uint4*)wfl)[tid + 256 * q] = ((const uint4*)(Gl + half * 4096))[tid + 256 * q];
                }
                __syncthreads();
#pragma unroll
                for (int ksl = 0; ksl < 4; ksl++) {
                    uint32_t addr = aBase + (uint32_t)((half * 4 + ksl) * 32);
                    uint32_t aH0, aH1, aH2, aH3, aL0, aL1, aL2, aL3;
                    LDM4(aH0, aH1, aH2, aH3, addr);
                    LDM4(aL0, aL1, aL2, aL3, addr + 17408);
#pragma unroll
                    for (int ntl = 0; ntl < 8; ntl++) {
                        int ci = ksl * 32 + (wc2 * 8 + ntl) * 2;
                        uint32_t bh0 = wfh[ci * 32 + lane], bh1 = wfh[ci * 32 + 32 + lane];
                        uint32_t bl0 = wfl[ci * 32 + lane], bl1 = wfl[ci * 32 + 32 + lane];
                        MMA16816(cfr[ntl], aH0, aH1, aH2, aH3, bh0, bh1);
                        MMA16816(cfr[ntl], aH0, aH1, aH2, aH3, bl0, bl1);
                        MMA16816(cfr[ntl], aL0, aL1, aL2, aL3, bh0, bh1);
                    }
                }
                __syncthreads();
            }
        }
        // ---- epilogue: relu + deg gate ----
        int r1 = row0 + mrow0 + grp;
        int r2 = r1 + 8;
        int ok1 = (r1 < NN) && (g_deg[r1] != 0);
        int ok2 = (r2 < NN) && (g_deg[r2] != 0);
#pragma unroll
        for (int ntl = 0; ntl < 8; ntl++) {
            int col0 = wc2 * 64 + ntl * 8 + tig * 2;
            if (ok1)
                *(float2*)(hnext + r1 * HD + col0) =
                    make_float2(fmaxf(cfr[ntl][0], 0.f), fmaxf(cfr[ntl][1], 0.f));
            if (ok2)
                *(float2*)(hnext + r2 * HD + col0) =
                    make_float2(fmaxf(cfr[ntl][2], 0.f), fmaxf(cfr[ntl][3], 0.f));
        }
    }
}

// ---------------- P/Q tensorized: P = h@We1[0:128], Q = h@We1[128:256] ----------------
#define PQ2_X_HI 0
#define PQ2_X_LO 17408
#define PQ2_WF_HI 34816
#define PQ2_WF_LO 51200
#define PQ2_SMEM 67584
__global__ void __launch_bounds__(256, 3)
pq_kernel(const int* __restrict__ lnum) {
    const float* X = ((*lnum) & 1) ? g_h2 : g_h;
    extern __shared__ char psm[];
    uint32_t sb = smem_u32(psm);
    uint32_t* wfh = (uint32_t*)(psm + PQ2_WF_HI);
    uint32_t* wfl = (uint32_t*)(psm + PQ2_WF_LO);
    int tid = threadIdx.x;
    int warp = tid >> 5, lane = tid & 31;
    int grp = lane >> 2, tig = lane & 3;
    int wr4 = warp & 3, wc2 = warp >> 2;
    int mrow0 = wr4 * 16;
    uint32_t aBase = sb + PQ2_X_HI + (uint32_t)((mrow0 + (lane & 15)) * 272 + ((lane >> 4) & 1) * 16);

    for (int tile = blockIdx.x; tile < G64; tile += 391) {
        int row0 = tile * 64;
        __syncthreads();
#pragma unroll
        for (int q = 0; q < 8; q++) {
            int f = tid + 256 * q;
            int row = f >> 5, kq = f & 31;
            int gr = row0 + row;
            float4 hv = (gr < NN) ? *(const float4*)(X + gr * HD + kq * 4)
                                  : make_float4(0.f, 0.f, 0.f, 0.f);
            uint32_t H01, H23, L01, L23;
            SPLIT4(hv, H01, H23, L01, L23);
            *(uint2*)(psm + PQ2_X_HI + row * 272 + kq * 8) = make_uint2(H01, H23);
            *(uint2*)(psm + PQ2_X_LO + row * 272 + kq * 8) = make_uint2(L01, L23);
        }
        __syncthreads();
        for (int m = 0; m < 2; m++) {
            float cfr[8][4];
#pragma unroll
            for (int ntl = 0; ntl < 8; ntl++) {
                cfr[ntl][0] = 0.f; cfr[ntl][1] = 0.f; cfr[ntl][2] = 0.f; cfr[ntl][3] = 0.f;
            }
            const uint32_t* Gh = g_Efh[m];
            const uint32_t* Gl = g_Efl[m];
            for (int half = 0; half < 2; half++) {
#pragma unroll
                for (int q = 0; q < 4; q++) {
                    ((uint4*)wfh)[tid + 256 * q] = ((const uint4*)(Gh + half * 4096))[tid + 256 * q];
                    ((uint4*)wfl)[tid + 256 * q] = ((const uint4*)(Gl + half * 4096))[tid + 256 * q];
                }
                __syncthreads();
#pragma unroll
                for (int ksl = 0; ksl < 4; ksl++) {
                    uint32_t addr = aBase + (uint32_t)((half * 4 + ksl) * 32);
                    uint32_t aH0, aH1, aH2, aH3, aL0, aL1, aL2, aL3;
                    LDM4(aH0, aH1, aH2, aH3, addr);
                    LDM4(aL0, aL1, aL2, aL3, addr + 17408);
#pragma unroll
                    for (int ntl = 0; ntl < 8; ntl++) {
                        int ci = ksl * 32 + (wc2 * 8 + ntl) * 2;
                        uint32_t bh0 = wfh[ci * 32 + lane], bh1 = wfh[ci * 32 + 32 + lane];
                        uint32_t bl0 = wfl[ci * 32 + lane], bl1 = wfl[ci * 32 + 32 + lane];
                        MMA16816(cfr[ntl], aH0, aH1, aH2, aH3, bh0, bh1);
                        MMA16816(cfr[ntl], aH0, aH1, aH2, aH3, bl0, bl1);
                        MMA16816(cfr[ntl], aL0, aL1, aL2, aL3, bh0, bh1);
                    }
                }
                __syncthreads();
            }
            float* C = m ? g_Q : g_P;
            int r1 = row0 + mrow0 + grp;
            int r2 = r1 + 8;
#pragma unroll
            for (int ntl = 0; ntl < 8; ntl++) {
                int col0 = wc2 * 64 + ntl * 8 + tig * 2;
                if (r1 < NN) *(float2*)(C + r1 * HD + col0) = make_float2(cfr[ntl][0], cfr[ntl][1]);
                if (r2 < NN) *(float2*)(C + r2 * HD + col0) = make_float2(cfr[ntl][2], cfr[ntl][3]);
            }
        }
    }
}

// ---------------- node head (proven FFMA2 version, on forked stream) ----------------
#define NH_SMEM_FLOATS (8448 + 2048 + 4352 + 128)
__global__ void nh_kernel(const float* __restrict__ Wn1, const float* __restrict__ bn1,
                          const float* __restrict__ Wn2, const float* __restrict__ bn2,
                          float* __restrict__ out, const int* __restrict__ lnum) {
    const float* X = ((*lnum) & 1) ? g_h2 : g_h;
    extern __shared__ float nsm[];
    float* Hst  = nsm;            // [k 128][r 64] stride 66
    float* Wbuf = Hst + 8448;     // 2048 chunk
    float* tsb  = Wbuf + 2048;    // [r 64][j 64] stride 68
    float* W2s  = tsb + 4352;     // 64*2
    int tid = threadIdx.x;
    int warp = tid >> 5, lane = tid & 31;
    int row0 = blockIdx.x * 64;
    if (tid < 128) W2s[tid] = Wn2[tid];
#pragma unroll 4
    for (int q = 0; q < 32; q++) {
        int e = tid + 256 * q;
        int r = e >> 7, k = e & 127;
        int gr = row0 + r;
        Hst[k * 66 + r] = (gr < NN) ? X[gr * HD + k] : 0.f;
    }
    __syncthreads();

    int jb8 = warp * 8;
    ull acc2[2][4];
    {
        ulonglong2 b01 = *(const ulonglong2*)(bn1 + jb8);
        ulonglong2 b23 = *(const ulonglong2*)(bn1 + jb8 + 4);
        acc2[0][0] = b01.x; acc2[0][1] = b01.y; acc2[0][2] = b23.x; acc2[0][3] = b23.y;
#pragma unroll
        for (int i = 0; i < 4; i++) acc2[1][i] = acc2[0][i];
    }
    for (int c = 0; c < 4; c++) {
#pragma unroll
        for (int q = 0; q < 8; q++) Wbuf[tid + 256 * q] = Wn1[c * 2048 + tid + 256 * q];
        __syncthreads();
#pragma unroll 8
        for (int kk = 0; kk < 32; kk++) {
            const float* wr = Wbuf + kk * 64 + jb8;
            ulonglong2 wA = *(const ulonglong2*)(wr);
            ulonglong2 wB = *(const ulonglong2*)(wr + 4);
            float2 xv = *(const float2*)(Hst + (c * 32 + kk) * 66 + lane * 2);
            ull x0 = pk2(xv.x, xv.x), x1 = pk2(xv.y, xv.y);
            ffma2(acc2[0][0], x0, wA.x); ffma2(acc2[0][1], x0, wA.y);
            ffma2(acc2[0][2], x0, wB.x); ffma2(acc2[0][3], x0, wB.y);
            ffma2(acc2[1][0], x1, wA.x); ffma2(acc2[1][1], x1, wA.y);
            ffma2(acc2[1][2], x1, wB.x); ffma2(acc2[1][3], x1, wB.y);
        }
        __syncthreads();
    }
#pragma unroll
    for (int rr = 0; rr < 2; rr++) {
        int r = lane * 2 + rr;
        float f[8];
#pragma unroll
        for (int i = 0; i < 4; i++) upk2(acc2[rr][i], f[2 * i], f[2 * i + 1]);
        float4 o1, o2;
        o1.x = fmaxf(f[0], 0.f); o1.y = fmaxf(f[1], 0.f); o1.z = fmaxf(f[2], 0.f); o1.w = fmaxf(f[3], 0.f);
        o2.x = fmaxf(f[4], 0.f); o2.y = fmaxf(f[5], 0.f); o2.z = fmaxf(f[6], 0.f); o2.w = fmaxf(f[7], 0.f);
        *(float4*)(tsb + r * 68 + jb8) = o1;
        *(float4*)(tsb + r * 68 + jb8 + 4) = o2;
    }
    __syncthreads();
    if (tid < 128) {
        int r = tid >> 1, o = tid & 1;
        float s = 0.f;
#pragma unroll 8
        for (int j = 0; j < 64; j++) s += tsb[r * 68 + j] * W2s[j * 2 + o];
        int gr = row0 + r;
        if (gr < NN) out[gr * 2 + o] = s + bn2[o];
    }
}

// ---------------- fused edge head (proven R10 mma.sync version) ----------------
#define EDGE_SMEM_BYTES (34816 + 34816 + 16384 + 16384 + 1536 + 256 + 32)
#define TSL_OFF 34816
#define BFH_OFF 69632
#define BFL_OFF 86016
#define W3T_OFF 102400
#define B2S_OFF 103936
#define B3S_OFF 104192
__global__ void __launch_bounds__(256, 2)
edge_kernel(const float* __restrict__ ea, const float* __restrict__ We1,
            const float* __restrict__ be1, const float* __restrict__ We2,
            const float* __restrict__ be2, const float* __restrict__ We3,
            const float* __restrict__ be3, float* __restrict__ out) {
    extern __shared__ char esm[];
    char* tsH = esm;
    char* tsL = esm + TSL_OFF;
    uint32_t* bfH = (uint32_t*)(esm + BFH_OFF);
    uint32_t* bfL = (uint32_t*)(esm + BFL_OFF);
    float* w3t = (float*)(esm + W3T_OFF);   // [6][64] transposed
    float* b2s = (float*)(esm + B2S_OFF);   // 64
    float* b3s = (float*)(esm + B3S_OFF);   // 8
    __shared__ int esrc[128], edst[128];
    int tid = threadIdx.x, warp = tid >> 5, lane = tid & 31;
    int grp = lane >> 2, tig = lane & 3;
    int j0 = lane * 4;
    uint32_t sb = smem_u32(esm);

    for (int i = tid; i < 384; i += 256) w3t[i] = We3[(i & 63) * 6 + (i >> 6)];
    if (tid < 64) b2s[tid] = be2[tid];
    if (tid < 8) b3s[tid] = (tid < 6) ? be3[tid] : 0.f;
    for (int c = warp; c < 128; c += 8) {
        int ks = c >> 4, nt = (c >> 1) & 7, r = c & 1;
        int k0 = ks * 16 + tig * 2 + r * 8;
        int n = nt * 8 + grp;
        float v0 = We2[k0 * 64 + n];
        float v1 = We2[(k0 + 1) * 64 + n];
        __nv_bfloat16 h0 = __float2bfloat16_rn(v0);
        __nv_bfloat16 h1 = __float2bfloat16_rn(v1);
        float l0 = v0 - __bfloat162float(h0);
        float l1 = v1 - __bfloat162float(h1);
        uint32_t rh = ((uint32_t)__bfloat16_as_ushort(h1) << 16) | (uint32_t)__bfloat16_as_ushort(h0);
        uint32_t rl;
        asm("cvt.rn.bf16x2.f32 %0, %1, %2;" : "=r"(rl) : "f"(l1), "f"(l0));
        bfH[c * 32 + lane] = rh;
        bfL[c * 32 + lane] = rl;
    }

    float4 bq = __ldg((const float4*)(be1 + j0));
    float4 wck[8];
#pragma unroll
    for (int k = 0; k < 8; k++)
        wck[k] = __ldg((const float4*)(We1 + 256 * HD + k * 128 + j0));
    __syncthreads();

    for (int e0 = blockIdx.x * 128; e0 < EE; e0 += gridDim.x * 128) {
        if (tid < 128) {
            int e = e0 + tid;
            esrc[tid] = g_src[e];
            edst[tid] = g_dst[e];
        }
        __syncthreads();
        for (int it = 0; it < 16; it++) {
            int el = warp + 8 * it;
            int s = esrc[el], d = edst[el];
            float4 pp = __ldg((const float4*)(g_P + s * HD + j0));
            float4 qq = __ldg((const float4*)(g_Q + d * HD + j0));
            float4 e0v = __ldg((const float4*)(ea + (e0 + el) * EAD));
            float4 e1v = __ldg((const float4*)(ea + (e0 + el) * EAD + 4));
            float4 t = bq;
            t.x += e0v.x * wck[0].x + e0v.y * wck[1].x + e0v.z * wck[2].x + e0v.w * wck[3].x
                 + e1v.x * wck[4].x + e1v.y * wck[5].x + e1v.z * wck[6].x + e1v.w * wck[7].x;
            t.y += e0v.x * wck[0].y + e0v.y * wck[1].y + e0v.z * wck[2].y + e0v.w * wck[3].y
                 + e1v.x * wck[4].y + e1v.y * wck[5].y + e1v.z * wck[6].y + e1v.w * wck[7].y;
            t.z += e0v.x * wck[0].z + e0v.y * wck[1].z + e0v.z * wck[2].z + e0v.w * wck[3].z
                 + e1v.x * wck[4].z + e1v.y * wck[5].z + e1v.z * wck[6].z + e1v.w * wck[7].z;
            t.w += e0v.x * wck[0].w + e0v.y * wck[1].w + e0v.z * wck[2].w + e0v.w * wck[3].w
                 + e1v.x * wck[4].w + e1v.y * wck[5].w + e1v.z * wck[6].w + e1v.w * wck[7].w;
            t.x = fmaxf(t.x + pp.x + qq.x, 0.f);
            t.y = fmaxf(t.y + pp.y + qq.y, 0.f);
            t.z = fmaxf(t.z + pp.z + qq.z, 0.f);
            t.w = fmaxf(t.w + pp.w + qq.w, 0.f);
            uint32_t H01, H23, L01, L23;
            SPLIT4(t, H01, H23, L01, L23);
            *(uint2*)(tsH + el * 272 + lane * 8) = make_uint2(H01, H23);
            *(uint2*)(tsL + el * 272 + lane * 8) = make_uint2(L01, L23);
        }
        __syncthreads();
        float cfr[8][4];
#pragma unroll
        for (int nt = 0; nt < 8; nt++) {
            cfr[nt][0] = 0.f; cfr[nt][1] = 0.f; cfr[nt][2] = 0.f; cfr[nt][3] = 0.f;
        }
        int mrow0 = warp * 16;
        uint32_t aBase = sb + (uint32_t)((mrow0 + (lane & 15)) * 272 + ((lane >> 4) & 1) * 16);
#pragma unroll
        for (int ks = 0; ks < 8; ks++) {
            uint32_t aH0, aH1, aH2, aH3, aL0, aL1, aL2, aL3;
            uint32_t addrH = aBase + ks * 32;
            LDM4(aH0, aH1, aH2, aH3, addrH);
            LDM4(aL0, aL1, aL2, aL3, addrH + TSL_OFF);
#pragma unroll
            for (int nt = 0; nt < 8; nt++) {
                int ci = ks * 16 + nt * 2;
                uint32_t bh0 = bfH[ci * 32 + lane], bh1 = bfH[(ci + 1) * 32 + lane];
                uint32_t bl0 = bfL[ci * 32 + lane], bl1 = bfL[(ci + 1) * 32 + lane];
                MMA16816(cfr[nt], aH0, aH1, aH2, aH3, bh0, bh1);
                MMA16816(cfr[nt], aH0, aH1, aH2, aH3, bl0, bl1);
                MMA16816(cfr[nt], aL0, aL1, aL2, aL3, bh0, bh1);
            }
        }
        float o6a[6], o6b[6];
#pragma unroll
        for (int o = 0; o < 6; o++) { o6a[o] = 0.f; o6b[o] = 0.f; }
#pragma unroll
        for (int nt = 0; nt < 8; nt++) {
            int col0 = nt * 8 + tig * 2;
            float ua0 = fmaxf(cfr[nt][0] + b2s[col0], 0.f);
            float ua1 = fmaxf(cfr[nt][1] + b2s[col0 + 1], 0.f);
            float ub0 = fmaxf(cfr[nt][2] + b2s[col0], 0.f);
            float ub1 = fmaxf(cfr[nt][3] + b2s[col0 + 1], 0.f);
#pragma unroll
            for (int o = 0; o < 6; o++) {
                float w0 = w3t[o * 64 + col0], w1 = w3t[o * 64 + col0 + 1];
                o6a[o] += ua0 * w0 + ua1 * w1;
                o6b[o] += ub0 * w0 + ub1 * w1;
            }
        }
#pragma unroll
        for (int o = 0; o < 6; o++) {
            o6a[o] += __shfl_xor_sync(0xffffffffu, o6a[o], 1);
            o6a[o] += __shfl_xor_sync(0xffffffffu, o6a[o], 2);
            o6b[o] += __shfl_xor_sync(0xffffffffu, o6b[o], 1);
            o6b[o] += __shfl_xor_sync(0xffffffffu, o6b[o], 2);
        }
        if (tig == 0) {
            int eA = e0 + mrow0 + grp;
            int eB = eA + 8;
            *(float2*)(out + eA * 6)     = make_float2(o6a[0] + b3s[0], o6a[1] + b3s[1]);
            *(float2*)(out + eA * 6 + 2) = make_float2(o6a[2] + b3s[2], o6a[3] + b3s[3]);
            *(float2*)(out + eA * 6 + 4) = make_float2(o6a[4] + b3s[4], o6a[5] + b3s[5]);
            *(float2*)(out + eB * 6)     = make_float2(o6b[0] + b3s[0], o6b[1] + b3s[1]);
            *(float2*)(out + eB * 6 + 2) = make_float2(o6b[2] + b3s[2], o6b[3] + b3s[3]);
            *(float2*)(out + eB * 6 + 4) = make_float2(o6b[4] + b3s[4], o6b[5] + b3s[5]);
        }
        __syncthreads();
    }
}

// ---------------- launch ----------------
extern "C" void kernel_launch(void* const* d_in, const int* in_sizes, int n_in,
                              void* d_out, int out_size) {
    const float* x    = (const float*)d_in[0];
    const void*  ei   = d_in[1];
    const float* ea   = (const float*)d_in[2];
    const int*   lnum = (const int*)d_in[3];
    const float* Wenc = (const float*)d_in[4];
    const float* benc = (const float*)d_in[5];
    const float* Wmsg = (const float*)d_in[6];
    const float* bmsg = (const float*)d_in[7];
    const float* Wupd = (const float*)d_in[8];
    const float* bupd = (const float*)d_in[9];
    const float* Wn1  = (const float*)d_in[10];
    const float* bn1  = (const float*)d_in[11];
    const float* Wn2  = (const float*)d_in[12];
    const float* bn2  = (const float*)d_in[13];
    const float* We1  = (const float*)d_in[14];
    const float* be1  = (const float*)d_in[15];
    const float* We2  = (const float*)d_in[16];
    const float* be2  = (const float*)d_in[17];
    const float* We3  = (const float*)d_in[18];
    const float* be3  = (const float*)d_in[19];
    float* out = (float*)d_out;

    float *hp, *h2p;
    cudaGetSymbolAddress((void**)&hp,  g_h);
    cudaGetSymbolAddress((void**)&h2p, g_h2);

    const int nhSmem = NH_SMEM_FLOATS * 4;
    cudaFuncSetAttribute(layer_kernel, cudaFuncAttributeMaxDynamicSharedMemorySize, LAYER2_SMEM);
    cudaFuncSetAttribute(pq_kernel, cudaFuncAttributeMaxDynamicSharedMemorySize, PQ2_SMEM);
    cudaFuncSetAttribute(nh_kernel, cudaFuncAttributeMaxDynamicSharedMemorySize, nhSmem);
    cudaFuncSetAttribute(edge_kernel, cudaFuncAttributeMaxDynamicSharedMemorySize, EDGE_SMEM_BYTES);

    cudaStream_t s0 = 0;
    bool fork = s_fork;

    detect_kernel<<<256, 256, 0, s0>>>((const long long*)ei);
    if (fork) {
        cudaEventRecord(s_ev0, s0);
        cudaStreamWaitEvent(s_b, s_ev0, 0);
        encuv_kernel<<<1312, 128, 0, s_b>>>(x, Wenc, benc, Wmsg, bmsg, Wupd, bupd);
        wfrag_kernel<<<64, 256, 0, s_b>>>(We1);
        cudaEventRecord(s_evB, s_b);
    }
    prep_kernel<<<1024, 256, 0, s0>>>(ei);
    scan1_kernel<<<SCAN_NB, SCAN_B, 0, s0>>>();
    scan3_kernel<<<SCAN_NB, SCAN_B, 0, s0>>>();
    scatter_kernel<<<1024, 256, 0, s0>>>();
    if (fork) {
        cudaStreamWaitEvent(s0, s_evB, 0);
    } else {
        encuv_kernel<<<1312, 128, 0, s0>>>(x, Wenc, benc, Wmsg, bmsg, Wupd, bupd);
        wfrag_kernel<<<64, 256, 0, s0>>>(We1);
    }

    for (int L = 0; L < MAX_LAYERS; L++) {
        const float* cur = (L & 1) ? h2p : hp;
        float* nxt = (L & 1) ? hp : h2p;
        layer_kernel<<<LGRID2 + 16, 256, LAYER2_SMEM, s0>>>(cur, nxt, lnum, L, Wupd, bupd);
    }

    if (fork) {
        cudaEventRecord(s_ev1, s0);
        cudaStreamWaitEvent(s_b, s_ev1, 0);
        nh_kernel<<<G64, 256, nhSmem, s_b>>>(Wn1, bn1, Wn2, bn2, out, lnum);
        cudaEventRecord(s_evB2, s_b);
    } else {
        nh_kernel<<<G64, 256, nhSmem, s0>>>(Wn1, bn1, Wn2, bn2, out, lnum);
    }
    pq_kernel<<<391, 256, PQ2_SMEM, s0>>>(lnum);
    edge_kernel<<<296, 256, EDGE_SMEM_BYTES, s0>>>(ea, We1, be1, We2, be2, We3, be3, out + NODE_OUT_ELEMS);
    if (fork) {
        cudaStreamWaitEvent(s0, s_evB2, 0);
    }
}

// round 12
// speedup vs baseline: 1.9839x; 1.0259x over previous
#include <cuda_runtime.h>
#include <cuda_bf16.h>
#include <cstdint>

// Problem constants (fixed by setup_inputs)
#define NN 50000
#define EE 400000
#define HD 128
#define FIN 16
#define EAD 8
#define MAX_LAYERS 6
#define NODE_OUT_ELEMS (NN * 2)
#define G64 ((NN + 63) / 64)   // 782
#define LGRID2 261             // 3 tiles per block (261*3 = 783 >= 782), single wave at occ 2

typedef unsigned long long ull;

// ---------------- scratch (device globals; no allocation allowed) ----------------
__device__ float g_h[NN * HD];
__device__ float g_h2[NN * HD];
__device__ float g_P[NN * HD];
__device__ float g_Q[NN * HD];
__device__ float g_U[HD * HD];
__device__ float g_V[HD * HD];
__device__ float g_c1[HD];

__device__ int g_src[EE];
__device__ int g_dst[EE];
__device__ int g_csrc[EE];    // CSR by dst: src ids
__device__ int g_cdst[EE];    // CSR by dst: dst ids (runs of equal values)
__device__ int g_ceid[EE];    // CSR by dst: original edge ids
__device__ int g_deg[NN];
__device__ int g_rowptr[NN + 1];
__device__ int g_cursor[NN];
__device__ int g_zlist[NN];
__device__ int g_zcount;
__device__ int g_is64;
__device__ int g_bsum[128];

// W fragments (bf16 hi/lo, mma.sync B-frag layout [c 256][lane 32])
__device__ __align__(16) uint32_t g_Ufh[8192], g_Ufl[8192];
__device__ __align__(16) uint32_t g_Vfh[8192], g_Vfl[8192];
__device__ __align__(16) uint32_t g_Efh[2][8192], g_Efl[2][8192];

// ---------------- f32x2 helpers ----------------
__device__ __forceinline__ ull pk2(float lo, float hi) {
    ull r;
    asm("mov.b64 %0, {%1, %2};" : "=l"(r) : "f"(lo), "f"(hi));
    return r;
}
__device__ __forceinline__ void upk2(ull v, float& lo, float& hi) {
    asm("mov.b64 {%0, %1}, %2;" : "=f"(lo), "=f"(hi) : "l"(v));
}
__device__ __forceinline__ void ffma2(ull& d, ull a, ull b) {
    asm("fma.rn.f32x2 %0, %1, %2, %0;" : "+l"(d) : "l"(a), "l"(b));
}
__device__ __forceinline__ uint32_t smem_u32(const void* p) {
    uint32_t a;
    asm("{ .reg .u64 t; cvta.to.shared.u64 t, %1; cvt.u32.u64 %0, t; }" : "=r"(a) : "l"(p));
    return a;
}

// ---------------- mma.sync helpers (sm_80 baseline PTX — compiles on sm_103) ----------
#define LDM4(R0, R1, R2, R3, ADDR)                                                   \
    asm volatile("ldmatrix.sync.aligned.m8n8.x4.shared.b16 {%0,%1,%2,%3}, [%4];"     \
                 : "=r"(R0), "=r"(R1), "=r"(R2), "=r"(R3) : "r"(ADDR))

#define MMA16816(C, A0, A1, A2, A3, B0, B1)                                          \
    asm volatile("mma.sync.aligned.m16n8k16.row.col.f32.bf16.bf16.f32 "              \
                 "{%0,%1,%2,%3}, {%4,%5,%6,%7}, {%8,%9}, {%0,%1,%2,%3};"             \
                 : "+f"((C)[0]), "+f"((C)[1]), "+f"((C)[2]), "+f"((C)[3])            \
                 : "r"(A0), "r"(A1), "r"(A2), "r"(A3), "r"(B0), "r"(B1))

// split a float4 to bf16x2 hi/lo pairs
#define SPLIT4(T, H01, H23, L01, L23)                                                \
    {                                                                                \
        __nv_bfloat16 _hx = __float2bfloat16_rn((T).x), _hy = __float2bfloat16_rn((T).y); \
        __nv_bfloat16 _hz = __float2bfloat16_rn((T).z), _hw = __float2bfloat16_rn((T).w); \
        float _lx = (T).x - __bfloat162float(_hx), _ly = (T).y - __bfloat162float(_hy);   \
        float _lz = (T).z - __bfloat162float(_hz), _lw = (T).w - __bfloat162float(_hw);   \
        H01 = ((uint32_t)__bfloat16_as_ushort(_hy) << 16) | (uint32_t)__bfloat16_as_ushort(_hx); \
        H23 = ((uint32_t)__bfloat16_as_ushort(_hw) << 16) | (uint32_t)__bfloat16_as_ushort(_hz); \
        asm("cvt.rn.bf16x2.f32 %0, %1, %2;" : "=r"(L01) : "f"(_ly), "f"(_lx));       \
        asm("cvt.rn.bf16x2.f32 %0, %1, %2;" : "=r"(L23) : "f"(_lw), "f"(_lz));       \
    }

// ---------------- streams/events for capture-forked concurrency ----------------
static cudaStream_t s_b = 0;
static cudaEvent_t s_ev0 = 0, s_ev1 = 0, s_evB = 0, s_evB2 = 0;
static bool s_fork = false;
static struct StreamInit {
    StreamInit() {
        bool ok = true;
        ok = ok && (cudaStreamCreateWithFlags(&s_b, cudaStreamNonBlocking) == cudaSuccess);
        ok = ok && (cudaEventCreateWithFlags(&s_ev0, cudaEventDisableTiming) == cudaSuccess);
        ok = ok && (cudaEventCreateWithFlags(&s_ev1, cudaEventDisableTiming) == cudaSuccess);
        ok = ok && (cudaEventCreateWithFlags(&s_evB, cudaEventDisableTiming) == cudaSuccess);
        ok = ok && (cudaEventCreateWithFlags(&s_evB2, cudaEventDisableTiming) == cudaSuccess);
        s_fork = ok;
    }
} s_streaminit;

// ---------------- detect dtype + zero deg ----------------
__global__ void detect_kernel(const long long* ei) {
    int idx = blockIdx.x * blockDim.x + threadIdx.x;
    int stride = gridDim.x * blockDim.x;
    for (int i = idx; i < NN; i += stride) g_deg[i] = 0;
    if (idx == 0) g_zcount = 0;
    if (blockIdx.x == 0) {
        __shared__ int bad;
        if (threadIdx.x == 0) bad = 0;
        __syncthreads();
        for (int i = threadIdx.x; i < 1024; i += blockDim.x) {
            long long v = ei[i];
            if (v < 0 || v >= NN) bad = 1;
        }
        __syncthreads();
        if (threadIdx.x == 0) g_is64 = bad ? 0 : 1;
    }
}

// ---------------- prep: convert + histogram ----------------
__global__ void prep_kernel(const void* ei) {
    int idx = blockIdx.x * blockDim.x + threadIdx.x;
    int stride = gridDim.x * blockDim.x;
    int is64 = g_is64;
    const long long* p64 = (const long long*)ei;
    const int* p32 = (const int*)ei;
    for (int i = idx; i < EE; i += stride) {
        int s, d;
        if (is64) {
            s = (int)p64[i];
            d = (int)p64[EE + i];
        } else {
            s = p32[i];
            d = p32[EE + i];
        }
        g_src[i] = s;
        g_dst[i] = d;
        atomicAdd(&g_deg[d], 1);
    }
}

// ---------------- multi-block exclusive scan ----------------
#define SCAN_B 512
#define SCAN_NB ((NN + SCAN_B - 1) / SCAN_B)   // 98

__global__ void scan1_kernel() {
    __shared__ int wsum[16];
    int b = blockIdx.x, tid = threadIdx.x;
    int i = b * SCAN_B + tid;
    int v = (i < NN) ? g_deg[i] : 0;
    int lane = tid & 31, w = tid >> 5;
    int x = v;
#pragma unroll
    for (int off = 1; off < 32; off <<= 1) {
        int t = __shfl_up_sync(0xffffffffu, x, off);
        if (lane >= off) x += t;
    }
    if (lane == 31) wsum[w] = x;
    __syncthreads();
    if (w == 0) {
        int s = (lane < 16) ? wsum[lane] : 0;
#pragma unroll
        for (int off = 1; off < 16; off <<= 1) {
            int t = __shfl_up_sync(0xffffffffu, s, off);
            if (lane >= off) s += t;
        }
        if (lane < 16) wsum[lane] = s;
    }
    __syncthreads();
    int base = (w > 0) ? wsum[w - 1] : 0;
    int incl = base + x;
    if (i < NN) g_rowptr[i] = incl - v;
    if (tid == SCAN_B - 1) g_bsum[b] = incl;
}

__global__ void scan3_kernel() {
    __shared__ int boffs;
    int b = blockIdx.x, tid = threadIdx.x;
    if (tid < 32) {
        int s = 0;
        for (int i = tid; i < b; i += 32) s += g_bsum[i];
#pragma unroll
        for (int off = 16; off >= 1; off >>= 1) s += __shfl_xor_sync(0xffffffffu, s, off);
        if (tid == 0) boffs = s;
    }
    __syncthreads();
    int i = b * SCAN_B + tid;
    if (i < NN) {
        int rp = g_rowptr[i] + boffs;
        g_rowptr[i] = rp;
        g_cursor[i] = rp;
        if (g_deg[i] == 0) {
            int p = atomicAdd(&g_zcount, 1);
            g_zlist[p] = i;
        }
    }
    if (b == 0 && tid == 0) g_rowptr[NN] = EE;
}

__global__ void scatter_kernel() {
    int idx = blockIdx.x * blockDim.x + threadIdx.x;
    int stride = gridDim.x * blockDim.x;
    for (int i = idx; i < EE; i += stride) {
        int d = g_dst[i];
        int pos = atomicAdd(&g_cursor[d], 1);
        g_csrc[pos] = g_src[i];
        g_cdst[pos] = d;
        g_ceid[pos] = i;
    }
}

// ---------------- encoder + uv fused ----------------
__global__ void encuv_kernel(const float* __restrict__ x, const float* __restrict__ Wenc,
                             const float* __restrict__ benc,
                             const float* __restrict__ Wmsg, const float* __restrict__ bmsg,
                             const float* __restrict__ Wupd, const float* __restrict__ bupd) {
    if (blockIdx.x >= 1184) {
        int k = blockIdx.x - 1184;   // 0..127
        int j = threadIdx.x;         // 0..127
        float u = Wupd[k * HD + j];
        float v = 0.f;
        for (int t = 0; t < HD; t++) {
            float wub = Wupd[(HD + t) * HD + j];
            u += Wmsg[(HD + k) * HD + t] * wub;
            v += Wmsg[k * HD + t] * wub;
        }
        g_U[k * HD + j] = u;
        g_V[k * HD + j] = v;
        if (k == 0) {
            float c = bupd[j];
            for (int t = 0; t < HD; t++) c += bmsg[t] * Wupd[(HD + t) * HD + j];
            g_c1[j] = c;
        }
        return;
    }
    __shared__ float ws[FIN * HD];
    __shared__ float bs[HD];
    __shared__ float xs[FIN];
    int tid = threadIdx.x;  // 128
    for (int i = tid; i < FIN * HD; i += 128) ws[i] = Wenc[i];
    bs[tid] = benc[tid];
    __syncthreads();
    for (int v = blockIdx.x; v < NN; v += 1184) {
        if (tid < FIN) xs[tid] = x[v * FIN + tid];
        __syncthreads();
        float acc = bs[tid];
#pragma unroll
        for (int k = 0; k < FIN; k++) acc += xs[k] * ws[k * HD + tid];
        g_h[v * HD + tid] = acc;
        __syncthreads();
    }
}

// ---------------- W fragment precompute (U, V, We1 halves) ----------------
__global__ void wfrag_kernel(const float* __restrict__ We1) {
    int idx0 = blockIdx.x * blockDim.x + threadIdx.x;
    int stride = gridDim.x * blockDim.x;
    for (int t = idx0; t < 4 * 8192; t += stride) {
        int plane = t >> 13, e = t & 8191;
        int c = e >> 5, lane = e & 31;
        int ks = c >> 5, nt = (c >> 1) & 15, r = c & 1;
        int grp = lane >> 2, tig = lane & 3;
        int k = ks * 16 + tig * 2 + r * 8;
        int n = nt * 8 + grp;
        const float* W = (plane == 0) ? g_U : (plane == 1) ? g_V
                       : (plane == 2) ? We1 : (We1 + 128 * HD);
        float v0 = W[k * HD + n];
        float v1 = W[(k + 1) * HD + n];
        __nv_bfloat16 h0 = __float2bfloat16_rn(v0);
        __nv_bfloat16 h1 = __float2bfloat16_rn(v1);
        float l0 = v0 - __bfloat162float(h0);
        float l1 = v1 - __bfloat162float(h1);
        uint32_t rh = ((uint32_t)__bfloat16_as_ushort(h1) << 16) | (uint32_t)__bfloat16_as_ushort(h0);
        uint32_t rl;
        asm("cvt.rn.bf16x2.f32 %0, %1, %2;" : "=r"(rl) : "f"(l1), "f"(l0));
        if (plane == 0) { g_Ufh[e] = rh; g_Ufl[e] = rl; }
        else if (plane == 1) { g_Vfh[e] = rh; g_Vfl[e] = rl; }
        else { g_Efh[plane - 2][e] = rh; g_Efl[plane - 2][e] = rl; }
    }
}

// ---------------- fused layer (tensorized): agg + h' = relu(h@U + A@V + c1) --------
#define L2_H_HI 0
#define L2_H_LO 17408
#define L2_A_HI 34816
#define L2_A_LO 52224
#define L2_WF_HI 69632
#define L2_WF_LO 86016
#define L2_C1S  102400
#define LAYER2_SMEM 102912
__global__ void __launch_bounds__(256, 2)
layer_kernel(const float* __restrict__ hcur, float* __restrict__ hnext,
             const int* __restrict__ lnum, int layer,
             const float* __restrict__ Wupd, const float* __restrict__ bupd) {
    if (layer >= *lnum) return;
    int tid = threadIdx.x;
    if (blockIdx.x >= LGRID2) {
        __shared__ float hs[HD];
        int zc = g_zcount;
        for (int zi = blockIdx.x - LGRID2; zi < zc; zi += 16) {
            int v = g_zlist[zi];
            if (tid < 128) hs[tid] = hcur[v * HD + tid];
            __syncthreads();
            if (tid < 128) {
                float acc = bupd[tid];
#pragma unroll 8
                for (int k = 0; k < HD; k++) acc += hs[k] * Wupd[k * HD + tid];
                hnext[v * HD + tid] = fmaxf(acc, 0.f);
            }
            __syncthreads();
        }
        return;
    }
    extern __shared__ char lsm[];
    uint32_t sb = smem_u32(lsm);
    uint32_t* wfh = (uint32_t*)(lsm + L2_WF_HI);
    uint32_t* wfl = (uint32_t*)(lsm + L2_WF_LO);
    float* c1s = (float*)(lsm + L2_C1S);
    int warp = tid >> 5, lane = tid & 31;
    int grp = lane >> 2, tig = lane & 3;
    if (tid < 128) c1s[tid] = g_c1[tid];

    int wr4 = warp & 3, wc2 = warp >> 2;
    int mrow0 = wr4 * 16;
    uint32_t aAddrH = sb + L2_H_HI + (uint32_t)((mrow0 + (lane & 15)) * 272 + ((lane >> 4) & 1) * 16);
    uint32_t aAddrA = aAddrH + (uint32_t)(L2_A_HI - L2_H_HI);

    for (int tile = blockIdx.x; tile < G64; tile += LGRID2) {
        int row0 = tile * 64;
        __syncthreads();
        // ---- stage H as bf16 hi/lo (row-major, stride 272) ----
#pragma unroll
        for (int q = 0; q < 8; q++) {
            int f = tid + 256 * q;          // 2048 float4 units = 64 rows x 32
            int row = f >> 5, kq = f & 31;
            int gr = row0 + row;
            float4 hv = (gr < NN) ? *(const float4*)(hcur + gr * HD + kq * 4)
                                  : make_float4(0.f, 0.f, 0.f, 0.f);
            uint32_t H01, H23, L01, L23;
            SPLIT4(hv, H01, H23, L01, L23);
            *(uint2*)(lsm + L2_H_HI + row * 272 + kq * 8) = make_uint2(H01, H23);
            *(uint2*)(lsm + L2_H_LO + row * 272 + kq * 8) = make_uint2(L01, L23);
        }
        // ---- mean-aggregate, write bf16 hi/lo directly ----
        for (int n = warp; n < 64; n += 8) {
            int v = row0 + n;
            float4 a0 = make_float4(0.f, 0.f, 0.f, 0.f);
            float4 a1 = make_float4(0.f, 0.f, 0.f, 0.f);
            float4 a2 = make_float4(0.f, 0.f, 0.f, 0.f);
            float4 a3 = make_float4(0.f, 0.f, 0.f, 0.f);
            int dg = 0;
            if (v < NN) {
                int s0r = g_rowptr[v], s1r = g_rowptr[v + 1];
                dg = s1r - s0r;
                int idx = s0r;
                for (; idx + 3 < s1r; idx += 4) {
                    int i0 = g_csrc[idx], i1 = g_csrc[idx + 1];
                    int i2 = g_csrc[idx + 2], i3 = g_csrc[idx + 3];
                    float4 h0 = __ldg((const float4*)(hcur + i0 * HD + lane * 4));
                    float4 h1 = __ldg((const float4*)(hcur + i1 * HD + lane * 4));
                    float4 h2 = __ldg((const float4*)(hcur + i2 * HD + lane * 4));
                    float4 h3 = __ldg((const float4*)(hcur + i3 * HD + lane * 4));
                    a0.x += h0.x; a0.y += h0.y; a0.z += h0.z; a0.w += h0.w;
                    a1.x += h1.x; a1.y += h1.y; a1.z += h1.z; a1.w += h1.w;
                    a2.x += h2.x; a2.y += h2.y; a2.z += h2.z; a2.w += h2.w;
                    a3.x += h3.x; a3.y += h3.y; a3.z += h3.z; a3.w += h3.w;
                }
                for (; idx < s1r; idx++) {
                    int i0 = g_csrc[idx];
                    float4 h0 = __ldg((const float4*)(hcur + i0 * HD + lane * 4));
                    a0.x += h0.x; a0.y += h0.y; a0.z += h0.z; a0.w += h0.w;
                }
            }
            float inv = 1.f / (float)(dg > 0 ? dg : 1);
            float4 s;
            s.x = (a0.x + a1.x + a2.x + a3.x) * inv;
            s.y = (a0.y + a1.y + a2.y + a3.y) * inv;
            s.z = (a0.z + a1.z + a2.z + a3.z) * inv;
            s.w = (a0.w + a1.w + a2.w + a3.w) * inv;
            uint32_t H01, H23, L01, L23;
            SPLIT4(s, H01, H23, L01, L23);
            *(uint2*)(lsm + L2_A_HI + n * 272 + lane * 8) = make_uint2(H01, H23);
            *(uint2*)(lsm + L2_A_LO + n * 272 + lane * 8) = make_uint2(L01, L23);
        }
        __syncthreads();
        // ---- MMA: C = c1 + H@U + A@V  (split-bf16, 3 MMAs per product) ----
        float cfr[8][4];
#pragma unroll
        for (int ntl = 0; ntl < 8; ntl++) {
            int col0 = wc2 * 64 + ntl * 8 + tig * 2;
            float b0 = c1s[col0], b1v = c1s[col0 + 1];
            cfr[ntl][0] = b0; cfr[ntl][1] = b1v; cfr[ntl][2] = b0; cfr[ntl][3] = b1v;
        }
        for (int pass = 0; pass < 2; pass++) {
            const uint32_t* Gh = pass ? g_Vfh : g_Ufh;
            const uint32_t* Gl = pass ? g_Vfl : g_Ufl;
            uint32_t aBase = pass ? aAddrA : aAddrH;
            for (int half = 0; half < 2; half++) {
#pragma unroll
                for (int q = 0; q < 4; q++) {
                    ((uint4*)wfh)[tid + 256 * q] = ((const uint4*)(Gh + half * 4096))[tid + 256 * q];
                    ((uint4*)wfl)[tid + 256 * q] = ((const uint4*)(Gl + half * 4096))[tid + 256 * q];
                }
                __syncthreads();
#pragma unroll
                for (int ksl = 0; ksl < 4; ksl++) {
                    uint32_t addr = aBase + (uint32_t)((half * 4 + ksl) * 32);
                    uint32_t aH0, aH1, aH2, aH3, aL0, aL1, aL2, aL3;
                    LDM4(aH0, aH1, aH2, aH3, addr);
                    LDM4(aL0, aL1, aL2, aL3, addr + 17408);
#pragma unroll
                    for (int ntl = 0; ntl < 8; ntl++) {
                        int ci = ksl * 32 + (wc2 * 8 + ntl) * 2;
                        uint32_t bh0 = wfh[ci * 32 + lane], bh1 = wfh[ci * 32 + 32 + lane];
                        uint32_t bl0 = wfl[ci * 32 + lane], bl1 = wfl[ci * 32 + 32 + lane];
                        MMA16816(cfr[ntl], aH0, aH1, aH2, aH3, bh0, bh1);
                        MMA16816(cfr[ntl], aH0, aH1, aH2, aH3, bl0, bl1);
                        MMA16816(cfr[ntl], aL0, aL1, aL2, aL3, bh0, bh1);
                    }
                }
                __syncthreads();
            }
        }
        // ---- epilogue: relu + deg gate ----
        int r1 = row0 + mrow0 + grp;
        int r2 = r1 + 8;
        int ok1 = (r1 < NN) && (g_deg[r1] != 0);
        int ok2 = (r2 < NN) && (g_deg[r2] != 0);
#pragma unroll
        for (int ntl = 0; ntl < 8; ntl++) {
            int col0 = wc2 * 64 + ntl * 8 + tig * 2;
            if (ok1)
                *(float2*)(hnext + r1 * HD + col0) =
                    make_float2(fmaxf(cfr[ntl][0], 0.f), fmaxf(cfr[ntl][1], 0.f));
            if (ok2)
                *(float2*)(hnext + r2 * HD + col0) =
                    make_float2(fmaxf(cfr[ntl][2], 0.f), fmaxf(cfr[ntl][3], 0.f));
        }
    }
}

// ---------------- P/Q tensorized: P = h@We1[0:128], Q = h@We1[128:256] ----------------
#define PQ2_X_HI 0
#define PQ2_X_LO 17408
#define PQ2_WF_HI 34816
#define PQ2_WF_LO 51200
#define PQ2_SMEM 67584
__global__ void __launch_bounds__(256, 3)
pq_kernel(const int* __restrict__ lnum) {
    const float* X = ((*lnum) & 1) ? g_h2 : g_h;
    extern __shared__ char psm[];
    uint32_t sb = smem_u32(psm);
    uint32_t* wfh = (uint32_t*)(psm + PQ2_WF_HI);
    uint32_t* wfl = (uint32_t*)(psm + PQ2_WF_LO);
    int tid = threadIdx.x;
    int warp = tid >> 5, lane = tid & 31;
    int grp = lane >> 2, tig = lane & 3;
    int wr4 = warp & 3, wc2 = warp >> 2;
    int mrow0 = wr4 * 16;
    uint32_t aBase = sb + PQ2_X_HI + (uint32_t)((mrow0 + (lane & 15)) * 272 + ((lane >> 4) & 1) * 16);

    for (int tile = blockIdx.x; tile < G64; tile += 391) {
        int row0 = tile * 64;
        __syncthreads();
#pragma unroll
        for (int q = 0; q < 8; q++) {
            int f = tid + 256 * q;
            int row = f >> 5, kq = f & 31;
            int gr = row0 + row;
            float4 hv = (gr < NN) ? *(const float4*)(X + gr * HD + kq * 4)
                                  : make_float4(0.f, 0.f, 0.f, 0.f);
            uint32_t H01, H23, L01, L23;
            SPLIT4(hv, H01, H23, L01, L23);
            *(uint2*)(psm + PQ2_X_HI + row * 272 + kq * 8) = make_uint2(H01, H23);
            *(uint2*)(psm + PQ2_X_LO + row * 272 + kq * 8) = make_uint2(L01, L23);
        }
        __syncthreads();
        for (int m = 0; m < 2; m++) {
            float cfr[8][4];
#pragma unroll
            for (int ntl = 0; ntl < 8; ntl++) {
                cfr[ntl][0] = 0.f; cfr[ntl][1] = 0.f; cfr[ntl][2] = 0.f; cfr[ntl][3] = 0.f;
            }
            const uint32_t* Gh = g_Efh[m];
            const uint32_t* Gl = g_Efl[m];
            for (int half = 0; half < 2; half++) {
#pragma unroll
                for (int q = 0; q < 4; q++) {
                    ((uint4*)wfh)[tid + 256 * q] = ((const uint4*)(Gh + half * 4096))[tid + 256 * q];
                    ((uint4*)wfl)[tid + 256 * q] = ((const uint4*)(Gl + half * 4096))[tid + 256 * q];
                }
                __syncthreads();
#pragma unroll
                for (int ksl = 0; ksl < 4; ksl++) {
                    uint32_t addr = aBase + (uint32_t)((half * 4 + ksl) * 32);
                    uint32_t aH0, aH1, aH2, aH3, aL0, aL1, aL2, aL3;
                    LDM4(aH0, aH1, aH2, aH3, addr);
                    LDM4(aL0, aL1, aL2, aL3, addr + 17408);
#pragma unroll
                    for (int ntl = 0; ntl < 8; ntl++) {
                        int ci = ksl * 32 + (wc2 * 8 + ntl) * 2;
                        uint32_t bh0 = wfh[ci * 32 + lane], bh1 = wfh[ci * 32 + 32 + lane];
                        uint32_t bl0 = wfl[ci * 32 + lane], bl1 = wfl[ci * 32 + 32 + lane];
                        MMA16816(cfr[ntl], aH0, aH1, aH2, aH3, bh0, bh1);
                        MMA16816(cfr[ntl], aH0, aH1, aH2, aH3, bl0, bl1);
                        MMA16816(cfr[ntl], aL0, aL1, aL2, aL3, bh0, bh1);
                    }
                }
                __syncthreads();
            }
            float* C = m ? g_Q : g_P;
            int r1 = row0 + mrow0 + grp;
            int r2 = r1 + 8;
#pragma unroll
            for (int ntl = 0; ntl < 8; ntl++) {
                int col0 = wc2 * 64 + ntl * 8 + tig * 2;
                if (r1 < NN) *(float2*)(C + r1 * HD + col0) = make_float2(cfr[ntl][0], cfr[ntl][1]);
                if (r2 < NN) *(float2*)(C + r2 * HD + col0) = make_float2(cfr[ntl][2], cfr[ntl][3]);
            }
        }
    }
}

// ---------------- node head (proven FFMA2 version, on forked stream) ----------------
#define NH_SMEM_FLOATS (8448 + 2048 + 4352 + 128)
__global__ void nh_kernel(const float* __restrict__ Wn1, const float* __restrict__ bn1,
                          const float* __restrict__ Wn2, const float* __restrict__ bn2,
                          float* __restrict__ out, const int* __restrict__ lnum) {
    const float* X = ((*lnum) & 1) ? g_h2 : g_h;
    extern __shared__ float nsm[];
    float* Hst  = nsm;            // [k 128][r 64] stride 66
    float* Wbuf = Hst + 8448;     // 2048 chunk
    float* tsb  = Wbuf + 2048;    // [r 64][j 64] stride 68
    float* W2s  = tsb + 4352;     // 64*2
    int tid = threadIdx.x;
    int warp = tid >> 5, lane = tid & 31;
    int row0 = blockIdx.x * 64;
    if (tid < 128) W2s[tid] = Wn2[tid];
#pragma unroll 4
    for (int q = 0; q < 32; q++) {
        int e = tid + 256 * q;
        int r = e >> 7, k = e & 127;
        int gr = row0 + r;
        Hst[k * 66 + r] = (gr < NN) ? X[gr * HD + k] : 0.f;
    }
    __syncthreads();

    int jb8 = warp * 8;
    ull acc2[2][4];
    {
        ulonglong2 b01 = *(const ulonglong2*)(bn1 + jb8);
        ulonglong2 b23 = *(const ulonglong2*)(bn1 + jb8 + 4);
        acc2[0][0] = b01.x; acc2[0][1] = b01.y; acc2[0][2] = b23.x; acc2[0][3] = b23.y;
#pragma unroll
        for (int i = 0; i < 4; i++) acc2[1][i] = acc2[0][i];
    }
    for (int c = 0; c < 4; c++) {
#pragma unroll
        for (int q = 0; q < 8; q++) Wbuf[tid + 256 * q] = Wn1[c * 2048 + tid + 256 * q];
        __syncthreads();
#pragma unroll 8
        for (int kk = 0; kk < 32; kk++) {
            const float* wr = Wbuf + kk * 64 + jb8;
            ulonglong2 wA = *(const ulonglong2*)(wr);
            ulonglong2 wB = *(const ulonglong2*)(wr + 4);
            float2 xv = *(const float2*)(Hst + (c * 32 + kk) * 66 + lane * 2);
            ull x0 = pk2(xv.x, xv.x), x1 = pk2(xv.y, xv.y);
            ffma2(acc2[0][0], x0, wA.x); ffma2(acc2[0][1], x0, wA.y);
            ffma2(acc2[0][2], x0, wB.x); ffma2(acc2[0][3], x0, wB.y);
            ffma2(acc2[1][0], x1, wA.x); ffma2(acc2[1][1], x1, wA.y);
            ffma2(acc2[1][2], x1, wB.x); ffma2(acc2[1][3], x1, wB.y);
        }
        __syncthreads();
    }
#pragma unroll
    for (int rr = 0; rr < 2; rr++) {
        int r = lane * 2 + rr;
        float f[8];
#pragma unroll
        for (int i = 0; i < 4; i++) upk2(acc2[rr][i], f[2 * i], f[2 * i + 1]);
        float4 o1, o2;
        o1.x = fmaxf(f[0], 0.f); o1.y = fmaxf(f[1], 0.f); o1.z = fmaxf(f[2], 0.f); o1.w = fmaxf(f[3], 0.f);
        o2.x = fmaxf(f[4], 0.f); o2.y = fmaxf(f[5], 0.f); o2.z = fmaxf(f[6], 0.f); o2.w = fmaxf(f[7], 0.f);
        *(float4*)(tsb + r * 68 + jb8) = o1;
        *(float4*)(tsb + r * 68 + jb8 + 4) = o2;
    }
    __syncthreads();
    if (tid < 128) {
        int r = tid >> 1, o = tid & 1;
        float s = 0.f;
#pragma unroll 8
        for (int j = 0; j < 64; j++) s += tsb[r * 68 + j] * W2s[j * 2 + o];
        int gr = row0 + r;
        if (gr < NN) out[gr * 2 + o] = s + bn2[o];
    }
}

// ---------------- fused edge head (mma.sync, CSR-ordered for Q locality) ----------------
// Edges processed in CSR-by-dst order: consecutive edges share dst -> Q[dst] L1 hits.
// Outputs scattered via original edge id.
#define EDGE_SMEM_BYTES (34816 + 34816 + 16384 + 16384 + 1536 + 256 + 32)
#define TSL_OFF 34816
#define BFH_OFF 69632
#define BFL_OFF 86016
#define W3T_OFF 102400
#define B2S_OFF 103936
#define B3S_OFF 104192
__global__ void __launch_bounds__(256, 2)
edge_kernel(const float* __restrict__ ea, const float* __restrict__ We1,
            const float* __restrict__ be1, const float* __restrict__ We2,
            const float* __restrict__ be2, const float* __restrict__ We3,
            const float* __restrict__ be3, float* __restrict__ out) {
    extern __shared__ char esm[];
    char* tsH = esm;
    char* tsL = esm + TSL_OFF;
    uint32_t* bfH = (uint32_t*)(esm + BFH_OFF);
    uint32_t* bfL = (uint32_t*)(esm + BFL_OFF);
    float* w3t = (float*)(esm + W3T_OFF);   // [6][64] transposed
    float* b2s = (float*)(esm + B2S_OFF);   // 64
    float* b3s = (float*)(esm + B3S_OFF);   // 8
    __shared__ int esrc[128], edst[128], eeid[128];
    int tid = threadIdx.x, warp = tid >> 5, lane = tid & 31;
    int grp = lane >> 2, tig = lane & 3;
    int j0 = lane * 4;
    uint32_t sb = smem_u32(esm);

    for (int i = tid; i < 384; i += 256) w3t[i] = We3[(i & 63) * 6 + (i >> 6)];
    if (tid < 64) b2s[tid] = be2[tid];
    if (tid < 8) b3s[tid] = (tid < 6) ? be3[tid] : 0.f;
    for (int c = warp; c < 128; c += 8) {
        int ks = c >> 4, nt = (c >> 1) & 7, r = c & 1;
        int k0 = ks * 16 + tig * 2 + r * 8;
        int n = nt * 8 + grp;
        float v0 = We2[k0 * 64 + n];
        float v1 = We2[(k0 + 1) * 64 + n];
        __nv_bfloat16 h0 = __float2bfloat16_rn(v0);
        __nv_bfloat16 h1 = __float2bfloat16_rn(v1);
        float l0 = v0 - __bfloat162float(h0);
        float l1 = v1 - __bfloat162float(h1);
        uint32_t rh = ((uint32_t)__bfloat16_as_ushort(h1) << 16) | (uint32_t)__bfloat16_as_ushort(h0);
        uint32_t rl;
        asm("cvt.rn.bf16x2.f32 %0, %1, %2;" : "=r"(rl) : "f"(l1), "f"(l0));
        bfH[c * 32 + lane] = rh;
        bfL[c * 32 + lane] = rl;
    }

    float4 bq = __ldg((const float4*)(be1 + j0));
    float4 wck[8];
#pragma unroll
    for (int k = 0; k < 8; k++)
        wck[k] = __ldg((const float4*)(We1 + 256 * HD + k * 128 + j0));
    __syncthreads();

    for (int e0 = blockIdx.x * 128; e0 < EE; e0 += gridDim.x * 128) {
        if (tid < 128) {
            int e = e0 + tid;
            esrc[tid] = g_csrc[e];
            edst[tid] = g_cdst[e];
            eeid[tid] = g_ceid[e];
        }
        __syncthreads();
        for (int it = 0; it < 16; it++) {
            int el = warp + 8 * it;
            int s = esrc[el], d = edst[el], eid = eeid[el];
            float4 pp = __ldg((const float4*)(g_P + s * HD + j0));
            float4 qq = __ldg((const float4*)(g_Q + d * HD + j0));
            float4 e0v = __ldg((const float4*)(ea + eid * EAD));
            float4 e1v = __ldg((const float4*)(ea + eid * EAD + 4));
            float4 t = bq;
            t.x += e0v.x * wck[0].x + e0v.y * wck[1].x + e0v.z * wck[2].x + e0v.w * wck[3].x
                 + e1v.x * wck[4].x + e1v.y * wck[5].x + e1v.z * wck[6].x + e1v.w * wck[7].x;
            t.y += e0v.x * wck[0].y + e0v.y * wck[1].y + e0v.z * wck[2].y + e0v.w * wck[3].y
                 + e1v.x * wck[4].y + e1v.y * wck[5].y + e1v.z * wck[6].y + e1v.w * wck[7].y;
            t.z += e0v.x * wck[0].z + e0v.y * wck[1].z + e0v.z * wck[2].z + e0v.w * wck[3].z
                 + e1v.x * wck[4].z + e1v.y * wck[5].z + e1v.z * wck[6].z + e1v.w * wck[7].z;
            t.w += e0v.x * wck[0].w + e0v.y * wck[1].w + e0v.z * wck[2].w + e0v.w * wck[3].w
                 + e1v.x * wck[4].w + e1v.y * wck[5].w + e1v.z * wck[6].w + e1v.w * wck[7].w;
            t.x = fmaxf(t.x + pp.x + qq.x, 0.f);
            t.y = fmaxf(t.y + pp.y + qq.y, 0.f);
            t.z = fmaxf(t.z + pp.z + qq.z, 0.f);
            t.w = fmaxf(t.w + pp.w + qq.w, 0.f);
            uint32_t H01, H23, L01, L23;
            SPLIT4(t, H01, H23, L01, L23);
            *(uint2*)(tsH + el * 272 + lane * 8) = make_uint2(H01, H23);
            *(uint2*)(tsL + el * 272 + lane * 8) = make_uint2(L01, L23);
        }
        __syncthreads();
        float cfr[8][4];
#pragma unroll
        for (int nt = 0; nt < 8; nt++) {
            cfr[nt][0] = 0.f; cfr[nt][1] = 0.f; cfr[nt][2] = 0.f; cfr[nt][3] = 0.f;
        }
        int mrow0 = warp * 16;
        uint32_t aBase = sb + (uint32_t)((mrow0 + (lane & 15)) * 272 + ((lane >> 4) & 1) * 16);
#pragma unroll
        for (int ks = 0; ks < 8; ks++) {
            uint32_t aH0, aH1, aH2, aH3, aL0, aL1, aL2, aL3;
            uint32_t addrH = aBase + ks * 32;
            LDM4(aH0, aH1, aH2, aH3, addrH);
            LDM4(aL0, aL1, aL2, aL3, addrH + TSL_OFF);
#pragma unroll
            for (int nt = 0; nt < 8; nt++) {
                int ci = ks * 16 + nt * 2;
                uint32_t bh0 = bfH[ci * 32 + lane], bh1 = bfH[(ci + 1) * 32 + lane];
                uint32_t bl0 = bfL[ci * 32 + lane], bl1 = bfL[(ci + 1) * 32 + lane];
                MMA16816(cfr[nt], aH0, aH1, aH2, aH3, bh0, bh1);
                MMA16816(cfr[nt], aH0, aH1, aH2, aH3, bl0, bl1);
                MMA16816(cfr[nt], aL0, aL1, aL2, aL3, bh0, bh1);
            }
        }
        float o6a[6], o6b[6];
#pragma unroll
        for (int o = 0; o < 6; o++) { o6a[o] = 0.f; o6b[o] = 0.f; }
#pragma unroll
        for (int nt = 0; nt < 8; nt++) {
            int col0 = nt * 8 + tig * 2;
            float ua0 = fmaxf(cfr[nt][0] + b2s[col0], 0.f);
            float ua1 = fmaxf(cfr[nt][1] + b2s[col0 + 1], 0.f);
            float ub0 = fmaxf(cfr[nt][2] + b2s[col0], 0.f);
            float ub1 = fmaxf(cfr[nt][3] + b2s[col0 + 1], 0.f);
#pragma unroll
            for (int o = 0; o < 6; o++) {
                float w0 = w3t[o * 64 + col0], w1 = w3t[o * 64 + col0 + 1];
                o6a[o] += ua0 * w0 + ua1 * w1;
                o6b[o] += ub0 * w0 + ub1 * w1;
            }
        }
#pragma unroll
        for (int o = 0; o < 6; o++) {
            o6a[o] += __shfl_xor_sync(0xffffffffu, o6a[o], 1);
            o6a[o] += __shfl_xor_sync(0xffffffffu, o6a[o], 2);
            o6b[o] += __shfl_xor_sync(0xffffffffu, o6b[o], 1);
            o6b[o] += __shfl_xor_sync(0xffffffffu, o6b[o], 2);
        }
        if (tig == 0) {
            int eidA = eeid[mrow0 + grp];
            int eidB = eeid[mrow0 + grp + 8];
            *(float2*)(out + eidA * 6)     = make_float2(o6a[0] + b3s[0], o6a[1] + b3s[1]);
            *(float2*)(out + eidA * 6 + 2) = make_float2(o6a[2] + b3s[2], o6a[3] + b3s[3]);
            *(float2*)(out + eidA * 6 + 4) = make_float2(o6a[4] + b3s[4], o6a[5] + b3s[5]);
            *(float2*)(out + eidB * 6)     = make_float2(o6b[0] + b3s[0], o6b[1] + b3s[1]);
            *(float2*)(out + eidB * 6 + 2) = make_float2(o6b[2] + b3s[2], o6b[3] + b3s[3]);
            *(float2*)(out + eidB * 6 + 4) = make_float2(o6b[4] + b3s[4], o6b[5] + b3s[5]);
        }
        __syncthreads();
    }
}

// ---------------- launch ----------------
extern "C" void kernel_launch(void* const* d_in, const int* in_sizes, int n_in,
                              void* d_out, int out_size) {
    const float* x    = (const float*)d_in[0];
    const void*  ei   = d_in[1];
    const float* ea   = (const float*)d_in[2];
    const int*   lnum = (const int*)d_in[3];
    const float* Wenc = (const float*)d_in[4];
    const float* benc = (const float*)d_in[5];
    const float* Wmsg = (const float*)d_in[6];
    const float* bmsg = (const float*)d_in[7];
    const float* Wupd = (const float*)d_in[8];
    const float* bupd = (const float*)d_in[9];
    const float* Wn1  = (const float*)d_in[10];
    const float* bn1  = (const float*)d_in[11];
    const float* Wn2  = (const float*)d_in[12];
    const float* bn2  = (const float*)d_in[13];
    const float* We1  = (const float*)d_in[14];
    const float* be1  = (const float*)d_in[15];
    const float* We2  = (const float*)d_in[16];
    const float* be2  = (const float*)d_in[17];
    const float* We3  = (const float*)d_in[18];
    const float* be3  = (const float*)d_in[19];
    float* out = (float*)d_out;

    float *hp, *h2p;
    cudaGetSymbolAddress((void**)&hp,  g_h);
    cudaGetSymbolAddress((void**)&h2p, g_h2);

    const int nhSmem = NH_SMEM_FLOATS * 4;
    cudaFuncSetAttribute(layer_kernel, cudaFuncAttributeMaxDynamicSharedMemorySize, LAYER2_SMEM);
    cudaFuncSetAttribute(pq_kernel, cudaFuncAttributeMaxDynamicSharedMemorySize, PQ2_SMEM);
    cudaFuncSetAttribute(nh_kernel, cudaFuncAttributeMaxDynamicSharedMemorySize, nhSmem);
    cudaFuncSetAttribute(edge_kernel, cudaFuncAttributeMaxDynamicSharedMemorySize, EDGE_SMEM_BYTES);

    cudaStream_t s0 = 0;
    bool fork = s_fork;

    detect_kernel<<<256, 256, 0, s0>>>((const long long*)ei);
    if (fork) {
        cudaEventRecord(s_ev0, s0);
        cudaStreamWaitEvent(s_b, s_ev0, 0);
        encuv_kernel<<<1312, 128, 0, s_b>>>(x, Wenc, benc, Wmsg, bmsg, Wupd, bupd);
        wfrag_kernel<<<64, 256, 0, s_b>>>(We1);
        cudaEventRecord(s_evB, s_b);
    }
    prep_kernel<<<1024, 256, 0, s0>>>(ei);
    scan1_kernel<<<SCAN_NB, SCAN_B, 0, s0>>>();
    scan3_kernel<<<SCAN_NB, SCAN_B, 0, s0>>>();
    scatter_kernel<<<1024, 256, 0, s0>>>();
    if (fork) {
        cudaStreamWaitEvent(s0, s_evB, 0);
    } else {
        encuv_kernel<<<1312, 128, 0, s0>>>(x, Wenc, benc, Wmsg, bmsg, Wupd, bupd);
        wfrag_kernel<<<64, 256, 0, s0>>>(We1);
    }

    for (int L = 0; L < MAX_LAYERS; L++) {
        const float* cur = (L & 1) ? h2p : hp;
        float* nxt = (L & 1) ? hp : h2p;
        layer_kernel<<<LGRID2 + 16, 256, LAYER2_SMEM, s0>>>(cur, nxt, lnum, L, Wupd, bupd);
    }

    if (fork) {
        cudaEventRecord(s_ev1, s0);
        cudaStreamWaitEvent(s_b, s_ev1, 0);
        nh_kernel<<<G64, 256, nhSmem, s_b>>>(Wn1, bn1, Wn2, bn2, out, lnum);
        cudaEventRecord(s_evB2, s_b);
    } else {
        nh_kernel<<<G64, 256, nhSmem, s0>>>(Wn1, bn1, Wn2, bn2, out, lnum);
    }
    pq_kernel<<<391, 256, PQ2_SMEM, s0>>>(lnum);
    edge_kernel<<<296, 256, EDGE_SMEM_BYTES, s0>>>(ea, We1, be1, We2, be2, We3, be3, out + NODE_OUT_ELEMS);
    if (fork) {
        cudaStreamWaitEvent(s0, s_evB2, 0);
    }
}

// round 14
// speedup vs baseline: 2.1096x; 1.0633x over previous
#include <cuda_runtime.h>
#include <cuda_bf16.h>
#include <cstdint>

// Problem constants (fixed by setup_inputs)
#define NN 50000
#define EE 400000
#define HD 128
#define FIN 16
#define EAD 8
#define MAX_LAYERS 4
#define NODE_OUT_ELEMS (NN * 2)
#define G64 ((NN + 63) / 64)   // 782
#define LGRID 391              // 2 tiles per block, single wave at occ 3

typedef unsigned long long ull;

// ---------------- scratch (device globals; no allocation allowed) ----------------
__device__ float g_h[NN * HD];
__device__ float g_h2[NN * HD];
__device__ float g_P[NN * HD];
__device__ float g_Q[NN * HD];
__device__ float g_U[HD * HD];
__device__ float g_V[HD * HD];
__device__ float g_c1[HD];

__device__ int g_src[EE];
__device__ int g_dst[EE];
__device__ int g_csrc[EE];     // CSR by dst: src ids (for layer agg)
__device__ int2 g_cse[EE];     // CSR by dst: (src, eid) for edge kernel
__device__ int g_cdst[EE];     // CSR by dst: dst ids
__device__ int g_deg[NN];
__device__ int g_rowptr[NN + 1];
__device__ int g_cursor[NN];
__device__ int g_zlist[NN];
__device__ int g_zcount;
__device__ int g_is64;
__device__ int g_bsum[128];

// W fragments (bf16 hi/lo, mma.sync B-frag layout [c 256][lane 32])
__device__ __align__(16) uint32_t g_Ufh[8192], g_Ufl[8192];
__device__ __align__(16) uint32_t g_Vfh[8192], g_Vfl[8192];
__device__ __align__(16) uint32_t g_Efh[2][8192], g_Efl[2][8192];

// ---------------- f32x2 helpers ----------------
__device__ __forceinline__ ull pk2(float lo, float hi) {
    ull r;
    asm("mov.b64 %0, {%1, %2};" : "=l"(r) : "f"(lo), "f"(hi));
    return r;
}
__device__ __forceinline__ void upk2(ull v, float& lo, float& hi) {
    asm("mov.b64 {%0, %1}, %2;" : "=f"(lo), "=f"(hi) : "l"(v));
}
__device__ __forceinline__ void ffma2(ull& d, ull a, ull b) {
    asm("fma.rn.f32x2 %0, %1, %2, %0;" : "+l"(d) : "l"(a), "l"(b));
}
__device__ __forceinline__ uint32_t smem_u32(const void* p) {
    uint32_t a;
    asm("{ .reg .u64 t; cvta.to.shared.u64 t, %1; cvt.u32.u64 %0, t; }" : "=r"(a) : "l"(p));
    return a;
}

// ---------------- mma.sync helpers (sm_80 baseline PTX — compiles on sm_103) ----------
#define LDM4(R0, R1, R2, R3, ADDR)                                                   \
    asm volatile("ldmatrix.sync.aligned.m8n8.x4.shared.b16 {%0,%1,%2,%3}, [%4];"     \
                 : "=r"(R0), "=r"(R1), "=r"(R2), "=r"(R3) : "r"(ADDR))

#define MMA16816(C, A0, A1, A2, A3, B0, B1)                                          \
    asm volatile("mma.sync.aligned.m16n8k16.row.col.f32.bf16.bf16.f32 "              \
                 "{%0,%1,%2,%3}, {%4,%5,%6,%7}, {%8,%9}, {%0,%1,%2,%3};"             \
                 : "+f"((C)[0]), "+f"((C)[1]), "+f"((C)[2]), "+f"((C)[3])            \
                 : "r"(A0), "r"(A1), "r"(A2), "r"(A3), "r"(B0), "r"(B1))

// split a float4 to bf16x2 hi/lo pairs
#define SPLIT4(T, H01, H23, L01, L23)                                                \
    {                                                                                \
        __nv_bfloat16 _hx = __float2bfloat16_rn((T).x), _hy = __float2bfloat16_rn((T).y); \
        __nv_bfloat16 _hz = __float2bfloat16_rn((T).z), _hw = __float2bfloat16_rn((T).w); \
        float _lx = (T).x - __bfloat162float(_hx), _ly = (T).y - __bfloat162float(_hy);   \
        float _lz = (T).z - __bfloat162float(_hz), _lw = (T).w - __bfloat162float(_hw);   \
        H01 = ((uint32_t)__bfloat16_as_ushort(_hy) << 16) | (uint32_t)__bfloat16_as_ushort(_hx); \
        H23 = ((uint32_t)__bfloat16_as_ushort(_hw) << 16) | (uint32_t)__bfloat16_as_ushort(_hz); \
        asm("cvt.rn.bf16x2.f32 %0, %1, %2;" : "=r"(L01) : "f"(_ly), "f"(_lx));       \
        asm("cvt.rn.bf16x2.f32 %0, %1, %2;" : "=r"(L23) : "f"(_lw), "f"(_lz));       \
    }

// ---------------- streams/events for capture-forked concurrency ----------------
static cudaStream_t s_b = 0;
static cudaEvent_t s_ev0 = 0, s_ev1 = 0, s_evB = 0, s_evB2 = 0;
static bool s_fork = false;
static struct StreamInit {
    StreamInit() {
        bool ok = true;
        ok = ok && (cudaStreamCreateWithFlags(&s_b, cudaStreamNonBlocking) == cudaSuccess);
        ok = ok && (cudaEventCreateWithFlags(&s_ev0, cudaEventDisableTiming) == cudaSuccess);
        ok = ok && (cudaEventCreateWithFlags(&s_ev1, cudaEventDisableTiming) == cudaSuccess);
        ok = ok && (cudaEventCreateWithFlags(&s_evB, cudaEventDisableTiming) == cudaSuccess);
        ok = ok && (cudaEventCreateWithFlags(&s_evB2, cudaEventDisableTiming) == cudaSuccess);
        s_fork = ok;
    }
} s_streaminit;

// ---------------- detect dtype + zero deg ----------------
__global__ void detect_kernel(const long long* ei) {
    int idx = blockIdx.x * blockDim.x + threadIdx.x;
    int stride = gridDim.x * blockDim.x;
    for (int i = idx; i < NN; i += stride) g_deg[i] = 0;
    if (idx == 0) g_zcount = 0;
    if (blockIdx.x == 0) {
        __shared__ int bad;
        if (threadIdx.x == 0) bad = 0;
        __syncthreads();
        for (int i = threadIdx.x; i < 1024; i += blockDim.x) {
            long long v = ei[i];
            if (v < 0 || v >= NN) bad = 1;
        }
        __syncthreads();
        if (threadIdx.x == 0) g_is64 = bad ? 0 : 1;
    }
}

// ---------------- prep: convert + histogram ----------------
__global__ void prep_kernel(const void* ei) {
    int idx = blockIdx.x * blockDim.x + threadIdx.x;
    int stride = gridDim.x * blockDim.x;
    int is64 = g_is64;
    const long long* p64 = (const long long*)ei;
    const int* p32 = (const int*)ei;
    for (int i = idx; i < EE; i += stride) {
        int s, d;
        if (is64) {
            s = (int)p64[i];
            d = (int)p64[EE + i];
        } else {
            s = p32[i];
            d = p32[EE + i];
        }
        g_src[i] = s;
        g_dst[i] = d;
        atomicAdd(&g_deg[d], 1);
    }
}

// ---------------- multi-block exclusive scan ----------------
#define SCAN_B 512
#define SCAN_NB ((NN + SCAN_B - 1) / SCAN_B)   // 98

__global__ void scan1_kernel() {
    __shared__ int wsum[16];
    int b = blockIdx.x, tid = threadIdx.x;
    int i = b * SCAN_B + tid;
    int v = (i < NN) ? g_deg[i] : 0;
    int lane = tid & 31, w = tid >> 5;
    int x = v;
#pragma unroll
    for (int off = 1; off < 32; off <<= 1) {
        int t = __shfl_up_sync(0xffffffffu, x, off);
        if (lane >= off) x += t;
    }
    if (lane == 31) wsum[w] = x;
    __syncthreads();
    if (w == 0) {
        int s = (lane < 16) ? wsum[lane] : 0;
#pragma unroll
        for (int off = 1; off < 16; off <<= 1) {
            int t = __shfl_up_sync(0xffffffffu, s, off);
            if (lane >= off) s += t;
        }
        if (lane < 16) wsum[lane] = s;
    }
    __syncthreads();
    int base = (w > 0) ? wsum[w - 1] : 0;
    int incl = base + x;
    if (i < NN) g_rowptr[i] = incl - v;
    if (tid == SCAN_B - 1) g_bsum[b] = incl;
}

__global__ void scan3_kernel() {
    __shared__ int boffs;
    int b = blockIdx.x, tid = threadIdx.x;
    if (tid < 32) {
        int s = 0;
        for (int i = tid; i < b; i += 32) s += g_bsum[i];
#pragma unroll
        for (int off = 16; off >= 1; off >>= 1) s += __shfl_xor_sync(0xffffffffu, s, off);
        if (tid == 0) boffs = s;
    }
    __syncthreads();
    int i = b * SCAN_B + tid;
    if (i < NN) {
        int rp = g_rowptr[i] + boffs;
        g_rowptr[i] = rp;
        g_cursor[i] = rp;
        if (g_deg[i] == 0) {
            int p = atomicAdd(&g_zcount, 1);
            g_zlist[p] = i;
        }
    }
    if (b == 0 && tid == 0) g_rowptr[NN] = EE;
}

__global__ void scatter_kernel() {
    int idx = blockIdx.x * blockDim.x + threadIdx.x;
    int stride = gridDim.x * blockDim.x;
    for (int i = idx; i < EE; i += stride) {
        int d = g_dst[i];
        int s = g_src[i];
        int pos = atomicAdd(&g_cursor[d], 1);
        g_csrc[pos] = s;
        g_cse[pos] = make_int2(s, i);
        g_cdst[pos] = d;
    }
}

// ---------------- encoder + uv fused ----------------
__global__ void encuv_kernel(const float* __restrict__ x, const float* __restrict__ Wenc,
                             const float* __restrict__ benc,
                             const float* __restrict__ Wmsg, const float* __restrict__ bmsg,
                             const float* __restrict__ Wupd, const float* __restrict__ bupd) {
    if (blockIdx.x >= 1184) {
        int k = blockIdx.x - 1184;   // 0..127
        int j = threadIdx.x;         // 0..127
        float u = Wupd[k * HD + j];
        float v = 0.f;
        for (int t = 0; t < HD; t++) {
            float wub = Wupd[(HD + t) * HD + j];
            u += Wmsg[(HD + k) * HD + t] * wub;
            v += Wmsg[k * HD + t] * wub;
        }
        g_U[k * HD + j] = u;
        g_V[k * HD + j] = v;
        if (k == 0) {
            float c = bupd[j];
            for (int t = 0; t < HD; t++) c += bmsg[t] * Wupd[(HD + t) * HD + j];
            g_c1[j] = c;
        }
        return;
    }
    __shared__ float ws[FIN * HD];
    __shared__ float bs[HD];
    __shared__ float xs[FIN];
    int tid = threadIdx.x;  // 128
    for (int i = tid; i < FIN * HD; i += 128) ws[i] = Wenc[i];
    bs[tid] = benc[tid];
    __syncthreads();
    for (int v = blockIdx.x; v < NN; v += 1184) {
        if (tid < FIN) xs[tid] = x[v * FIN + tid];
        __syncthreads();
        float acc = bs[tid];
#pragma unroll
        for (int k = 0; k < FIN; k++) acc += xs[k] * ws[k * HD + tid];
        g_h[v * HD + tid] = acc;
        __syncthreads();
    }
}

// ---------------- W fragment precompute (U, V, We1 halves) ----------------
__global__ void wfrag_kernel(const float* __restrict__ We1) {
    int idx0 = blockIdx.x * blockDim.x + threadIdx.x;
    int stride = gridDim.x * blockDim.x;
    for (int t = idx0; t < 4 * 8192; t += stride) {
        int plane = t >> 13, e = t & 8191;
        int c = e >> 5, lane = e & 31;
        int ks = c >> 5, nt = (c >> 1) & 15, r = c & 1;
        int grp = lane >> 2, tig = lane & 3;
        int k = ks * 16 + tig * 2 + r * 8;
        int n = nt * 8 + grp;
        const float* W = (plane == 0) ? g_U : (plane == 1) ? g_V
                       : (plane == 2) ? We1 : (We1 + 128 * HD);
        float v0 = W[k * HD + n];
        float v1 = W[(k + 1) * HD + n];
        __nv_bfloat16 h0 = __float2bfloat16_rn(v0);
        __nv_bfloat16 h1 = __float2bfloat16_rn(v1);
        float l0 = v0 - __bfloat162float(h0);
        float l1 = v1 - __bfloat162float(h1);
        uint32_t rh = ((uint32_t)__bfloat16_as_ushort(h1) << 16) | (uint32_t)__bfloat16_as_ushort(h0);
        uint32_t rl;
        asm("cvt.rn.bf16x2.f32 %0, %1, %2;" : "=r"(rl) : "f"(l1), "f"(l0));
        if (plane == 0) { g_Ufh[e] = rh; g_Ufl[e] = rl; }
        else if (plane == 1) { g_Vfh[e] = rh; g_Vfl[e] = rl; }
        else { g_Efh[plane - 2][e] = rh; g_Efl[plane - 2][e] = rl; }
    }
}

// ---------------- fused layer (tensorized, occ 3): agg + h' = relu(h@U + A@V + c1) -----
// B-frags read directly from L1-resident global arrays (coalesced __ldg, no smem staging).
// smem: H_hi 17408 | H_lo 17408 | A_hi 17408 | A_lo 17408 | c1s 512 = 70 KB -> occ 3
#define L2_H_HI 0
#define L2_H_LO 17408
#define L2_A_HI 34816
#define L2_A_LO 52224
#define L2_C1S  69632
#define LAYER2_SMEM 70144
__global__ void __launch_bounds__(256, 3)
layer_kernel(const float* __restrict__ hcur, float* __restrict__ hnext,
             const int* __restrict__ lnum, int layer,
             const float* __restrict__ Wupd, const float* __restrict__ bupd) {
    if (layer >= *lnum) return;
    int tid = threadIdx.x;
    if (blockIdx.x >= LGRID) {
        __shared__ float hs[HD];
        int zc = g_zcount;
        for (int zi = blockIdx.x - LGRID; zi < zc; zi += 16) {
            int v = g_zlist[zi];
            if (tid < 128) hs[tid] = hcur[v * HD + tid];
            __syncthreads();
            if (tid < 128) {
                float acc = bupd[tid];
#pragma unroll 8
                for (int k = 0; k < HD; k++) acc += hs[k] * Wupd[k * HD + tid];
                hnext[v * HD + tid] = fmaxf(acc, 0.f);
            }
            __syncthreads();
        }
        return;
    }
    extern __shared__ char lsm[];
    uint32_t sb = smem_u32(lsm);
    float* c1s = (float*)(lsm + L2_C1S);
    int warp = tid >> 5, lane = tid & 31;
    int grp = lane >> 2, tig = lane & 3;
    if (tid < 128) c1s[tid] = g_c1[tid];

    int wr4 = warp & 3, wc2 = warp >> 2;
    int mrow0 = wr4 * 16;
    uint32_t aAddrH = sb + L2_H_HI + (uint32_t)((mrow0 + (lane & 15)) * 272 + ((lane >> 4) & 1) * 16);
    uint32_t aAddrA = aAddrH + (uint32_t)(L2_A_HI - L2_H_HI);

    for (int tile = blockIdx.x; tile < G64; tile += LGRID) {
        int row0 = tile * 64;
        __syncthreads();
        // ---- stage H as bf16 hi/lo (row-major, stride 272) ----
#pragma unroll
        for (int q = 0; q < 8; q++) {
            int f = tid + 256 * q;          // 2048 float4 units = 64 rows x 32
            int row = f >> 5, kq = f & 31;
            int gr = row0 + row;
            float4 hv = (gr < NN) ? *(const float4*)(hcur + gr * HD + kq * 4)
                                  : make_float4(0.f, 0.f, 0.f, 0.f);
            uint32_t H01, H23, L01, L23;
            SPLIT4(hv, H01, H23, L01, L23);
            *(uint2*)(lsm + L2_H_HI + row * 272 + kq * 8) = make_uint2(H01, H23);
            *(uint2*)(lsm + L2_H_LO + row * 272 + kq * 8) = make_uint2(L01, L23);
        }
        // ---- mean-aggregate, write bf16 hi/lo directly ----
        for (int n = warp; n < 64; n += 8) {
            int v = row0 + n;
            float4 a0 = make_float4(0.f, 0.f, 0.f, 0.f);
            float4 a1 = make_float4(0.f, 0.f, 0.f, 0.f);
            float4 a2 = make_float4(0.f, 0.f, 0.f, 0.f);
            float4 a3 = make_float4(0.f, 0.f, 0.f, 0.f);
            int dg = 0;
            if (v < NN) {
                int s0r = g_rowptr[v], s1r = g_rowptr[v + 1];
                dg = s1r - s0r;
                int idx = s0r;
                for (; idx + 3 < s1r; idx += 4) {
                    int i0 = g_csrc[idx], i1 = g_csrc[idx + 1];
                    int i2 = g_csrc[idx + 2], i3 = g_csrc[idx + 3];
                    float4 h0 = __ldg((const float4*)(hcur + i0 * HD + lane * 4));
                    float4 h1 = __ldg((const float4*)(hcur + i1 * HD + lane * 4));
                    float4 h2 = __ldg((const float4*)(hcur + i2 * HD + lane * 4));
                    float4 h3 = __ldg((const float4*)(hcur + i3 * HD + lane * 4));
                    a0.x += h0.x; a0.y += h0.y; a0.z += h0.z; a0.w += h0.w;
                    a1.x += h1.x; a1.y += h1.y; a1.z += h1.z; a1.w += h1.w;
                    a2.x += h2.x; a2.y += h2.y; a2.z += h2.z; a2.w += h2.w;
                    a3.x += h3.x; a3.y += h3.y; a3.z += h3.z; a3.w += h3.w;
                }
                for (; idx < s1r; idx++) {
                    int i0 = g_csrc[idx];
                    float4 h0 = __ldg((const float4*)(hcur + i0 * HD + lane * 4));
                    a0.x += h0.x; a0.y += h0.y; a0.z += h0.z; a0.w += h0.w;
                }
            }
            float inv = 1.f / (float)(dg > 0 ? dg : 1);
            float4 s;
            s.x = (a0.x + a1.x + a2.x + a3.x) * inv;
            s.y = (a0.y + a1.y + a2.y + a3.y) * inv;
            s.z = (a0.z + a1.z + a2.z + a3.z) * inv;
            s.w = (a0.w + a1.w + a2.w + a3.w) * inv;
            uint32_t H01, H23, L01, L23;
            SPLIT4(s, H01, H23, L01, L23);
            *(uint2*)(lsm + L2_A_HI + n * 272 + lane * 8) = make_uint2(H01, H23);
            *(uint2*)(lsm + L2_A_LO + n * 272 + lane * 8) = make_uint2(L01, L23);
        }
        __syncthreads();
        // ---- MMA: C = c1 + H@U + A@V  (split-bf16; B frags via coalesced __ldg) ----
        float cfr[8][4];
#pragma unroll
        for (int ntl = 0; ntl < 8; ntl++) {
            int col0 = wc2 * 64 + ntl * 8 + tig * 2;
            float b0 = c1s[col0], b1v = c1s[col0 + 1];
            cfr[ntl][0] = b0; cfr[ntl][1] = b1v; cfr[ntl][2] = b0; cfr[ntl][3] = b1v;
        }
        for (int pass = 0; pass < 2; pass++) {
            const uint32_t* Gh = pass ? g_Vfh : g_Ufh;
            const uint32_t* Gl = pass ? g_Vfl : g_Ufl;
            uint32_t aBase = pass ? aAddrA : aAddrH;
#pragma unroll
            for (int ks = 0; ks < 8; ks++) {
                uint32_t addr = aBase + (uint32_t)(ks * 32);
                uint32_t aH0, aH1, aH2, aH3, aL0, aL1, aL2, aL3;
                LDM4(aH0, aH1, aH2, aH3, addr);
                LDM4(aL0, aL1, aL2, aL3, addr + 17408);
#pragma unroll
                for (int ntl = 0; ntl < 8; ntl++) {
                    int ci = ks * 32 + (wc2 * 16 + ntl * 2);
                    uint32_t bh0 = __ldg(Gh + ci * 32 + lane);
                    uint32_t bh1 = __ldg(Gh + ci * 32 + 32 + lane);
                    uint32_t bl0 = __ldg(Gl + ci * 32 + lane);
                    uint32_t bl1 = __ldg(Gl + ci * 32 + 32 + lane);
                    MMA16816(cfr[ntl], aH0, aH1, aH2, aH3, bh0, bh1);
                    MMA16816(cfr[ntl], aH0, aH1, aH2, aH3, bl0, bl1);
                    MMA16816(cfr[ntl], aL0, aL1, aL2, aL3, bh0, bh1);
                }
            }
        }
        // ---- epilogue: relu + deg gate ----
        int r1 = row0 + mrow0 + grp;
        int r2 = r1 + 8;
        int ok1 = (r1 < NN) && (g_deg[r1] != 0);
        int ok2 = (r2 < NN) && (g_deg[r2] != 0);
#pragma unroll
        for (int ntl = 0; ntl < 8; ntl++) {
            int col0 = wc2 * 64 + ntl * 8 + tig * 2;
            if (ok1)
                *(float2*)(hnext + r1 * HD + col0) =
                    make_float2(fmaxf(cfr[ntl][0], 0.f), fmaxf(cfr[ntl][1], 0.f));
            if (ok2)
                *(float2*)(hnext + r2 * HD + col0) =
                    make_float2(fmaxf(cfr[ntl][2], 0.f), fmaxf(cfr[ntl][3], 0.f));
        }
    }
}

// ---------------- P/Q tensorized: P = h@We1[0:128], Q = h@We1[128:256] ----------------
#define PQ2_X_HI 0
#define PQ2_X_LO 17408
#define PQ2_WF_HI 34816
#define PQ2_WF_LO 51200
#define PQ2_SMEM 67584
__global__ void __launch_bounds__(256, 3)
pq_kernel(const int* __restrict__ lnum) {
    const float* X = ((*lnum) & 1) ? g_h2 : g_h;
    extern __shared__ char psm[];
    uint32_t sb = smem_u32(psm);
    uint32_t* wfh = (uint32_t*)(psm + PQ2_WF_HI);
    uint32_t* wfl = (uint32_t*)(psm + PQ2_WF_LO);
    int tid = threadIdx.x;
    int warp = tid >> 5, lane = tid & 31;
    int grp = lane >> 2, tig = lane & 3;
    int wr4 = warp & 3, wc2 = warp >> 2;
    int mrow0 = wr4 * 16;
    uint32_t aBase = sb + PQ2_X_HI + (uint32_t)((mrow0 + (lane & 15)) * 272 + ((lane >> 4) & 1) * 16);

    for (int tile = blockIdx.x; tile < G64; tile += 391) {
        int row0 = tile * 64;
        __syncthreads();
#pragma unroll
        for (int q = 0; q < 8; q++) {
            int f = tid + 256 * q;
            int row = f >> 5, kq = f & 31;
            int gr = row0 + row;
            float4 hv = (gr < NN) ? *(const float4*)(X + gr * HD + kq * 4)
                                  : make_float4(0.f, 0.f, 0.f, 0.f);
            uint32_t H01, H23, L01, L23;
            SPLIT4(hv, H01, H23, L01, L23);
            *(uint2*)(psm + PQ2_X_HI + row * 272 + kq * 8) = make_uint2(H01, H23);
            *(uint2*)(psm + PQ2_X_LO + row * 272 + kq * 8) = make_uint2(L01, L23);
        }
        __syncthreads();
        for (int m = 0; m < 2; m++) {
            float cfr[8][4];
#pragma unroll
            for (int ntl = 0; ntl < 8; ntl++) {
                cfr[ntl][0] = 0.f; cfr[ntl][1] = 0.f; cfr[ntl][2] = 0.f; cfr[ntl][3] = 0.f;
            }
            const uint32_t* Gh = g_Efh[m];
            const uint32_t* Gl = g_Efl[m];
            for (int half = 0; half < 2; half++) {
#pragma unroll
                for (int q = 0; q < 4; q++) {
                    ((uint4*)wfh)[tid + 256 * q] = ((const uint4*)(Gh + half * 4096))[tid + 256 * q];
                    ((uint4*)wfl)[tid + 256 * q] = ((const uint4*)(Gl + half * 4096))[tid + 256 * q];
                }
                __syncthreads();
#pragma unroll
                for (int ksl = 0; ksl < 4; ksl++) {
                    uint32_t addr = aBase + (uint32_t)((half * 4 + ksl) * 32);
                    uint32_t aH0, aH1, aH2, aH3, aL0, aL1, aL2, aL3;
                    LDM4(aH0, aH1, aH2, aH3, addr);
                    LDM4(aL0, aL1, aL2, aL3, addr + 17408);
#pragma unroll
                    for (int ntl = 0; ntl < 8; ntl++) {
                        int ci = ksl * 32 + (wc2 * 8 + ntl) * 2;
                        uint32_t bh0 = wfh[ci * 32 + lane], bh1 = wfh[ci * 32 + 32 + lane];
                        uint32_t bl0 = wfl[ci * 32 + lane], bl1 = wfl[ci * 32 + 32 + lane];
                        MMA16816(cfr[ntl], aH0, aH1, aH2, aH3, bh0, bh1);
                        MMA16816(cfr[ntl], aH0, aH1, aH2, aH3, bl0, bl1);
                        MMA16816(cfr[ntl], aL0, aL1, aL2, aL3, bh0, bh1);
                    }
                }
                __syncthreads();
            }
            float* C = m ? g_Q : g_P;
            int r1 = row0 + mrow0 + grp;
            int r2 = r1 + 8;
#pragma unroll
            for (int ntl = 0; ntl < 8; ntl++) {
                int col0 = wc2 * 64 + ntl * 8 + tig * 2;
                if (r1 < NN) *(float2*)(C + r1 * HD + col0) = make_float2(cfr[ntl][0], cfr[ntl][1]);
                if (r2 < NN) *(float2*)(C + r2 * HD + col0) = make_float2(cfr[ntl][2], cfr[ntl][3]);
            }
        }
    }
}

// ---------------- node head (proven FFMA2 version, on forked stream) ----------------
#define NH_SMEM_FLOATS (8448 + 2048 + 4352 + 128)
__global__ void nh_kernel(const float* __restrict__ Wn1, const float* __restrict__ bn1,
                          const float* __restrict__ Wn2, const float* __restrict__ bn2,
                          float* __restrict__ out, const int* __restrict__ lnum) {
    const float* X = ((*lnum) & 1) ? g_h2 : g_h;
    extern __shared__ float nsm[];
    float* Hst  = nsm;            // [k 128][r 64] stride 66
    float* Wbuf = Hst + 8448;     // 2048 chunk
    float* tsb  = Wbuf + 2048;    // [r 64][j 64] stride 68
    float* W2s  = tsb + 4352;     // 64*2
    int tid = threadIdx.x;
    int warp = tid >> 5, lane = tid & 31;
    int row0 = blockIdx.x * 64;
    if (tid < 128) W2s[tid] = Wn2[tid];
#pragma unroll 4
    for (int q = 0; q < 32; q++) {
        int e = tid + 256 * q;
        int r = e >> 7, k = e & 127;
        int gr = row0 + r;
        Hst[k * 66 + r] = (gr < NN) ? X[gr * HD + k] : 0.f;
    }
    __syncthreads();

    int jb8 = warp * 8;
    ull acc2[2][4];
    {
        ulonglong2 b01 = *(const ulonglong2*)(bn1 + jb8);
        ulonglong2 b23 = *(const ulonglong2*)(bn1 + jb8 + 4);
        acc2[0][0] = b01.x; acc2[0][1] = b01.y; acc2[0][2] = b23.x; acc2[0][3] = b23.y;
#pragma unroll
        for (int i = 0; i < 4; i++) acc2[1][i] = acc2[0][i];
    }
    for (int c = 0; c < 4; c++) {
#pragma unroll
        for (int q = 0; q < 8; q++) Wbuf[tid + 256 * q] = Wn1[c * 2048 + tid + 256 * q];
        __syncthreads();
#pragma unroll 8
        for (int kk = 0; kk < 32; kk++) {
            const float* wr = Wbuf + kk * 64 + jb8;
            ulonglong2 wA = *(const ulonglong2*)(wr);
            ulonglong2 wB = *(const ulonglong2*)(wr + 4);
            float2 xv = *(const float2*)(Hst + (c * 32 + kk) * 66 + lane * 2);
            ull x0 = pk2(xv.x, xv.x), x1 = pk2(xv.y, xv.y);
            ffma2(acc2[0][0], x0, wA.x); ffma2(acc2[0][1], x0, wA.y);
            ffma2(acc2[0][2], x0, wB.x); ffma2(acc2[0][3], x0, wB.y);
            ffma2(acc2[1][0], x1, wA.x); ffma2(acc2[1][1], x1, wA.y);
            ffma2(acc2[1][2], x1, wB.x); ffma2(acc2[1][3], x1, wB.y);
        }
        __syncthreads();
    }
#pragma unroll
    for (int rr = 0; rr < 2; rr++) {
        int r = lane * 2 + rr;
        float f[8];
#pragma unroll
        for (int i = 0; i < 4; i++) upk2(acc2[rr][i], f[2 * i], f[2 * i + 1]);
        float4 o1, o2;
        o1.x = fmaxf(f[0], 0.f); o1.y = fmaxf(f[1], 0.f); o1.z = fmaxf(f[2], 0.f); o1.w = fmaxf(f[3], 0.f);
        o2.x = fmaxf(f[4], 0.f); o2.y = fmaxf(f[5], 0.f); o2.z = fmaxf(f[6], 0.f); o2.w = fmaxf(f[7], 0.f);
        *(float4*)(tsb + r * 68 + jb8) = o1;
        *(float4*)(tsb + r * 68 + jb8 + 4) = o2;
    }
    __syncthreads();
    if (tid < 128) {
        int r = tid >> 1, o = tid & 1;
        float s = 0.f;
#pragma unroll 8
        for (int j = 0; j < 64; j++) s += tsb[r * 68 + j] * W2s[j * 2 + o];
        int gr = row0 + r;
        if (gr < NN) out[gr * 2 + o] = s + bn2[o];
    }
}

// ---------------- fused edge head (mma.sync, CSR-ordered for Q locality) ----------------
#define EDGE_SMEM_BYTES (34816 + 34816 + 16384 + 16384 + 1536 + 256 + 32)
#define TSL_OFF 34816
#define BFH_OFF 69632
#define BFL_OFF 86016
#define W3T_OFF 102400
#define B2S_OFF 103936
#define B3S_OFF 104192
__global__ void __launch_bounds__(256, 2)
edge_kernel(const float* __restrict__ ea, const float* __restrict__ We1,
            const float* __restrict__ be1, const float* __restrict__ We2,
            const float* __restrict__ be2, const float* __restrict__ We3,
            const float* __restrict__ be3, float* __restrict__ out) {
    extern __shared__ char esm[];
    char* tsH = esm;
    char* tsL = esm + TSL_OFF;
    uint32_t* bfH = (uint32_t*)(esm + BFH_OFF);
    uint32_t* bfL = (uint32_t*)(esm + BFL_OFF);
    float* w3t = (float*)(esm + W3T_OFF);   // [6][64] transposed
    float* b2s = (float*)(esm + B2S_OFF);   // 64
    float* b3s = (float*)(esm + B3S_OFF);   // 8
    __shared__ int esrc[128], edst[128], eeid[128];
    int tid = threadIdx.x, warp = tid >> 5, lane = tid & 31;
    int grp = lane >> 2, tig = lane & 3;
    int j0 = lane * 4;
    uint32_t sb = smem_u32(esm);

    for (int i = tid; i < 384; i += 256) w3t[i] = We3[(i & 63) * 6 + (i >> 6)];
    if (tid < 64) b2s[tid] = be2[tid];
    if (tid < 8) b3s[tid] = (tid < 6) ? be3[tid] : 0.f;
    for (int c = warp; c < 128; c += 8) {
        int ks = c >> 4, nt = (c >> 1) & 7, r = c & 1;
        int k0 = ks * 16 + tig * 2 + r * 8;
        int n = nt * 8 + grp;
        float v0 = We2[k0 * 64 + n];
        float v1 = We2[(k0 + 1) * 64 + n];
        __nv_bfloat16 h0 = __float2bfloat16_rn(v0);
        __nv_bfloat16 h1 = __float2bfloat16_rn(v1);
        float l0 = v0 - __bfloat162float(h0);
        float l1 = v1 - __bfloat162float(h1);
        uint32_t rh = ((uint32_t)__bfloat16_as_ushort(h1) << 16) | (uint32_t)__bfloat16_as_ushort(h0);
        uint32_t rl;
        asm("cvt.rn.bf16x2.f32 %0, %1, %2;" : "=r"(rl) : "f"(l1), "f"(l0));
        bfH[c * 32 + lane] = rh;
        bfL[c * 32 + lane] = rl;
    }

    float4 bq = __ldg((const float4*)(be1 + j0));
    float4 wck[8];
#pragma unroll
    for (int k = 0; k < 8; k++)
        wck[k] = __ldg((const float4*)(We1 + 256 * HD + k * 128 + j0));
    __syncthreads();

    for (int e0 = blockIdx.x * 128; e0 < EE; e0 += gridDim.x * 128) {
        if (tid < 128) {
            int e = e0 + tid;
            int2 se = g_cse[e];
            esrc[tid] = se.x;
            eeid[tid] = se.y;
            edst[tid] = g_cdst[e];
        }
        __syncthreads();
        for (int it = 0; it < 16; it++) {
            int el = warp + 8 * it;
            int s = esrc[el], d = edst[el], eid = eeid[el];
            float4 pp = __ldg((const float4*)(g_P + s * HD + j0));
            float4 qq = __ldg((const float4*)(g_Q + d * HD + j0));
            float4 e0v = __ldg((const float4*)(ea + eid * EAD));
            float4 e1v = __ldg((const float4*)(ea + eid * EAD + 4));
            float4 t = bq;
            t.x += e0v.x * wck[0].x + e0v.y * wck[1].x + e0v.z * wck[2].x + e0v.w * wck[3].x
                 + e1v.x * wck[4].x + e1v.y * wck[5].x + e1v.z * wck[6].x + e1v.w * wck[7].x;
            t.y += e0v.x * wck[0].y + e0v.y * wck[1].y + e0v.z * wck[2].y + e0v.w * wck[3].y
                 + e1v.x * wck[4].y + e1v.y * wck[5].y + e1v.z * wck[6].y + e1v.w * wck[7].y;
            t.z += e0v.x * wck[0].z + e0v.y * wck[1].z + e0v.z * wck[2].z + e0v.w * wck[3].z
                 + e1v.x * wck[4].z + e1v.y * wck[5].z + e1v.z * wck[6].z + e1v.w * wck[7].z;
            t.w += e0v.x * wck[0].w + e0v.y * wck[1].w + e0v.z * wck[2].w + e0v.w * wck[3].w
                 + e1v.x * wck[4].w + e1v.y * wck[5].w + e1v.z * wck[6].w + e1v.w * wck[7].w;
            t.x = fmaxf(t.x + pp.x + qq.x, 0.f);
            t.y = fmaxf(t.y + pp.y + qq.y, 0.f);
            t.z = fmaxf(t.z + pp.z + qq.z, 0.f);
            t.w = fmaxf(t.w + pp.w + qq.w, 0.f);
            uint32_t H01, H23, L01, L23;
            SPLIT4(t, H01, H23, L01, L23);
            *(uint2*)(tsH + el * 272 + lane * 8) = make_uint2(H01, H23);
            *(uint2*)(tsL + el * 272 + lane * 8) = make_uint2(L01, L23);
        }
        __syncthreads();
        float cfr[8][4];
#pragma unroll
        for (int nt = 0; nt < 8; nt++) {
            cfr[nt][0] = 0.f; cfr[nt][1] = 0.f; cfr[nt][2] = 0.f; cfr[nt][3] = 0.f;
        }
        int mrow0 = warp * 16;
        uint32_t aBase = sb + (uint32_t)((mrow0 + (lane & 15)) * 272 + ((lane >> 4) & 1) * 16);
#pragma unroll
        for (int ks = 0; ks < 8; ks++) {
            uint32_t aH0, aH1, aH2, aH3, aL0, aL1, aL2, aL3;
            uint32_t addrH = aBase + ks * 32;
            LDM4(aH0, aH1, aH2, aH3, addrH);
            LDM4(aL0, aL1, aL2, aL3, addrH + TSL_OFF);
#pragma unroll
            for (int nt = 0; nt < 8; nt++) {
                int ci = ks * 16 + nt * 2;
                uint32_t bh0 = bfH[ci * 32 + lane], bh1 = bfH[(ci + 1) * 32 + lane];
                uint32_t bl0 = bfL[ci * 32 + lane], bl1 = bfL[(ci + 1) * 32 + lane];
                MMA16816(cfr[nt], aH0, aH1, aH2, aH3, bh0, bh1);
                MMA16816(cfr[nt], aH0, aH1, aH2, aH3, bl0, bl1);
                MMA16816(cfr[nt], aL0, aL1, aL2, aL3, bh0, bh1);
            }
        }
        float o6a[6], o6b[6];
#pragma unroll
        for (int o = 0; o < 6; o++) { o6a[o] = 0.f; o6b[o] = 0.f; }
#pragma unroll
        for (int nt = 0; nt < 8; nt++) {
            int col0 = nt * 8 + tig * 2;
            float ua0 = fmaxf(cfr[nt][0] + b2s[col0], 0.f);
            float ua1 = fmaxf(cfr[nt][1] + b2s[col0 + 1], 0.f);
            float ub0 = fmaxf(cfr[nt][2] + b2s[col0], 0.f);
            float ub1 = fmaxf(cfr[nt][3] + b2s[col0 + 1], 0.f);
#pragma unroll
            for (int o = 0; o < 6; o++) {
                float w0 = w3t[o * 64 + col0], w1 = w3t[o * 64 + col0 + 1];
                o6a[o] += ua0 * w0 + ua1 * w1;
                o6b[o] += ub0 * w0 + ub1 * w1;
            }
        }
#pragma unroll
        for (int o = 0; o < 6; o++) {
            o6a[o] += __shfl_xor_sync(0xffffffffu, o6a[o], 1);
            o6a[o] += __shfl_xor_sync(0xffffffffu, o6a[o], 2);
            o6b[o] += __shfl_xor_sync(0xffffffffu, o6b[o], 1);
            o6b[o] += __shfl_xor_sync(0xffffffffu, o6b[o], 2);
        }
        if (tig == 0) {
            int eidA = eeid[mrow0 + grp];
            int eidB = eeid[mrow0 + grp + 8];
            *(float2*)(out + eidA * 6)     = make_float2(o6a[0] + b3s[0], o6a[1] + b3s[1]);
            *(float2*)(out + eidA * 6 + 2) = make_float2(o6a[2] + b3s[2], o6a[3] + b3s[3]);
            *(float2*)(out + eidA * 6 + 4) = make_float2(o6a[4] + b3s[4], o6a[5] + b3s[5]);
            *(float2*)(out + eidB * 6)     = make_float2(o6b[0] + b3s[0], o6b[1] + b3s[1]);
            *(float2*)(out + eidB * 6 + 2) = make_float2(o6b[2] + b3s[2], o6b[3] + b3s[3]);
            *(float2*)(out + eidB * 6 + 4) = make_float2(o6b[4] + b3s[4], o6b[5] + b3s[5]);
        }
        __syncthreads();
    }
}

// ---------------- launch ----------------
extern "C" void kernel_launch(void* const* d_in, const int* in_sizes, int n_in,
                              void* d_out, int out_size) {
    const float* x    = (const float*)d_in[0];
    const void*  ei   = d_in[1];
    const float* ea   = (const float*)d_in[2];
    const int*   lnum = (const int*)d_in[3];
    const float* Wenc = (const float*)d_in[4];
    const float* benc = (const float*)d_in[5];
    const float* Wmsg = (const float*)d_in[6];
    const float* bmsg = (const float*)d_in[7];
    const float* Wupd = (const float*)d_in[8];
    const float* bupd = (const float*)d_in[9];
    const float* Wn1  = (const float*)d_in[10];
    const float* bn1  = (const float*)d_in[11];
    const float* Wn2  = (const float*)d_in[12];
    const float* bn2  = (const float*)d_in[13];
    const float* We1  = (const float*)d_in[14];
    const float* be1  = (const float*)d_in[15];
    const float* We2  = (const float*)d_in[16];
    const float* be2  = (const float*)d_in[17];
    const float* We3  = (const float*)d_in[18];
    const float* be3  = (const float*)d_in[19];
    float* out = (float*)d_out;

    float *hp, *h2p;
    cudaGetSymbolAddress((void**)&hp,  g_h);
    cudaGetSymbolAddress((void**)&h2p, g_h2);

    const int nhSmem = NH_SMEM_FLOATS * 4;
    cudaFuncSetAttribute(layer_kernel, cudaFuncAttributeMaxDynamicSharedMemorySize, LAYER2_SMEM);
    cudaFuncSetAttribute(pq_kernel, cudaFuncAttributeMaxDynamicSharedMemorySize, PQ2_SMEM);
    cudaFuncSetAttribute(nh_kernel, cudaFuncAttributeMaxDynamicSharedMemorySize, nhSmem);
    cudaFuncSetAttribute(edge_kernel, cudaFuncAttributeMaxDynamicSharedMemorySize, EDGE_SMEM_BYTES);

    cudaStream_t s0 = 0;
    bool fork = s_fork;

    detect_kernel<<<256, 256, 0, s0>>>((const long long*)ei);
    if (fork) {
        cudaEventRecord(s_ev0, s0);
        cudaStreamWaitEvent(s_b, s_ev0, 0);
        encuv_kernel<<<1312, 128, 0, s_b>>>(x, Wenc, benc, Wmsg, bmsg, Wupd, bupd);
        wfrag_kernel<<<64, 256, 0, s_b>>>(We1);
        cudaEventRecord(s_evB, s_b);
    }
    prep_kernel<<<1024, 256, 0, s0>>>(ei);
    scan1_kernel<<<SCAN_NB, SCAN_B, 0, s0>>>();
    scan3_kernel<<<SCAN_NB, SCAN_B, 0, s0>>>();
    scatter_kernel<<<1024, 256, 0, s0>>>();
    if (fork) {
        cudaStreamWaitEvent(s0, s_evB, 0);
    } else {
        encuv_kernel<<<1312, 128, 0, s0>>>(x, Wenc, benc, Wmsg, bmsg, Wupd, bupd);
        wfrag_kernel<<<64, 256, 0, s0>>>(We1);
    }

    for (int L = 0; L < MAX_LAYERS; L++) {
        const float* cur = (L & 1) ? h2p : hp;
        float* nxt = (L & 1) ? hp : h2p;
        layer_kernel<<<LGRID + 16, 256, LAYER2_SMEM, s0>>>(cur, nxt, lnum, L, Wupd, bupd);
    }

    if (fork) {
        cudaEventRecord(s_ev1, s0);
        cudaStreamWaitEvent(s_b, s_ev1, 0);
        nh_kernel<<<G64, 256, nhSmem, s_b>>>(Wn1, bn1, Wn2, bn2, out, lnum);
        cudaEventRecord(s_evB2, s_b);
    } else {
        nh_kernel<<<G64, 256, nhSmem, s0>>>(Wn1, bn1, Wn2, bn2, out, lnum);
    }
    pq_kernel<<<391, 256, PQ2_SMEM, s0>>>(lnum);
    edge_kernel<<<296, 256, EDGE_SMEM_BYTES, s0>>>(ea, We1, be1, We2, be2, We3, be3, out + NODE_OUT_ELEMS);
    if (fork) {
        cudaStreamWaitEvent(s0, s_evB2, 0);
    }
}